// round 11
// baseline (speedup 1.0000x reference)
#include <cuda_runtime.h>
#include <cuda_bf16.h>
#include <math.h>
#include <stdint.h>

// ---------------------------------------------------------------------------
// Problem constants
// ---------------------------------------------------------------------------
#define NN      2048
#define SEQ     64
#define DIM     256
#define NH      8
#define DH      32
#define GHEADS  4
#define NEDGE   32768
#define NTOK    (NN*SEQ)
#define SPH     512
#define NREL    3
#define NSEG    (NREL*NN)     // 6144

// ---------------------------------------------------------------------------
// Scratch (device globals)
// ---------------------------------------------------------------------------
__device__ float g_QKV[NTOK*3*DIM];
__device__ float g_H  [NN*DIM];
__device__ float g_TH [NN*DIM];
__device__ float g_PE [SEQ*DIM];
__device__ float g_XG [NSEG*GHEADS*DIM];
__device__ float g_AS [NSEG*GHEADS];
__device__ float g_AD [NSEG*GHEADS];
__device__ float g_NUMR[NSEG*DIM];
__device__ float g_BF [4*NREL*1024];       // fused GAT bias per layer

// CSR of edges sorted by (rel, dst) — built once
__device__ int g_off[NSEG + 1];
__device__ int g_pos[NSEG + 1];
__device__ int g_srt[NEDGE];

// bf16 hi/lo split activations
__device__ __nv_bfloat16 g_Xh [NTOK*DIM],  g_Xl [NTOK*DIM];
__device__ __nv_bfloat16 g_T1h[NTOK*DIM],  g_T1l[NTOK*DIM];
__device__ __nv_bfloat16 g_Hh [NN*DIM],    g_Hl [NN*DIM];
__device__ __nv_bfloat16 g_SPHh[NN*SPH],   g_SPHl[NN*SPH];

// identity-split msg weights (for fused-weight precompute)
__device__ __nv_bfloat16 g_MSGh[NREL*256*256], g_MSGl[NREL*256*256];
// fused msg@gat weights, K-major [l][r][1024][256]
__device__ __nv_bfloat16 g_WFh[4*NREL*1024*256], g_WFl[4*NREL*1024*256];

// transposed + split weights, K-major [N, K]
#define WT_QKV   0
#define WT_WO    (WT_QKV + 2*768*256)
#define WT_W1    (WT_WO  + 2*256*256)
#define WT_W2    (WT_W1  + 2*256*256)
#define WT_MSG   (WT_W2  + 2*256*256)
#define WT_GAT   (WT_MSG + 3*256*256)
#define WT_SP1   (WT_GAT + 4*1024*256)
#define WT_SP2   (WT_SP1 + 512*256)
#define WT_TOTAL (WT_SP2 + 256*512)
__device__ __nv_bfloat16 g_WTh[WT_TOTAL], g_WTl[WT_TOTAL];

// ---------------------------------------------------------------------------
// Helpers
// ---------------------------------------------------------------------------
__device__ __forceinline__ float lrelu(float x) { return x > 0.f ? x : 0.2f * x; }

__device__ __forceinline__ uint32_t smem_u32(const void* p) {
    uint32_t a;
    asm("{ .reg .u64 t; cvta.to.shared.u64 t, %1; cvt.u32.u64 %0, t; }" : "=r"(a) : "l"(p));
    return a;
}

__device__ __forceinline__ void split1(float v, __nv_bfloat16& h, __nv_bfloat16& l) {
    h = __float2bfloat16_rn(v);
    l = __float2bfloat16_rn(v - __bfloat162float(h));
}

__device__ __forceinline__ void split2(float a, float b, uint32_t& hi, uint32_t& lo) {
    __nv_bfloat16 ha, la, hb, lb;
    split1(a, ha, la);
    split1(b, hb, lb);
    hi = (uint32_t)__bfloat16_as_ushort(ha) | ((uint32_t)__bfloat16_as_ushort(hb) << 16);
    lo = (uint32_t)__bfloat16_as_ushort(la) | ((uint32_t)__bfloat16_as_ushort(lb) << 16);
}

__device__ __forceinline__ float bflo(uint32_t x) {
    return __bfloat162float(__ushort_as_bfloat16((unsigned short)(x & 0xffffu)));
}
__device__ __forceinline__ float bfhi(uint32_t x) {
    return __bfloat162float(__ushort_as_bfloat16((unsigned short)(x >> 16)));
}

__device__ __forceinline__ void ldsm_x4(uint32_t* r, uint32_t a) {
    asm volatile("ldmatrix.sync.aligned.m8n8.x4.shared.b16 {%0,%1,%2,%3}, [%4];"
                 : "=r"(r[0]), "=r"(r[1]), "=r"(r[2]), "=r"(r[3]) : "r"(a));
}
__device__ __forceinline__ void ldsm_x2(uint32_t* r, uint32_t a) {
    asm volatile("ldmatrix.sync.aligned.m8n8.x2.shared.b16 {%0,%1}, [%2];"
                 : "=r"(r[0]), "=r"(r[1]) : "r"(a));
}

__device__ __forceinline__ void mma16816(float* c, const uint32_t* a, const uint32_t* b) {
    asm volatile(
        "mma.sync.aligned.m16n8k16.row.col.f32.bf16.bf16.f32 "
        "{%0,%1,%2,%3}, {%4,%5,%6,%7}, {%8,%9}, {%0,%1,%2,%3};"
        : "+f"(c[0]), "+f"(c[1]), "+f"(c[2]), "+f"(c[3])
        : "r"(a[0]), "r"(a[1]), "r"(a[2]), "r"(a[3]), "r"(b[0]), "r"(b[1]));
}

__device__ __forceinline__ void cp_async16(uint32_t dst, const void* src) {
    asm volatile("cp.async.cg.shared.global [%0], [%1], 16;" :: "r"(dst), "l"(src) : "memory");
}
__device__ __forceinline__ void cp_commit() {
    asm volatile("cp.async.commit_group;" ::: "memory");
}
template<int W> __device__ __forceinline__ void cp_wait() {
    asm volatile("cp.async.wait_group %0;" :: "n"(W) : "memory");
}

// ---------------------------------------------------------------------------
// Pipelined bf16-split GEMM (256 threads, 128x128 tile, 3-stage)
// rmaj>0: outputs written block-relation-major with block width (1<<rshift):
//   o = (col>>rshift)*rmaj + row*(1<<rshift) + (col & ((1<<rshift)-1))
// ---------------------------------------------------------------------------
#define ARR_BYTES  8192
#define STAGE_BYTES (4*ARR_BYTES)
#define NSTAGE 3

__device__ __forceinline__ void gemm_issue(
    uint32_t sb, int stage, int tid,
    const __nv_bfloat16* Ahi, const __nv_bfloat16* Alo, int lda,
    const __nv_bfloat16* Bhi, const __nv_bfloat16* Blo, int K,
    int row0, int col0, int k0)
{
    #pragma unroll
    for (int i = 0; i < 8; i++) {
        int idx = tid + i * 256;
        int arr = idx >> 9;
        int j   = idx & 511;
        int r   = j >> 2;
        int c   = j & 3;
        uint32_t dst = sb + stage * STAGE_BYTES + arr * ARR_BYTES
                     + (uint32_t)(r * 4 + (c ^ ((r >> 1) & 3))) * 16;
        const __nv_bfloat16* src;
        if (arr == 0)      src = Ahi + (size_t)(row0 + r) * lda + k0 + c * 8;
        else if (arr == 1) src = Alo + (size_t)(row0 + r) * lda + k0 + c * 8;
        else if (arr == 2) src = Bhi + (size_t)(col0 + r) * K + k0 + c * 8;
        else               src = Blo + (size_t)(col0 + r) * K + k0 + c * 8;
        cp_async16(dst, src);
    }
    cp_commit();
}

__global__ void __launch_bounds__(256)
gemm_bf16(const __nv_bfloat16* __restrict__ Ahi, const __nv_bfloat16* __restrict__ Alo, int lda,
          const __nv_bfloat16* __restrict__ Bhi, const __nv_bfloat16* __restrict__ Blo,
          const float* __restrict__ bias,
          float* __restrict__ Cf,
          __nv_bfloat16* __restrict__ Chi, __nv_bfloat16* __restrict__ Clo,
          int M, int N, int K, int act, int rmaj, int rshift) {
    extern __shared__ char sm[];
    const uint32_t sb = smem_u32(sm);
    const int tid  = threadIdx.x;
    const int lane = tid & 31;
    const int warp = tid >> 5;
    const int wm = warp & 3;
    const int wn = warp >> 2;
    const int row0 = blockIdx.y * 128;
    const int col0 = blockIdx.x * 128;

    float acc[2][8][4];
    #pragma unroll
    for (int i = 0; i < 2; i++)
        #pragma unroll
        for (int j = 0; j < 8; j++)
            #pragma unroll
            for (int k = 0; k < 4; k++) acc[i][j][k] = 0.f;

    const int nch = K >> 5;
    gemm_issue(sb, 0, tid, Ahi, Alo, lda, Bhi, Blo, K, row0, col0, 0);
    if (nch > 1)
        gemm_issue(sb, 1, tid, Ahi, Alo, lda, Bhi, Blo, K, row0, col0, 32);

    for (int ch = 0; ch < nch; ch++) {
        if (ch + 1 < nch) cp_wait<1>(); else cp_wait<0>();
        __syncthreads();

        const uint32_t base = sb + (ch % NSTAGE) * STAGE_BYTES;
        #pragma unroll
        for (int s = 0; s < 2; s++) {
            uint32_t ah[2][4], al[2][4];
            #pragma unroll
            for (int mt = 0; mt < 2; mt++) {
                int row = wm * 32 + mt * 16 + (lane & 15);
                int c = 2 * s + (lane >> 4);
                uint32_t off = (uint32_t)(row * 4 + (c ^ ((row >> 1) & 3))) * 16;
                ldsm_x4(ah[mt], base + off);
                ldsm_x4(al[mt], base + ARR_BYTES + off);
            }
            #pragma unroll
            for (int nt = 0; nt < 8; nt++) {
                int nr = wn * 64 + nt * 8 + (lane & 7);
                int c = 2 * s + ((lane >> 3) & 1);
                uint32_t off = (uint32_t)(nr * 4 + (c ^ ((nr >> 1) & 3))) * 16;
                uint32_t bh[2], bl[2];
                ldsm_x2(bh, base + 2 * ARR_BYTES + off);
                ldsm_x2(bl, base + 3 * ARR_BYTES + off);
                #pragma unroll
                for (int mt = 0; mt < 2; mt++) {
                    mma16816(acc[mt][nt], ah[mt], bh);
                    mma16816(acc[mt][nt], ah[mt], bl);
                    mma16816(acc[mt][nt], al[mt], bh);
                }
            }
        }
        __syncthreads();
        if (ch + 2 < nch)
            gemm_issue(sb, (ch + 2) % NSTAGE, tid, Ahi, Alo, lda, Bhi, Blo, K,
                       row0, col0, (ch + 2) << 5);
    }

    const int g4 = lane >> 2, tig = lane & 3;
    #pragma unroll
    for (int nt = 0; nt < 8; nt++) {
        int col = col0 + wn * 64 + nt * 8 + tig * 2;
        float b0 = 0.f, b1 = 0.f;
        if (bias) { b0 = bias[col]; b1 = bias[col + 1]; }
        #pragma unroll
        for (int mt = 0; mt < 2; mt++) {
            int row = row0 + wm * 32 + mt * 16 + g4;
            float v0 = acc[mt][nt][0] + b0;
            float v1 = acc[mt][nt][1] + b1;
            float v2 = acc[mt][nt][2] + b0;
            float v3 = acc[mt][nt][3] + b1;
            if (act) {
                v0 = fmaxf(v0, 0.f); v1 = fmaxf(v1, 0.f);
                v2 = fmaxf(v2, 0.f); v3 = fmaxf(v3, 0.f);
            }
            size_t o0, o1;
            if (rmaj) {
                int bw = 1 << rshift;
                o0 = (size_t)(col >> rshift) * rmaj + (size_t)row * bw + (col & (bw - 1));
                o1 = o0 + (size_t)8 * bw;
            } else {
                o0 = (size_t)row * N + col;
                o1 = o0 + (size_t)8 * N;
            }
            if (Cf) {
                *(float2*)(Cf + o0) = make_float2(v0, v1);
                *(float2*)(Cf + o1) = make_float2(v2, v3);
            }
            if (Chi) {
                uint32_t h01, l01, h23, l23;
                split2(v0, v1, h01, l01);
                split2(v2, v3, h23, l23);
                *(uint32_t*)(Chi + o0) = h01;
                *(uint32_t*)(Clo + o0) = l01;
                *(uint32_t*)(Chi + o1) = h23;
                *(uint32_t*)(Clo + o1) = l23;
            }
        }
    }
}

// ---------------------------------------------------------------------------
// Fused GEMM + residual + LayerNorm (unchanged)
// ---------------------------------------------------------------------------
#define LSTG 49152

__device__ __forceinline__ void gemm_ln_issue(
    uint32_t sb, int stage, int tid, int row0, int k0,
    const __nv_bfloat16* Ahi, const __nv_bfloat16* Alo,
    const __nv_bfloat16* Bhi, const __nv_bfloat16* Blo)
{
    #pragma unroll
    for (int i = 0; i < 6; i++) {
        int idx = tid + i * 512;
        uint32_t stg = sb + stage * LSTG;
        const __nv_bfloat16* src;
        uint32_t dst;
        if (idx < 1024) {
            int j = idx & 511;
            int r = j >> 2, c = j & 3;
            dst = stg + ((idx >> 9) ? 8192u : 0u)
                + (uint32_t)(r * 4 + (c ^ ((r >> 1) & 3))) * 16;
            src = ((idx >> 9) ? Alo : Ahi) + (size_t)(row0 + r) * 256 + k0 + c * 8;
        } else {
            int j = (idx - 1024) & 1023;
            int r = j >> 2, c = j & 3;
            dst = stg + ((idx >= 2048) ? 32768u : 16384u)
                + (uint32_t)(r * 4 + (c ^ ((r >> 1) & 3))) * 16;
            src = ((idx >= 2048) ? Blo : Bhi) + (size_t)r * 256 + k0 + c * 8;
        }
        cp_async16(dst, src);
    }
    cp_commit();
}

__global__ void __launch_bounds__(512)
gemm_ln(const __nv_bfloat16* __restrict__ Ahi, const __nv_bfloat16* __restrict__ Alo,
        const __nv_bfloat16* __restrict__ Bhi, const __nv_bfloat16* __restrict__ Blo,
        const float* __restrict__ bias,
        const float* __restrict__ lng, const float* __restrict__ lnb,
        __nv_bfloat16* Xh, __nv_bfloat16* Xl) {
    extern __shared__ char sm[];
    const uint32_t sb = smem_u32(sm);
    float* s_sum  = (float*)(sm + 3 * LSTG);
    float* s_g    = (float*)(sm + 3 * LSTG + 4096);
    float* s_b    = s_g + 256;
    float* s_bias = s_b + 256;
    const int tid  = threadIdx.x;
    const int lane = tid & 31;
    const int warp = tid >> 5;
    const int wm = warp & 3;
    const int wn = warp >> 2;
    const int row0 = blockIdx.x * 128;

    if (tid < 256) { s_g[tid] = lng[tid]; s_b[tid] = lnb[tid]; s_bias[tid] = bias[tid]; }

    float acc[2][8][4];
    #pragma unroll
    for (int i = 0; i < 2; i++)
        #pragma unroll
        for (int j = 0; j < 8; j++)
            #pragma unroll
            for (int k = 0; k < 4; k++) acc[i][j][k] = 0.f;

    gemm_ln_issue(sb, 0, tid, row0, 0, Ahi, Alo, Bhi, Blo);
    gemm_ln_issue(sb, 1, tid, row0, 32, Ahi, Alo, Bhi, Blo);

    for (int ch = 0; ch < 8; ch++) {
        if (ch < 7) cp_wait<1>(); else cp_wait<0>();
        __syncthreads();
        const uint32_t base = sb + (ch % 3) * LSTG;
        #pragma unroll
        for (int s = 0; s < 2; s++) {
            uint32_t ah[2][4], al[2][4];
            #pragma unroll
            for (int mt = 0; mt < 2; mt++) {
                int row = wm * 32 + mt * 16 + (lane & 15);
                int c = 2 * s + (lane >> 4);
                uint32_t off = (uint32_t)(row * 4 + (c ^ ((row >> 1) & 3))) * 16;
                ldsm_x4(ah[mt], base + off);
                ldsm_x4(al[mt], base + 8192 + off);
            }
            #pragma unroll
            for (int nt = 0; nt < 8; nt++) {
                int nr = wn * 64 + nt * 8 + (lane & 7);
                int c = 2 * s + ((lane >> 3) & 1);
                uint32_t off = (uint32_t)(nr * 4 + (c ^ ((nr >> 1) & 3))) * 16;
                uint32_t bh[2], bl[2];
                ldsm_x2(bh, base + 16384 + off);
                ldsm_x2(bl, base + 32768 + off);
                #pragma unroll
                for (int mt = 0; mt < 2; mt++) {
                    mma16816(acc[mt][nt], ah[mt], bh);
                    mma16816(acc[mt][nt], ah[mt], bl);
                    mma16816(acc[mt][nt], al[mt], bh);
                }
            }
        }
        __syncthreads();
        if (ch + 2 < 8)
            gemm_ln_issue(sb, (ch + 2) % 3, tid, row0, (ch + 2) * 32, Ahi, Alo, Bhi, Blo);
    }

    const int g4 = lane >> 2, tig = lane & 3;
    float ps[2][2][2];
    #pragma unroll
    for (int mt = 0; mt < 2; mt++)
        #pragma unroll
        for (int h = 0; h < 2; h++) { ps[mt][h][0] = 0.f; ps[mt][h][1] = 0.f; }

    #pragma unroll
    for (int nt = 0; nt < 8; nt++) {
        int col = wn * 64 + nt * 8 + tig * 2;
        float b0 = s_bias[col], b1 = s_bias[col + 1];
        #pragma unroll
        for (int mt = 0; mt < 2; mt++) {
            size_t rA = (size_t)(row0 + wm * 32 + mt * 16 + g4) * 256 + col;
            uint32_t rh0 = *(const uint32_t*)(Xh + rA);
            uint32_t rl0 = *(const uint32_t*)(Xl + rA);
            uint32_t rh1 = *(const uint32_t*)(Xh + rA + 8 * 256);
            uint32_t rl1 = *(const uint32_t*)(Xl + rA + 8 * 256);
            float v0 = acc[mt][nt][0] + b0 + bflo(rh0) + bflo(rl0);
            float v1 = acc[mt][nt][1] + b1 + bfhi(rh0) + bfhi(rl0);
            float v2 = acc[mt][nt][2] + b0 + bflo(rh1) + bflo(rl1);
            float v3 = acc[mt][nt][3] + b1 + bfhi(rh1) + bfhi(rl1);
            acc[mt][nt][0] = v0; acc[mt][nt][1] = v1;
            acc[mt][nt][2] = v2; acc[mt][nt][3] = v3;
            ps[mt][0][0] += v0 + v1; ps[mt][0][1] += v0 * v0 + v1 * v1;
            ps[mt][1][0] += v2 + v3; ps[mt][1][1] += v2 * v2 + v3 * v3;
        }
    }
    #pragma unroll
    for (int mt = 0; mt < 2; mt++)
        #pragma unroll
        for (int h = 0; h < 2; h++) {
            ps[mt][h][0] += __shfl_xor_sync(0xffffffffu, ps[mt][h][0], 1);
            ps[mt][h][0] += __shfl_xor_sync(0xffffffffu, ps[mt][h][0], 2);
            ps[mt][h][1] += __shfl_xor_sync(0xffffffffu, ps[mt][h][1], 1);
            ps[mt][h][1] += __shfl_xor_sync(0xffffffffu, ps[mt][h][1], 2);
        }
    if (tig == 0) {
        #pragma unroll
        for (int mt = 0; mt < 2; mt++)
            #pragma unroll
            for (int h = 0; h < 2; h++) {
                int row = wm * 32 + mt * 16 + g4 + h * 8;
                *(float2*)&s_sum[(row * 4 + wn) * 2] =
                    make_float2(ps[mt][h][0], ps[mt][h][1]);
            }
    }
    __syncthreads();

    float mean[2][2], rstd[2][2];
    #pragma unroll
    for (int mt = 0; mt < 2; mt++)
        #pragma unroll
        for (int h = 0; h < 2; h++) {
            int row = wm * 32 + mt * 16 + g4 + h * 8;
            float s = 0.f, q = 0.f;
            #pragma unroll
            for (int w = 0; w < 4; w++) {
                float2 t = *(float2*)&s_sum[(row * 4 + w) * 2];
                s += t.x; q += t.y;
            }
            float m = s * (1.f / 256.f);
            float var = fmaxf(q * (1.f / 256.f) - m * m, 0.f);
            mean[mt][h] = m;
            rstd[mt][h] = rsqrtf(var + 1e-5f);
        }

    #pragma unroll
    for (int nt = 0; nt < 8; nt++) {
        int col = wn * 64 + nt * 8 + tig * 2;
        float gg0 = s_g[col], gg1 = s_g[col + 1];
        float bb0 = s_b[col], bb1 = s_b[col + 1];
        #pragma unroll
        for (int mt = 0; mt < 2; mt++) {
            size_t rA = (size_t)(row0 + wm * 32 + mt * 16 + g4) * 256 + col;
            float o0 = (acc[mt][nt][0] - mean[mt][0]) * rstd[mt][0] * gg0 + bb0;
            float o1 = (acc[mt][nt][1] - mean[mt][0]) * rstd[mt][0] * gg1 + bb1;
            float o2 = (acc[mt][nt][2] - mean[mt][1]) * rstd[mt][1] * gg0 + bb0;
            float o3 = (acc[mt][nt][3] - mean[mt][1]) * rstd[mt][1] * gg1 + bb1;
            uint32_t h01, l01, h23, l23;
            split2(o0, o1, h01, l01);
            split2(o2, o3, h23, l23);
            *(uint32_t*)(Xh + rA)           = h01;
            *(uint32_t*)(Xl + rA)           = l01;
            *(uint32_t*)(Xh + rA + 8 * 256) = h23;
            *(uint32_t*)(Xl + rA + 8 * 256) = l23;
        }
    }
}

// ---------------------------------------------------------------------------
// Merged weight transpose + split
// ---------------------------------------------------------------------------
__global__ void transpose_all(const float* Wqkv, const float* Wo, const float* W1,
                              const float* W2, const float* msg_W, const float* gat_W,
                              const float* spW1, const float* spW2,
                              __nv_bfloat16* Thi, __nv_bfloat16* Tlo) {
    const int z = blockIdx.z;
    const float* src;
    int dstoff, K, N;
    if (z < 2)       { src = Wqkv + (size_t)z * 256 * 768; dstoff = WT_QKV + z * 768 * 256; K = 256; N = 768; }
    else if (z < 4)  { int l = z - 2;  src = Wo + (size_t)l * 65536;  dstoff = WT_WO + l * 65536;  K = 256; N = 256; }
    else if (z < 6)  { int l = z - 4;  src = W1 + (size_t)l * 65536;  dstoff = WT_W1 + l * 65536;  K = 256; N = 256; }
    else if (z < 8)  { int l = z - 6;  src = W2 + (size_t)l * 65536;  dstoff = WT_W2 + l * 65536;  K = 256; N = 256; }
    else if (z < 11) { int r = z - 8;  src = msg_W + (size_t)r * 65536; dstoff = WT_MSG + r * 65536; K = 256; N = 256; }
    else if (z < 15) { int l = z - 11; src = gat_W + (size_t)l * 256 * 1024; dstoff = WT_GAT + l * 1024 * 256; K = 256; N = 1024; }
    else if (z < 16) { src = spW1; dstoff = WT_SP1; K = 256; N = 512; }
    else             { src = spW2; dstoff = WT_SP2; K = 512; N = 256; }

    int n0 = blockIdx.x * 32, k0 = blockIdx.y * 32;
    if (n0 >= N || k0 >= K) return;

    __shared__ float t[32][33];
    int x = threadIdx.x, y = threadIdx.y;
    #pragma unroll
    for (int i = 0; i < 4; i++)
        t[y + i * 8][x] = src[(size_t)(k0 + y + i * 8) * N + n0 + x];
    __syncthreads();
    #pragma unroll
    for (int i = 0; i < 4; i++) {
        float v = t[x][y + i * 8];
        __nv_bfloat16 h, l;
        split1(v, h, l);
        size_t o = (size_t)dstoff + (size_t)(n0 + y + i * 8) * K + k0 + x;
        Thi[o] = h; Tlo[o] = l;
    }
}

// identity split of msg_W (row-major [3,256,256]) for fused-weight GEMM B operand
__global__ void split_msg(const float* __restrict__ msg_W) {
    int i = blockIdx.x * 256 + threadIdx.x;
    __nv_bfloat16 h, l;
    split1(msg_W[i], h, l);
    g_MSGh[i] = h; g_MSGl[i] = l;
}

// fused bias: bf[l][r*1024+n] = sum_c msg_b[r][c] * gat_W[l][c][n]
__global__ void bias_fuse(const float* __restrict__ gat_W, const float* __restrict__ msg_b) {
    int lr = blockIdx.y;               // 0..11
    int l = lr / 3, r = lr % 3;
    int n = blockIdx.x * 128 + threadIdx.x;
    const float* gw = gat_W + (size_t)l * 256 * 1024 + n;
    const float* mb = msg_b + r * 256;
    float acc = 0.f;
    for (int c = 0; c < 256; c++) acc += mb[c] * gw[(size_t)c * 1024];
    g_BF[l * 3072 + r * 1024 + n] = acc;
}

// ---------------------------------------------------------------------------
// CSR build (once)
// ---------------------------------------------------------------------------
__global__ void csr_count(const int* __restrict__ dst, const int* __restrict__ etype) {
    int e = blockIdx.x * blockDim.x + threadIdx.x;
    if (e >= NEDGE) return;
    atomicAdd(&g_pos[etype[e] * NN + dst[e]], 1);
}

__global__ void __launch_bounds__(1024) csr_scan() {
    __shared__ int s[1024];
    const int tid = threadIdx.x;
    const int base = tid * 6;
    int local[6];
    int sum = 0;
    #pragma unroll
    for (int k = 0; k < 6; k++) { local[k] = sum; sum += g_pos[base + k]; }
    s[tid] = sum;
    __syncthreads();
    for (int d = 1; d < 1024; d <<= 1) {
        int v = (tid >= d) ? s[tid - d] : 0;
        __syncthreads();
        s[tid] += v;
        __syncthreads();
    }
    int pre = s[tid] - sum;
    #pragma unroll
    for (int k = 0; k < 6; k++) {
        g_off[base + k] = pre + local[k];
        g_pos[base + k] = pre + local[k];
    }
    if (tid == 1023) g_off[NSEG] = s[1023];
}

__global__ void csr_scatter(const int* __restrict__ src, const int* __restrict__ dst,
                            const int* __restrict__ etype) {
    int e = blockIdx.x * blockDim.x + threadIdx.x;
    if (e >= NEDGE) return;
    int p = atomicAdd(&g_pos[etype[e] * NN + dst[e]], 1);
    g_srt[p] = src[e];
}

// ---------------------------------------------------------------------------
// PE table + embedding
// ---------------------------------------------------------------------------
__global__ void pe_kernel() {
    int s = blockIdx.x, d = threadIdx.x;
    int i2 = d >> 1;
    float div = expf((float)(2 * i2) * (-logf(10000.f) / (float)DIM));
    float arg = (float)s * div;
    g_PE[s * DIM + d] = (d & 1) ? cosf(arg) : sinf(arg);
}

__global__ void embed_kernel(const float* __restrict__ tok_emb,
                             const int* __restrict__ tokens) {
    int row = blockIdx.x;
    int s = row & (SEQ - 1);
    int d = threadIdx.x;
    int tok = tokens[row];
    float v = tok_emb[(size_t)tok * DIM + d] * 16.f + g_PE[s * DIM + d];
    size_t o = (size_t)row * DIM + d;
    __nv_bfloat16 h, l;
    split1(v, h, l);
    g_Xh[o] = h; g_Xl[o] = l;
}

// ---------------------------------------------------------------------------
// Attention
// ---------------------------------------------------------------------------
__global__ void attn_kernel() {
    int n = blockIdx.x >> 3;
    int h = blockIdx.x & 7;
    __shared__ float Qs[SEQ][DH + 1];
    __shared__ float Ks[SEQ][DH + 1];
    __shared__ float Vs[SEQ][DH + 1];
    const float* base = g_QKV + (size_t)n * SEQ * 3 * DIM;
    for (int e = threadIdx.x; e < SEQ * DH; e += blockDim.x) {
        int r = e >> 5, d = e & 31;
        Qs[r][d] = base[r * 3 * DIM + h * DH + d];
        Ks[r][d] = base[r * 3 * DIM + DIM + h * DH + d];
        Vs[r][d] = base[r * 3 * DIM + 2 * DIM + h * DH + d];
    }
    __syncthreads();
    int i = threadIdx.x;
    float q[DH];
    #pragma unroll
    for (int d = 0; d < DH; d++) q[d] = Qs[i][d];
    const float scale = 0.17677669529663687f;
    float m = -1e30f, l = 0.f;
    float o[DH];
    #pragma unroll
    for (int d = 0; d < DH; d++) o[d] = 0.f;
    for (int j = 0; j < SEQ; j++) {
        float s0 = 0.f, s1 = 0.f, s2 = 0.f, s3 = 0.f;
        #pragma unroll
        for (int d = 0; d < DH; d += 4) {
            s0 += q[d]     * Ks[j][d];
            s1 += q[d + 1] * Ks[j][d + 1];
            s2 += q[d + 2] * Ks[j][d + 2];
            s3 += q[d + 3] * Ks[j][d + 3];
        }
        float s = ((s0 + s1) + (s2 + s3)) * scale;
        if (s > m) {
            float c = expf(m - s);
            l *= c;
            #pragma unroll
            for (int d = 0; d < DH; d++) o[d] *= c;
            m = s;
        }
        float p = expf(s - m);
        l += p;
        #pragma unroll
        for (int d = 0; d < DH; d++) o[d] += p * Vs[j][d];
    }
    float inv = 1.f / l;
    size_t ob = ((size_t)n * SEQ + i) * DIM + h * DH;
    #pragma unroll
    for (int d = 0; d < DH; d += 2) {
        uint32_t hi, lo;
        split2(o[d] * inv, o[d + 1] * inv, hi, lo);
        *(uint32_t*)(g_T1h + ob + d) = hi;
        *(uint32_t*)(g_T1l + ob + d) = lo;
    }
}

// ---------------------------------------------------------------------------
// mean over seq + type emb
// ---------------------------------------------------------------------------
__global__ void mean_kernel(const int* __restrict__ types,
                            const float* __restrict__ type_emb) {
    int n = blockIdx.x, d = threadIdx.x;
    float acc = 0.f;
    const __nv_bfloat16* bh = g_Xh + (size_t)n * SEQ * DIM + d;
    const __nv_bfloat16* bl = g_Xl + (size_t)n * SEQ * DIM + d;
    for (int s = 0; s < SEQ; s++)
        acc += __bfloat162float(bh[s * DIM]) + __bfloat162float(bl[s * DIM]);
    float v = acc * (1.f / SEQ) + type_emb[(size_t)types[n] * DIM + d];
    size_t o = (size_t)n * DIM + d;
    g_H[o] = v;
    __nv_bfloat16 h, l;
    split1(v, h, l);
    g_Hh[o] = h; g_Hl[o] = l;
}

// ---------------------------------------------------------------------------
// GNN kernels
// ---------------------------------------------------------------------------
__global__ void asd_kernel(const float* __restrict__ asrc,
                           const float* __restrict__ adst) {
    int i = blockIdx.x;
    int w = threadIdx.x >> 5, lane = threadIdx.x & 31;
    float s1 = 0.f, s2 = 0.f;
    const float* xg = g_XG + (size_t)i * GHEADS * DIM + w * DIM;
    #pragma unroll
    for (int d = lane; d < DIM; d += 32) {
        float xv = xg[d];
        s1 += xv * asrc[w * DIM + d];
        s2 += xv * adst[w * DIM + d];
    }
    #pragma unroll
    for (int off = 16; off > 0; off >>= 1) {
        s1 += __shfl_down_sync(0xffffffffu, s1, off);
        s2 += __shfl_down_sync(0xffffffffu, s2, off);
    }
    if (lane == 0) {
        g_AS[i * GHEADS + w] = s1;
        g_AD[i * GHEADS + w] = s2;
    }
}

__global__ void __launch_bounds__(128) csr_agg() {
    __shared__ float s_acc[4][DIM];
    const int i = blockIdx.x;
    const int w = threadIdx.x >> 5;
    const int lane = threadIdx.x & 31;
    const int rbase = (i >> 11) << 11;
    const int beg = g_off[i], end = g_off[i + 1];

    const float ad = g_AD[i * GHEADS + w];
    const float self_e = lrelu(g_AS[i * GHEADS + w] + ad);

    float m = self_e;
    for (int j = beg + lane; j < end; j += 32)
        m = fmaxf(m, lrelu(g_AS[(rbase + g_srt[j]) * GHEADS + w] + ad));
    #pragma unroll
    for (int off = 16; off > 0; off >>= 1)
        m = fmaxf(m, __shfl_xor_sync(0xffffffffu, m, off));

    float den = expf(self_e - m);
    float acc[8];
    const float* xs = g_XG + (size_t)i * (GHEADS * DIM) + w * DIM;
    #pragma unroll
    for (int k = 0; k < 8; k++) acc[k] = den * xs[lane + 32 * k];
    for (int j = beg; j < end; j++) {
        int s = rbase + g_srt[j];
        float wgt = expf(lrelu(g_AS[s * GHEADS + w] + ad) - m);
        den += wgt;
        const float* xv = g_XG + (size_t)s * (GHEADS * DIM) + w * DIM;
        #pragma unroll
        for (int k = 0; k < 8; k++) acc[k] += wgt * xv[lane + 32 * k];
    }
    float inv = 0.25f / den;
    #pragma unroll
    for (int k = 0; k < 8; k++) s_acc[w][lane + 32 * k] = acc[k] * inv;
    __syncthreads();
    float* nm = g_NUMR + (size_t)i * DIM;
    #pragma unroll
    for (int k = 0; k < 2; k++) {
        int d = threadIdx.x + 128 * k;
        nm[d] = s_acc[0][d] + s_acc[1][d] + s_acc[2][d] + s_acc[3][d];
    }
}

__global__ void combupd_kernel(const float* __restrict__ gb) {
    int n = blockIdx.x, d = threadIdx.x;
    float acc = g_NUMR[(size_t)n * DIM + d]
              + g_NUMR[(size_t)(NN + n) * DIM + d]
              + g_NUMR[(size_t)(2 * NN + n) * DIM + d];
    size_t o = (size_t)n * DIM + d;
    float v = fmaxf(g_H[o] + acc + 3.f * gb[d], 0.f);
    g_H[o] = v;
    __nv_bfloat16 h, l;
    split1(v, h, l);
    g_Hh[o] = h; g_Hl[o] = l;
}

__global__ void final_kernel(const float* __restrict__ log_c, float* __restrict__ out) {
    int n = blockIdx.x, d = threadIdx.x;
    __shared__ float sh[256];
    __shared__ float stat;
    float scale = sqrtf(expf(log_c[0]));
    float st = tanhf(g_TH[(size_t)n * DIM + d]) * 2.f * scale;
    sh[d] = st * st; __syncthreads();
    for (int s = 128; s > 0; s >>= 1) { if (d < s) sh[d] += sh[d + s]; __syncthreads(); }
    if (d == 0) stat = sh[0];
    __syncthreads();
    float r = fmaxf(sqrtf(stat), 1e-8f);
    if (d == 0) out[(size_t)n * 257] = coshf(r);
    out[(size_t)n * 257 + 1 + d] = sinhf(r) / r * st;
}

// ---------------------------------------------------------------------------
// Host orchestration
// ---------------------------------------------------------------------------
extern "C" void kernel_launch(void* const* d_in, const int* in_sizes, int n_in,
                              void* d_out, int out_size) {
    const float* tok_emb = (const float*)d_in[0];
    const float* Wqkv    = (const float*)d_in[1];
    const float* bqkv    = (const float*)d_in[2];
    const float* Wo      = (const float*)d_in[3];
    const float* bo      = (const float*)d_in[4];
    const float* ln1g    = (const float*)d_in[5];
    const float* ln1b    = (const float*)d_in[6];
    const float* ln2g    = (const float*)d_in[7];
    const float* ln2b    = (const float*)d_in[8];
    const float* W1      = (const float*)d_in[9];
    const float* b1      = (const float*)d_in[10];
    const float* W2      = (const float*)d_in[11];
    const float* b2      = (const float*)d_in[12];
    const float* type_emb= (const float*)d_in[13];
    const float* msg_W   = (const float*)d_in[14];
    const float* msg_b   = (const float*)d_in[15];
    const float* gat_W   = (const float*)d_in[16];
    const float* gat_b   = (const float*)d_in[17];
    const float* asrc    = (const float*)d_in[18];
    const float* adst    = (const float*)d_in[19];
    const float* spW1    = (const float*)d_in[20];
    const float* spb1    = (const float*)d_in[21];
    const float* spW2    = (const float*)d_in[22];
    const float* spb2    = (const float*)d_in[23];
    const float* log_c   = (const float*)d_in[24];
    const int*   tokens  = (const int*)d_in[25];
    const int*   types   = (const int*)d_in[26];
    const int*   eidx    = (const int*)d_in[27];
    const int*   etype   = (const int*)d_in[28];
    const int* esrc = eidx;
    const int* edst = eidx + NEDGE;
    float* out = (float*)d_out;

    float *pQKV, *pH, *pTH, *pXG, *pBF;
    int *pPos;
    __nv_bfloat16 *pXh, *pXl, *pT1h, *pT1l, *pHh, *pHl,
                  *pSPHh, *pSPHl, *pWTh, *pWTl, *pMSGh, *pMSGl, *pWFh, *pWFl;
    cudaGetSymbolAddress((void**)&pQKV,  g_QKV);
    cudaGetSymbolAddress((void**)&pH,    g_H);
    cudaGetSymbolAddress((void**)&pTH,   g_TH);
    cudaGetSymbolAddress((void**)&pXG,   g_XG);
    cudaGetSymbolAddress((void**)&pBF,   g_BF);
    cudaGetSymbolAddress((void**)&pPos,  g_pos);
    cudaGetSymbolAddress((void**)&pXh,   g_Xh);
    cudaGetSymbolAddress((void**)&pXl,   g_Xl);
    cudaGetSymbolAddress((void**)&pT1h,  g_T1h);
    cudaGetSymbolAddress((void**)&pT1l,  g_T1l);
    cudaGetSymbolAddress((void**)&pHh,   g_Hh);
    cudaGetSymbolAddress((void**)&pHl,   g_Hl);
    cudaGetSymbolAddress((void**)&pSPHh, g_SPHh);
    cudaGetSymbolAddress((void**)&pSPHl, g_SPHl);
    cudaGetSymbolAddress((void**)&pWTh,  g_WTh);
    cudaGetSymbolAddress((void**)&pWTl,  g_WTl);
    cudaGetSymbolAddress((void**)&pMSGh, g_MSGh);
    cudaGetSymbolAddress((void**)&pMSGl, g_MSGl);
    cudaGetSymbolAddress((void**)&pWFh,  g_WFh);
    cudaGetSymbolAddress((void**)&pWFl,  g_WFl);

    cudaFuncSetAttribute(gemm_bf16, cudaFuncAttributeMaxDynamicSharedMemorySize,
                         NSTAGE * STAGE_BYTES);
    cudaFuncSetAttribute(gemm_ln, cudaFuncAttributeMaxDynamicSharedMemorySize,
                         3 * LSTG + 4096 + 3 * 1024);
    const int SMEM   = NSTAGE * STAGE_BYTES;
    const int SMEMLN = 3 * LSTG + 4096 + 3 * 1024;

    // 0) weight prep, PE, CSR build, fused GAT weights (once)
    transpose_all<<<dim3(32, 16, 17), dim3(32, 8)>>>(
        Wqkv, Wo, W1, W2, msg_W, gat_W, spW1, spW2, pWTh, pWTl);
    split_msg<<<NREL * 256, 256>>>(msg_W);
    bias_fuse<<<dim3(8, 12), 128>>>(gat_W, msg_b);
    pe_kernel<<<SEQ, 256>>>();
    cudaMemsetAsync(pPos, 0, (NSEG + 1) * sizeof(int));
    csr_count<<<NEDGE / 256, 256>>>(edst, etype);
    csr_scan<<<1, 1024>>>();
    csr_scatter<<<NEDGE / 256, 256>>>(esrc, edst, etype);
    // WfT[l] = WgatT[l] @ msg_W  (batched over 3 relations; rmaj [r][1024][256])
    for (int l = 0; l < 4; l++)
        gemm_bf16<<<dim3(6, 8), 256, SMEM>>>(
            pWTh + WT_GAT + l * 1024 * 256, pWTl + WT_GAT + l * 1024 * 256, 256,
            pMSGh, pMSGl, nullptr, nullptr,
            pWFh + (size_t)l * 3 * 1024 * 256, pWFl + (size_t)l * 3 * 1024 * 256,
            1024, 768, 256, 0, 1024 * 256, 8);

    // 1) embedding + PE
    embed_kernel<<<NTOK, 256>>>(tok_emb, tokens);

    // 2) transformer encoder (LN fused into Wo / W2 GEMMs)
    for (int l = 0; l < 2; l++) {
        gemm_bf16<<<dim3(6, NTOK / 128), 256, SMEM>>>(
            pXh, pXl, 256, pWTh + WT_QKV + l * 768 * 256, pWTl + WT_QKV + l * 768 * 256,
            bqkv + l * 768, pQKV, nullptr, nullptr, NTOK, 768, 256, 0, 0, 0);
        attn_kernel<<<NN * NH, 64>>>();
        gemm_ln<<<NTOK / 128, 512, SMEMLN>>>(
            pT1h, pT1l, pWTh + WT_WO + l * 65536, pWTl + WT_WO + l * 65536,
            bo + l * 256, ln1g + l * 256, ln1b + l * 256, pXh, pXl);
        gemm_bf16<<<dim3(2, NTOK / 128), 256, SMEM>>>(
            pXh, pXl, 256, pWTh + WT_W1 + l * 65536, pWTl + WT_W1 + l * 65536,
            b1 + l * 256, nullptr, pT1h, pT1l, NTOK, 256, 256, 1, 0, 0);
        gemm_ln<<<NTOK / 128, 512, SMEMLN>>>(
            pT1h, pT1l, pWTh + WT_W2 + l * 65536, pWTl + WT_W2 + l * 65536,
            b2 + l * 256, ln2g + l * 256, ln2b + l * 256, pXh, pXl);
    }

    // 3) mean over seq + type embedding
    mean_kernel<<<NN, 256>>>(types, type_emb);

    // 4) 4 GNN layers: single fused GEMM XG = h @ Wf[l] (+fused bias), rel-major
    for (int l = 0; l < 4; l++) {
        gemm_bf16<<<dim3(24, NN / 128), 256, SMEM>>>(
            pHh, pHl, 256,
            pWFh + (size_t)l * 3 * 1024 * 256, pWFl + (size_t)l * 3 * 1024 * 256,
            pBF + l * 3072, pXG, nullptr, nullptr,
            NN, 3072, 256, 0, NN * 1024, 10);
        asd_kernel<<<NSEG, 128>>>(asrc + l * GHEADS * DIM, adst + l * GHEADS * DIM);
        csr_agg<<<NSEG, 128>>>();
        combupd_kernel<<<NN, 256>>>(gat_b + l * 256);
    }

    // 5) scoring MLP + Lorentz exp map
    gemm_bf16<<<dim3(4, NN / 128), 256, SMEM>>>(
        pHh, pHl, 256, pWTh + WT_SP1, pWTl + WT_SP1,
        spb1, nullptr, pSPHh, pSPHl, NN, 512, 256, 1, 0, 0);
    gemm_bf16<<<dim3(2, NN / 128), 256, SMEM>>>(
        pSPHh, pSPHl, 512, pWTh + WT_SP2, pWTl + WT_SP2,
        spb2, pTH, nullptr, nullptr, NN, 256, 512, 0, 0, 0);
    final_kernel<<<NN, 256>>>(log_c, out);
}

// round 12
// speedup vs baseline: 1.0807x; 1.0807x over previous
#include <cuda_runtime.h>
#include <cuda_bf16.h>
#include <math.h>
#include <stdint.h>

// ---------------------------------------------------------------------------
// Problem constants
// ---------------------------------------------------------------------------
#define NN      2048
#define SEQ     64
#define DIM     256
#define NH      8
#define DH      32
#define GHEADS  4
#define NEDGE   32768
#define NTOK    (NN*SEQ)
#define SPH     512
#define NREL    3
#define NSEG    (NREL*NN)     // 6144

// ---------------------------------------------------------------------------
// Scratch (device globals)
// ---------------------------------------------------------------------------
__device__ float g_QKV[NTOK*3*DIM];
__device__ float g_H  [NN*DIM];
__device__ float g_TH [NN*DIM];
__device__ float g_PE [SEQ*DIM];
__device__ float g_XG [NSEG*GHEADS*DIM];
__device__ float g_AS [NSEG*GHEADS];
__device__ float g_AD [NSEG*GHEADS];
__device__ float g_NUMR[NSEG*DIM];

// CSR of edges sorted by (rel, dst) — rebuilt each run (input-dependent)
__device__ int g_off[NSEG + 1];
__device__ int g_srt[NEDGE];

// bf16 hi/lo split activations
__device__ __nv_bfloat16 g_Xh [NTOK*DIM],  g_Xl [NTOK*DIM];
__device__ __nv_bfloat16 g_T1h[NTOK*DIM],  g_T1l[NTOK*DIM];
__device__ __nv_bfloat16 g_Hh [NN*DIM],    g_Hl [NN*DIM];
__device__ __nv_bfloat16 g_THAh[NREL*NN*DIM], g_THAl[NREL*NN*DIM];
__device__ __nv_bfloat16 g_SPHh[NN*SPH],   g_SPHl[NN*SPH];

// transposed + split weights, K-major [N, K]
#define WT_QKV   0
#define WT_WO    (WT_QKV + 2*768*256)
#define WT_W1    (WT_WO  + 2*256*256)
#define WT_W2    (WT_W1  + 2*256*256)
#define WT_MSG   (WT_W2  + 2*256*256)
#define WT_GAT   (WT_MSG + 3*256*256)
#define WT_SP1   (WT_GAT + 4*1024*256)
#define WT_SP2   (WT_SP1 + 512*256)
#define WT_TOTAL (WT_SP2 + 256*512)
__device__ __nv_bfloat16 g_WTh[WT_TOTAL], g_WTl[WT_TOTAL];

// ---------------------------------------------------------------------------
// Helpers
// ---------------------------------------------------------------------------
__device__ __forceinline__ float lrelu(float x) { return x > 0.f ? x : 0.2f * x; }

__device__ __forceinline__ uint32_t smem_u32(const void* p) {
    uint32_t a;
    asm("{ .reg .u64 t; cvta.to.shared.u64 t, %1; cvt.u32.u64 %0, t; }" : "=r"(a) : "l"(p));
    return a;
}

__device__ __forceinline__ void split1(float v, __nv_bfloat16& h, __nv_bfloat16& l) {
    h = __float2bfloat16_rn(v);
    l = __float2bfloat16_rn(v - __bfloat162float(h));
}

__device__ __forceinline__ void split2(float a, float b, uint32_t& hi, uint32_t& lo) {
    __nv_bfloat16 ha, la, hb, lb;
    split1(a, ha, la);
    split1(b, hb, lb);
    hi = (uint32_t)__bfloat16_as_ushort(ha) | ((uint32_t)__bfloat16_as_ushort(hb) << 16);
    lo = (uint32_t)__bfloat16_as_ushort(la) | ((uint32_t)__bfloat16_as_ushort(lb) << 16);
}

__device__ __forceinline__ float bflo(uint32_t x) {
    return __bfloat162float(__ushort_as_bfloat16((unsigned short)(x & 0xffffu)));
}
__device__ __forceinline__ float bfhi(uint32_t x) {
    return __bfloat162float(__ushort_as_bfloat16((unsigned short)(x >> 16)));
}

__device__ __forceinline__ void ldsm_x4(uint32_t* r, uint32_t a) {
    asm volatile("ldmatrix.sync.aligned.m8n8.x4.shared.b16 {%0,%1,%2,%3}, [%4];"
                 : "=r"(r[0]), "=r"(r[1]), "=r"(r[2]), "=r"(r[3]) : "r"(a));
}

__device__ __forceinline__ void mma16816(float* c, const uint32_t* a, const uint32_t* b) {
    asm volatile(
        "mma.sync.aligned.m16n8k16.row.col.f32.bf16.bf16.f32 "
        "{%0,%1,%2,%3}, {%4,%5,%6,%7}, {%8,%9}, {%0,%1,%2,%3};"
        : "+f"(c[0]), "+f"(c[1]), "+f"(c[2]), "+f"(c[3])
        : "r"(a[0]), "r"(a[1]), "r"(a[2]), "r"(a[3]), "r"(b[0]), "r"(b[1]));
}

__device__ __forceinline__ void cp_async16(uint32_t dst, const void* src) {
    asm volatile("cp.async.cg.shared.global [%0], [%1], 16;" :: "r"(dst), "l"(src) : "memory");
}
__device__ __forceinline__ void cp_commit() {
    asm volatile("cp.async.commit_group;" ::: "memory");
}
template<int W> __device__ __forceinline__ void cp_wait() {
    asm volatile("cp.async.wait_group %0;" :: "n"(W) : "memory");
}

// ---------------------------------------------------------------------------
// Pipelined bf16-split GEMM (256 threads, 128x128 tile, 3-stage)
// B fragments loaded via ldmatrix.x4 covering two adjacent n-tiles.
// ---------------------------------------------------------------------------
#define ARR_BYTES  8192
#define STAGE_BYTES (4*ARR_BYTES)
#define NSTAGE 3

__device__ __forceinline__ void gemm_issue(
    uint32_t sb, int stage, int tid,
    const __nv_bfloat16* Ahi, const __nv_bfloat16* Alo, int lda,
    const __nv_bfloat16* Bhi, const __nv_bfloat16* Blo, int K,
    int row0, int col0, int k0)
{
    #pragma unroll
    for (int i = 0; i < 8; i++) {
        int idx = tid + i * 256;
        int arr = idx >> 9;
        int j   = idx & 511;
        int r   = j >> 2;
        int c   = j & 3;
        uint32_t dst = sb + stage * STAGE_BYTES + arr * ARR_BYTES
                     + (uint32_t)(r * 4 + (c ^ ((r >> 1) & 3))) * 16;
        const __nv_bfloat16* src;
        if (arr == 0)      src = Ahi + (size_t)(row0 + r) * lda + k0 + c * 8;
        else if (arr == 1) src = Alo + (size_t)(row0 + r) * lda + k0 + c * 8;
        else if (arr == 2) src = Bhi + (size_t)(col0 + r) * K + k0 + c * 8;
        else               src = Blo + (size_t)(col0 + r) * K + k0 + c * 8;
        cp_async16(dst, src);
    }
    cp_commit();
}

__global__ void __launch_bounds__(256)
gemm_bf16(const __nv_bfloat16* __restrict__ Ahi, const __nv_bfloat16* __restrict__ Alo, int lda,
          const __nv_bfloat16* __restrict__ Bhi, const __nv_bfloat16* __restrict__ Blo,
          const float* __restrict__ bias,
          float* __restrict__ Cf,
          __nv_bfloat16* __restrict__ Chi, __nv_bfloat16* __restrict__ Clo,
          int M, int N, int K, int act, int rmaj) {
    extern __shared__ char sm[];
    const uint32_t sb = smem_u32(sm);
    const int tid  = threadIdx.x;
    const int lane = tid & 31;
    const int warp = tid >> 5;
    const int wm = warp & 3;
    const int wn = warp >> 2;
    const int row0 = blockIdx.y * 128;
    const int col0 = blockIdx.x * 128;

    float acc[2][8][4];
    #pragma unroll
    for (int i = 0; i < 2; i++)
        #pragma unroll
        for (int j = 0; j < 8; j++)
            #pragma unroll
            for (int k = 0; k < 4; k++) acc[i][j][k] = 0.f;

    const int nch = K >> 5;
    gemm_issue(sb, 0, tid, Ahi, Alo, lda, Bhi, Blo, K, row0, col0, 0);
    if (nch > 1)
        gemm_issue(sb, 1, tid, Ahi, Alo, lda, Bhi, Blo, K, row0, col0, 32);

    for (int ch = 0; ch < nch; ch++) {
        if (ch + 1 < nch) cp_wait<1>(); else cp_wait<0>();
        __syncthreads();

        const uint32_t base = sb + (ch % NSTAGE) * STAGE_BYTES;
        #pragma unroll
        for (int s = 0; s < 2; s++) {
            uint32_t ah[2][4], al[2][4];
            #pragma unroll
            for (int mt = 0; mt < 2; mt++) {
                int row = wm * 32 + mt * 16 + (lane & 15);
                int c = 2 * s + (lane >> 4);
                uint32_t off = (uint32_t)(row * 4 + (c ^ ((row >> 1) & 3))) * 16;
                ldsm_x4(ah[mt], base + off);
                ldsm_x4(al[mt], base + ARR_BYTES + off);
            }
            #pragma unroll
            for (int ntp = 0; ntp < 4; ntp++) {
                int nr = wn * 64 + (ntp * 2 + ((lane >> 4) & 1)) * 8 + (lane & 7);
                int c = 2 * s + ((lane >> 3) & 1);
                uint32_t off = (uint32_t)(nr * 4 + (c ^ ((nr >> 1) & 3))) * 16;
                uint32_t bh[4], bl[4];
                ldsm_x4(bh, base + 2 * ARR_BYTES + off);
                ldsm_x4(bl, base + 3 * ARR_BYTES + off);
                #pragma unroll
                for (int half = 0; half < 2; half++) {
                    int nt = ntp * 2 + half;
                    #pragma unroll
                    for (int mt = 0; mt < 2; mt++) {
                        mma16816(acc[mt][nt], ah[mt], bh + 2 * half);
                        mma16816(acc[mt][nt], ah[mt], bl + 2 * half);
                        mma16816(acc[mt][nt], al[mt], bh + 2 * half);
                    }
                }
            }
        }
        __syncthreads();
        if (ch + 2 < nch)
            gemm_issue(sb, (ch + 2) % NSTAGE, tid, Ahi, Alo, lda, Bhi, Blo, K,
                       row0, col0, (ch + 2) << 5);
    }

    const int g4 = lane >> 2, tig = lane & 3;
    #pragma unroll
    for (int nt = 0; nt < 8; nt++) {
        int col = col0 + wn * 64 + nt * 8 + tig * 2;
        float b0 = 0.f, b1 = 0.f;
        if (bias) { b0 = bias[col]; b1 = bias[col + 1]; }
        #pragma unroll
        for (int mt = 0; mt < 2; mt++) {
            int row = row0 + wm * 32 + mt * 16 + g4;
            float v0 = acc[mt][nt][0] + b0;
            float v1 = acc[mt][nt][1] + b1;
            float v2 = acc[mt][nt][2] + b0;
            float v3 = acc[mt][nt][3] + b1;
            if (act) {
                v0 = fmaxf(v0, 0.f); v1 = fmaxf(v1, 0.f);
                v2 = fmaxf(v2, 0.f); v3 = fmaxf(v3, 0.f);
            }
            if (Cf) {
                *(float2*)(Cf + (size_t)row * N + col)       = make_float2(v0, v1);
                *(float2*)(Cf + (size_t)(row + 8) * N + col) = make_float2(v2, v3);
            }
            if (Chi) {
                uint32_t h01, l01, h23, l23;
                split2(v0, v1, h01, l01);
                split2(v2, v3, h23, l23);
                size_t o0, o1;
                if (rmaj) {
                    o0 = (size_t)(col >> 8) * rmaj + (size_t)row * 256 + (col & 255);
                    o1 = o0 + 8 * 256;
                } else {
                    o0 = (size_t)row * N + col;
                    o1 = o0 + (size_t)8 * N;
                }
                *(uint32_t*)(Chi + o0) = h01;
                *(uint32_t*)(Clo + o0) = l01;
                *(uint32_t*)(Chi + o1) = h23;
                *(uint32_t*)(Clo + o1) = l23;
            }
        }
    }
}

// ---------------------------------------------------------------------------
// Fused GEMM + residual + LayerNorm
// ---------------------------------------------------------------------------
#define LSTG 49152

__device__ __forceinline__ void gemm_ln_issue(
    uint32_t sb, int stage, int tid, int row0, int k0,
    const __nv_bfloat16* Ahi, const __nv_bfloat16* Alo,
    const __nv_bfloat16* Bhi, const __nv_bfloat16* Blo)
{
    #pragma unroll
    for (int i = 0; i < 6; i++) {
        int idx = tid + i * 512;
        uint32_t stg = sb + stage * LSTG;
        const __nv_bfloat16* src;
        uint32_t dst;
        if (idx < 1024) {
            int j = idx & 511;
            int r = j >> 2, c = j & 3;
            dst = stg + ((idx >> 9) ? 8192u : 0u)
                + (uint32_t)(r * 4 + (c ^ ((r >> 1) & 3))) * 16;
            src = ((idx >> 9) ? Alo : Ahi) + (size_t)(row0 + r) * 256 + k0 + c * 8;
        } else {
            int j = (idx - 1024) & 1023;
            int r = j >> 2, c = j & 3;
            dst = stg + ((idx >= 2048) ? 32768u : 16384u)
                + (uint32_t)(r * 4 + (c ^ ((r >> 1) & 3))) * 16;
            src = ((idx >= 2048) ? Blo : Bhi) + (size_t)r * 256 + k0 + c * 8;
        }
        cp_async16(dst, src);
    }
    cp_commit();
}

__global__ void __launch_bounds__(512)
gemm_ln(const __nv_bfloat16* __restrict__ Ahi, const __nv_bfloat16* __restrict__ Alo,
        const __nv_bfloat16* __restrict__ Bhi, const __nv_bfloat16* __restrict__ Blo,
        const float* __restrict__ bias,
        const float* __restrict__ lng, const float* __restrict__ lnb,
        __nv_bfloat16* Xh, __nv_bfloat16* Xl) {
    extern __shared__ char sm[];
    const uint32_t sb = smem_u32(sm);
    float* s_sum  = (float*)(sm + 3 * LSTG);
    float* s_g    = (float*)(sm + 3 * LSTG + 4096);
    float* s_b    = s_g + 256;
    float* s_bias = s_b + 256;
    const int tid  = threadIdx.x;
    const int lane = tid & 31;
    const int warp = tid >> 5;
    const int wm = warp & 3;
    const int wn = warp >> 2;
    const int row0 = blockIdx.x * 128;

    if (tid < 256) { s_g[tid] = lng[tid]; s_b[tid] = lnb[tid]; s_bias[tid] = bias[tid]; }

    float acc[2][8][4];
    #pragma unroll
    for (int i = 0; i < 2; i++)
        #pragma unroll
        for (int j = 0; j < 8; j++)
            #pragma unroll
            for (int k = 0; k < 4; k++) acc[i][j][k] = 0.f;

    gemm_ln_issue(sb, 0, tid, row0, 0, Ahi, Alo, Bhi, Blo);
    gemm_ln_issue(sb, 1, tid, row0, 32, Ahi, Alo, Bhi, Blo);

    for (int ch = 0; ch < 8; ch++) {
        if (ch < 7) cp_wait<1>(); else cp_wait<0>();
        __syncthreads();
        const uint32_t base = sb + (ch % 3) * LSTG;
        #pragma unroll
        for (int s = 0; s < 2; s++) {
            uint32_t ah[2][4], al[2][4];
            #pragma unroll
            for (int mt = 0; mt < 2; mt++) {
                int row = wm * 32 + mt * 16 + (lane & 15);
                int c = 2 * s + (lane >> 4);
                uint32_t off = (uint32_t)(row * 4 + (c ^ ((row >> 1) & 3))) * 16;
                ldsm_x4(ah[mt], base + off);
                ldsm_x4(al[mt], base + 8192 + off);
            }
            #pragma unroll
            for (int ntp = 0; ntp < 4; ntp++) {
                int nr = wn * 64 + (ntp * 2 + ((lane >> 4) & 1)) * 8 + (lane & 7);
                int c = 2 * s + ((lane >> 3) & 1);
                uint32_t off = (uint32_t)(nr * 4 + (c ^ ((nr >> 1) & 3))) * 16;
                uint32_t bh[4], bl[4];
                ldsm_x4(bh, base + 16384 + off);
                ldsm_x4(bl, base + 32768 + off);
                #pragma unroll
                for (int half = 0; half < 2; half++) {
                    int nt = ntp * 2 + half;
                    #pragma unroll
                    for (int mt = 0; mt < 2; mt++) {
                        mma16816(acc[mt][nt], ah[mt], bh + 2 * half);
                        mma16816(acc[mt][nt], ah[mt], bl + 2 * half);
                        mma16816(acc[mt][nt], al[mt], bh + 2 * half);
                    }
                }
            }
        }
        __syncthreads();
        if (ch + 2 < 8)
            gemm_ln_issue(sb, (ch + 2) % 3, tid, row0, (ch + 2) * 32, Ahi, Alo, Bhi, Blo);
    }

    const int g4 = lane >> 2, tig = lane & 3;
    float ps[2][2][2];
    #pragma unroll
    for (int mt = 0; mt < 2; mt++)
        #pragma unroll
        for (int h = 0; h < 2; h++) { ps[mt][h][0] = 0.f; ps[mt][h][1] = 0.f; }

    #pragma unroll
    for (int nt = 0; nt < 8; nt++) {
        int col = wn * 64 + nt * 8 + tig * 2;
        float b0 = s_bias[col], b1 = s_bias[col + 1];
        #pragma unroll
        for (int mt = 0; mt < 2; mt++) {
            size_t rA = (size_t)(row0 + wm * 32 + mt * 16 + g4) * 256 + col;
            uint32_t rh0 = *(const uint32_t*)(Xh + rA);
            uint32_t rl0 = *(const uint32_t*)(Xl + rA);
            uint32_t rh1 = *(const uint32_t*)(Xh + rA + 8 * 256);
            uint32_t rl1 = *(const uint32_t*)(Xl + rA + 8 * 256);
            float v0 = acc[mt][nt][0] + b0 + bflo(rh0) + bflo(rl0);
            float v1 = acc[mt][nt][1] + b1 + bfhi(rh0) + bfhi(rl0);
            float v2 = acc[mt][nt][2] + b0 + bflo(rh1) + bflo(rl1);
            float v3 = acc[mt][nt][3] + b1 + bfhi(rh1) + bfhi(rl1);
            acc[mt][nt][0] = v0; acc[mt][nt][1] = v1;
            acc[mt][nt][2] = v2; acc[mt][nt][3] = v3;
            ps[mt][0][0] += v0 + v1; ps[mt][0][1] += v0 * v0 + v1 * v1;
            ps[mt][1][0] += v2 + v3; ps[mt][1][1] += v2 * v2 + v3 * v3;
        }
    }
    #pragma unroll
    for (int mt = 0; mt < 2; mt++)
        #pragma unroll
        for (int h = 0; h < 2; h++) {
            ps[mt][h][0] += __shfl_xor_sync(0xffffffffu, ps[mt][h][0], 1);
            ps[mt][h][0] += __shfl_xor_sync(0xffffffffu, ps[mt][h][0], 2);
            ps[mt][h][1] += __shfl_xor_sync(0xffffffffu, ps[mt][h][1], 1);
            ps[mt][h][1] += __shfl_xor_sync(0xffffffffu, ps[mt][h][1], 2);
        }
    if (tig == 0) {
        #pragma unroll
        for (int mt = 0; mt < 2; mt++)
            #pragma unroll
            for (int h = 0; h < 2; h++) {
                int row = wm * 32 + mt * 16 + g4 + h * 8;
                *(float2*)&s_sum[(row * 4 + wn) * 2] =
                    make_float2(ps[mt][h][0], ps[mt][h][1]);
            }
    }
    __syncthreads();

    float mean[2][2], rstd[2][2];
    #pragma unroll
    for (int mt = 0; mt < 2; mt++)
        #pragma unroll
        for (int h = 0; h < 2; h++) {
            int row = wm * 32 + mt * 16 + g4 + h * 8;
            float s = 0.f, q = 0.f;
            #pragma unroll
            for (int w = 0; w < 4; w++) {
                float2 t = *(float2*)&s_sum[(row * 4 + w) * 2];
                s += t.x; q += t.y;
            }
            float m = s * (1.f / 256.f);
            float var = fmaxf(q * (1.f / 256.f) - m * m, 0.f);
            mean[mt][h] = m;
            rstd[mt][h] = rsqrtf(var + 1e-5f);
        }

    #pragma unroll
    for (int nt = 0; nt < 8; nt++) {
        int col = wn * 64 + nt * 8 + tig * 2;
        float gg0 = s_g[col], gg1 = s_g[col + 1];
        float bb0 = s_b[col], bb1 = s_b[col + 1];
        #pragma unroll
        for (int mt = 0; mt < 2; mt++) {
            size_t rA = (size_t)(row0 + wm * 32 + mt * 16 + g4) * 256 + col;
            float o0 = (acc[mt][nt][0] - mean[mt][0]) * rstd[mt][0] * gg0 + bb0;
            float o1 = (acc[mt][nt][1] - mean[mt][0]) * rstd[mt][0] * gg1 + bb1;
            float o2 = (acc[mt][nt][2] - mean[mt][1]) * rstd[mt][1] * gg0 + bb0;
            float o3 = (acc[mt][nt][3] - mean[mt][1]) * rstd[mt][1] * gg1 + bb1;
            uint32_t h01, l01, h23, l23;
            split2(o0, o1, h01, l01);
            split2(o2, o3, h23, l23);
            *(uint32_t*)(Xh + rA)           = h01;
            *(uint32_t*)(Xl + rA)           = l01;
            *(uint32_t*)(Xh + rA + 8 * 256) = h23;
            *(uint32_t*)(Xl + rA + 8 * 256) = l23;
        }
    }
}

// ---------------------------------------------------------------------------
// Merged weight transpose + split
// ---------------------------------------------------------------------------
__global__ void transpose_all(const float* Wqkv, const float* Wo, const float* W1,
                              const float* W2, const float* msg_W, const float* gat_W,
                              const float* spW1, const float* spW2,
                              __nv_bfloat16* Thi, __nv_bfloat16* Tlo) {
    const int z = blockIdx.z;
    const float* src;
    int dstoff, K, N;
    if (z < 2)       { src = Wqkv + (size_t)z * 256 * 768; dstoff = WT_QKV + z * 768 * 256; K = 256; N = 768; }
    else if (z < 4)  { int l = z - 2;  src = Wo + (size_t)l * 65536;  dstoff = WT_WO + l * 65536;  K = 256; N = 256; }
    else if (z < 6)  { int l = z - 4;  src = W1 + (size_t)l * 65536;  dstoff = WT_W1 + l * 65536;  K = 256; N = 256; }
    else if (z < 8)  { int l = z - 6;  src = W2 + (size_t)l * 65536;  dstoff = WT_W2 + l * 65536;  K = 256; N = 256; }
    else if (z < 11) { int r = z - 8;  src = msg_W + (size_t)r * 65536; dstoff = WT_MSG + r * 65536; K = 256; N = 256; }
    else if (z < 15) { int l = z - 11; src = gat_W + (size_t)l * 256 * 1024; dstoff = WT_GAT + l * 1024 * 256; K = 256; N = 1024; }
    else if (z < 16) { src = spW1; dstoff = WT_SP1; K = 256; N = 512; }
    else             { src = spW2; dstoff = WT_SP2; K = 512; N = 256; }

    int n0 = blockIdx.x * 32, k0 = blockIdx.y * 32;
    if (n0 >= N || k0 >= K) return;

    __shared__ float t[32][33];
    int x = threadIdx.x, y = threadIdx.y;
    #pragma unroll
    for (int i = 0; i < 4; i++)
        t[y + i * 8][x] = src[(size_t)(k0 + y + i * 8) * N + n0 + x];
    __syncthreads();
    #pragma unroll
    for (int i = 0; i < 4; i++) {
        float v = t[x][y + i * 8];
        __nv_bfloat16 h, l;
        split1(v, h, l);
        size_t o = (size_t)dstoff + (size_t)(n0 + y + i * 8) * K + k0 + x;
        Thi[o] = h; Tlo[o] = l;
    }
}

// ---------------------------------------------------------------------------
// Fused CSR build: count + scan + scatter in one block (smem counters)
// ---------------------------------------------------------------------------
__global__ void __launch_bounds__(1024) csr_build(const int* __restrict__ src,
                                                  const int* __restrict__ dst,
                                                  const int* __restrict__ etype) {
    __shared__ int cnt[NSEG];          // 24 KB
    __shared__ int ws[1024];
    const int tid = threadIdx.x;
    #pragma unroll
    for (int k = 0; k < 6; k++) cnt[tid + k * 1024] = 0;
    __syncthreads();
    for (int e = tid; e < NEDGE; e += 1024)
        atomicAdd(&cnt[etype[e] * NN + dst[e]], 1);
    __syncthreads();
    const int base = tid * 6;
    int local[6];
    int sum = 0;
    #pragma unroll
    for (int k = 0; k < 6; k++) { local[k] = sum; sum += cnt[base + k]; }
    ws[tid] = sum;
    __syncthreads();
    for (int d = 1; d < 1024; d <<= 1) {
        int v = (tid >= d) ? ws[tid - d] : 0;
        __syncthreads();
        ws[tid] += v;
        __syncthreads();
    }
    int pre = ws[tid] - sum;
    #pragma unroll
    for (int k = 0; k < 6; k++) {
        g_off[base + k] = pre + local[k];
        cnt[base + k] = pre + local[k];
    }
    if (tid == 1023) g_off[NSEG] = ws[1023];
    __syncthreads();
    for (int e = tid; e < NEDGE; e += 1024) {
        int p = atomicAdd(&cnt[etype[e] * NN + dst[e]], 1);
        g_srt[p] = src[e];
    }
}

// ---------------------------------------------------------------------------
// PE table + embedding
// ---------------------------------------------------------------------------
__global__ void pe_kernel() {
    int s = blockIdx.x, d = threadIdx.x;
    int i2 = d >> 1;
    float div = expf((float)(2 * i2) * (-logf(10000.f) / (float)DIM));
    float arg = (float)s * div;
    g_PE[s * DIM + d] = (d & 1) ? cosf(arg) : sinf(arg);
}

__global__ void embed_kernel(const float* __restrict__ tok_emb,
                             const int* __restrict__ tokens) {
    int row = blockIdx.x;
    int s = row & (SEQ - 1);
    int d = threadIdx.x;
    int tok = tokens[row];
    float v = tok_emb[(size_t)tok * DIM + d] * 16.f + g_PE[s * DIM + d];
    size_t o = (size_t)row * DIM + d;
    __nv_bfloat16 h, l;
    split1(v, h, l);
    g_Xh[o] = h; g_Xl[o] = l;
}

// ---------------------------------------------------------------------------
// Attention
// ---------------------------------------------------------------------------
__global__ void attn_kernel() {
    int n = blockIdx.x >> 3;
    int h = blockIdx.x & 7;
    __shared__ float Qs[SEQ][DH + 1];
    __shared__ float Ks[SEQ][DH + 1];
    __shared__ float Vs[SEQ][DH + 1];
    const float* base = g_QKV + (size_t)n * SEQ * 3 * DIM;
    for (int e = threadIdx.x; e < SEQ * DH; e += blockDim.x) {
        int r = e >> 5, d = e & 31;
        Qs[r][d] = base[r * 3 * DIM + h * DH + d];
        Ks[r][d] = base[r * 3 * DIM + DIM + h * DH + d];
        Vs[r][d] = base[r * 3 * DIM + 2 * DIM + h * DH + d];
    }
    __syncthreads();
    int i = threadIdx.x;
    float q[DH];
    #pragma unroll
    for (int d = 0; d < DH; d++) q[d] = Qs[i][d];
    const float scale = 0.17677669529663687f;
    float m = -1e30f, l = 0.f;
    float o[DH];
    #pragma unroll
    for (int d = 0; d < DH; d++) o[d] = 0.f;
    for (int j = 0; j < SEQ; j++) {
        float s0 = 0.f, s1 = 0.f, s2 = 0.f, s3 = 0.f;
        #pragma unroll
        for (int d = 0; d < DH; d += 4) {
            s0 += q[d]     * Ks[j][d];
            s1 += q[d + 1] * Ks[j][d + 1];
            s2 += q[d + 2] * Ks[j][d + 2];
            s3 += q[d + 3] * Ks[j][d + 3];
        }
        float s = ((s0 + s1) + (s2 + s3)) * scale;
        if (s > m) {
            float c = expf(m - s);
            l *= c;
            #pragma unroll
            for (int d = 0; d < DH; d++) o[d] *= c;
            m = s;
        }
        float p = expf(s - m);
        l += p;
        #pragma unroll
        for (int d = 0; d < DH; d++) o[d] += p * Vs[j][d];
    }
    float inv = 1.f / l;
    size_t ob = ((size_t)n * SEQ + i) * DIM + h * DH;
    #pragma unroll
    for (int d = 0; d < DH; d += 2) {
        uint32_t hi, lo;
        split2(o[d] * inv, o[d + 1] * inv, hi, lo);
        *(uint32_t*)(g_T1h + ob + d) = hi;
        *(uint32_t*)(g_T1l + ob + d) = lo;
    }
}

// ---------------------------------------------------------------------------
// mean over seq + type emb
// ---------------------------------------------------------------------------
__global__ void mean_kernel(const int* __restrict__ types,
                            const float* __restrict__ type_emb) {
    int n = blockIdx.x, d = threadIdx.x;
    float acc = 0.f;
    const __nv_bfloat16* bh = g_Xh + (size_t)n * SEQ * DIM + d;
    const __nv_bfloat16* bl = g_Xl + (size_t)n * SEQ * DIM + d;
    for (int s = 0; s < SEQ; s++)
        acc += __bfloat162float(bh[s * DIM]) + __bfloat162float(bl[s * DIM]);
    float v = acc * (1.f / SEQ) + type_emb[(size_t)types[n] * DIM + d];
    size_t o = (size_t)n * DIM + d;
    g_H[o] = v;
    __nv_bfloat16 h, l;
    split1(v, h, l);
    g_Hh[o] = h; g_Hl[o] = l;
}

// ---------------------------------------------------------------------------
// GNN kernels
// ---------------------------------------------------------------------------
__global__ void asd_kernel(const float* __restrict__ asrc,
                           const float* __restrict__ adst) {
    int i = blockIdx.x;
    int w = threadIdx.x >> 5, lane = threadIdx.x & 31;
    float s1 = 0.f, s2 = 0.f;
    const float* xg = g_XG + (size_t)i * GHEADS * DIM + w * DIM;
    #pragma unroll
    for (int d = lane; d < DIM; d += 32) {
        float xv = xg[d];
        s1 += xv * asrc[w * DIM + d];
        s2 += xv * adst[w * DIM + d];
    }
    #pragma unroll
    for (int off = 16; off > 0; off >>= 1) {
        s1 += __shfl_down_sync(0xffffffffu, s1, off);
        s2 += __shfl_down_sync(0xffffffffu, s2, off);
    }
    if (lane == 0) {
        g_AS[i * GHEADS + w] = s1;
        g_AD[i * GHEADS + w] = s2;
    }
}

__global__ void __launch_bounds__(128) csr_agg() {
    __shared__ float s_acc[4][DIM];
    const int i = blockIdx.x;
    const int w = threadIdx.x >> 5;
    const int lane = threadIdx.x & 31;
    const int rbase = (i >> 11) << 11;
    const int beg = g_off[i], end = g_off[i + 1];

    const float ad = g_AD[i * GHEADS + w];
    const float self_e = lrelu(g_AS[i * GHEADS + w] + ad);

    float m = self_e;
    for (int j = beg + lane; j < end; j += 32)
        m = fmaxf(m, lrelu(g_AS[(rbase + g_srt[j]) * GHEADS + w] + ad));
    #pragma unroll
    for (int off = 16; off > 0; off >>= 1)
        m = fmaxf(m, __shfl_xor_sync(0xffffffffu, m, off));

    float den = expf(self_e - m);
    float acc[8];
    const float* xs = g_XG + (size_t)i * (GHEADS * DIM) + w * DIM;
    #pragma unroll
    for (int k = 0; k < 8; k++) acc[k] = den * xs[lane + 32 * k];
    for (int j = beg; j < end; j++) {
        int s = rbase + g_srt[j];
        float wgt = expf(lrelu(g_AS[s * GHEADS + w] + ad) - m);
        den += wgt;
        const float* xv = g_XG + (size_t)s * (GHEADS * DIM) + w * DIM;
        #pragma unroll
        for (int k = 0; k < 8; k++) acc[k] += wgt * xv[lane + 32 * k];
    }
    float inv = 0.25f / den;
    #pragma unroll
    for (int k = 0; k < 8; k++) s_acc[w][lane + 32 * k] = acc[k] * inv;
    __syncthreads();
    float* nm = g_NUMR + (size_t)i * DIM;
    #pragma unroll
    for (int k = 0; k < 2; k++) {
        int d = threadIdx.x + 128 * k;
        nm[d] = s_acc[0][d] + s_acc[1][d] + s_acc[2][d] + s_acc[3][d];
    }
}

__global__ void combupd_kernel(const float* __restrict__ gb) {
    int n = blockIdx.x, d = threadIdx.x;
    float acc = g_NUMR[(size_t)n * DIM + d]
              + g_NUMR[(size_t)(NN + n) * DIM + d]
              + g_NUMR[(size_t)(2 * NN + n) * DIM + d];
    size_t o = (size_t)n * DIM + d;
    float v = fmaxf(g_H[o] + acc + 3.f * gb[d], 0.f);
    g_H[o] = v;
    __nv_bfloat16 h, l;
    split1(v, h, l);
    g_Hh[o] = h; g_Hl[o] = l;
}

__global__ void final_kernel(const float* __restrict__ log_c, float* __restrict__ out) {
    int n = blockIdx.x, d = threadIdx.x;
    __shared__ float sh[256];
    __shared__ float stat;
    float scale = sqrtf(expf(log_c[0]));
    float st = tanhf(g_TH[(size_t)n * DIM + d]) * 2.f * scale;
    sh[d] = st * st; __syncthreads();
    for (int s = 128; s > 0; s >>= 1) { if (d < s) sh[d] += sh[d + s]; __syncthreads(); }
    if (d == 0) stat = sh[0];
    __syncthreads();
    float r = fmaxf(sqrtf(stat), 1e-8f);
    if (d == 0) out[(size_t)n * 257] = coshf(r);
    out[(size_t)n * 257 + 1 + d] = sinhf(r) / r * st;
}

// ---------------------------------------------------------------------------
// Host orchestration
// ---------------------------------------------------------------------------
extern "C" void kernel_launch(void* const* d_in, const int* in_sizes, int n_in,
                              void* d_out, int out_size) {
    const float* tok_emb = (const float*)d_in[0];
    const float* Wqkv    = (const float*)d_in[1];
    const float* bqkv    = (const float*)d_in[2];
    const float* Wo      = (const float*)d_in[3];
    const float* bo      = (const float*)d_in[4];
    const float* ln1g    = (const float*)d_in[5];
    const float* ln1b    = (const float*)d_in[6];
    const float* ln2g    = (const float*)d_in[7];
    const float* ln2b    = (const float*)d_in[8];
    const float* W1      = (const float*)d_in[9];
    const float* b1      = (const float*)d_in[10];
    const float* W2      = (const float*)d_in[11];
    const float* b2      = (const float*)d_in[12];
    const float* type_emb= (const float*)d_in[13];
    const float* msg_W   = (const float*)d_in[14];
    const float* msg_b   = (const float*)d_in[15];
    const float* gat_W   = (const float*)d_in[16];
    const float* gat_b   = (const float*)d_in[17];
    const float* asrc    = (const float*)d_in[18];
    const float* adst    = (const float*)d_in[19];
    const float* spW1    = (const float*)d_in[20];
    const float* spb1    = (const float*)d_in[21];
    const float* spW2    = (const float*)d_in[22];
    const float* spb2    = (const float*)d_in[23];
    const float* log_c   = (const float*)d_in[24];
    const int*   tokens  = (const int*)d_in[25];
    const int*   types   = (const int*)d_in[26];
    const int*   eidx    = (const int*)d_in[27];
    const int*   etype   = (const int*)d_in[28];
    const int* esrc = eidx;
    const int* edst = eidx + NEDGE;
    float* out = (float*)d_out;

    float *pQKV, *pH, *pTH, *pXG;
    __nv_bfloat16 *pXh, *pXl, *pT1h, *pT1l, *pHh, *pHl, *pTHAh, *pTHAl,
                  *pSPHh, *pSPHl, *pWTh, *pWTl;
    cudaGetSymbolAddress((void**)&pQKV,  g_QKV);
    cudaGetSymbolAddress((void**)&pH,    g_H);
    cudaGetSymbolAddress((void**)&pTH,   g_TH);
    cudaGetSymbolAddress((void**)&pXG,   g_XG);
    cudaGetSymbolAddress((void**)&pXh,   g_Xh);
    cudaGetSymbolAddress((void**)&pXl,   g_Xl);
    cudaGetSymbolAddress((void**)&pT1h,  g_T1h);
    cudaGetSymbolAddress((void**)&pT1l,  g_T1l);
    cudaGetSymbolAddress((void**)&pHh,   g_Hh);
    cudaGetSymbolAddress((void**)&pHl,   g_Hl);
    cudaGetSymbolAddress((void**)&pTHAh, g_THAh);
    cudaGetSymbolAddress((void**)&pTHAl, g_THAl);
    cudaGetSymbolAddress((void**)&pSPHh, g_SPHh);
    cudaGetSymbolAddress((void**)&pSPHl, g_SPHl);
    cudaGetSymbolAddress((void**)&pWTh,  g_WTh);
    cudaGetSymbolAddress((void**)&pWTl,  g_WTl);

    cudaFuncSetAttribute(gemm_bf16, cudaFuncAttributeMaxDynamicSharedMemorySize,
                         NSTAGE * STAGE_BYTES);
    cudaFuncSetAttribute(gemm_ln, cudaFuncAttributeMaxDynamicSharedMemorySize,
                         3 * LSTG + 4096 + 3 * 1024);
    const int SMEM   = NSTAGE * STAGE_BYTES;
    const int SMEMLN = 3 * LSTG + 4096 + 3 * 1024;

    // 0) merged weight transpose+split, PE, fused CSR build
    transpose_all<<<dim3(32, 16, 17), dim3(32, 8)>>>(
        Wqkv, Wo, W1, W2, msg_W, gat_W, spW1, spW2, pWTh, pWTl);
    pe_kernel<<<SEQ, 256>>>();
    csr_build<<<1, 1024>>>(esrc, edst, etype);

    // 1) embedding + PE
    embed_kernel<<<NTOK, 256>>>(tok_emb, tokens);

    // 2) transformer encoder (LN fused into Wo / W2 GEMMs)
    for (int l = 0; l < 2; l++) {
        gemm_bf16<<<dim3(6, NTOK / 128), 256, SMEM>>>(
            pXh, pXl, 256, pWTh + WT_QKV + l * 768 * 256, pWTl + WT_QKV + l * 768 * 256,
            bqkv + l * 768, pQKV, nullptr, nullptr, NTOK, 768, 256, 0, 0);
        attn_kernel<<<NN * NH, 64>>>();
        gemm_ln<<<NTOK / 128, 512, SMEMLN>>>(
            pT1h, pT1l, pWTh + WT_WO + l * 65536, pWTl + WT_WO + l * 65536,
            bo + l * 256, ln1g + l * 256, ln1b + l * 256, pXh, pXl);
        gemm_bf16<<<dim3(2, NTOK / 128), 256, SMEM>>>(
            pXh, pXl, 256, pWTh + WT_W1 + l * 65536, pWTl + WT_W1 + l * 65536,
            b1 + l * 256, nullptr, pT1h, pT1l, NTOK, 256, 256, 1, 0);
        gemm_ln<<<NTOK / 128, 512, SMEMLN>>>(
            pT1h, pT1l, pWTh + WT_W2 + l * 65536, pWTl + WT_W2 + l * 65536,
            b2 + l * 256, ln2g + l * 256, ln2b + l * 256, pXh, pXl);
    }

    // 3) mean over seq + type embedding
    mean_kernel<<<NN, 256>>>(types, type_emb);

    // 4) 4 GNN layers (relations batched; CSR aggregation with head-mean fused)
    for (int l = 0; l < 4; l++) {
        gemm_bf16<<<dim3(6, NN / 128), 256, SMEM>>>(
            pHh, pHl, 256, pWTh + WT_MSG, pWTl + WT_MSG,
            msg_b, nullptr, pTHAh, pTHAl, NN, 768, 256, 0, NN * DIM);
        gemm_bf16<<<dim3(8, NSEG / 128), 256, SMEM>>>(
            pTHAh, pTHAl, 256,
            pWTh + WT_GAT + l * 1024 * 256, pWTl + WT_GAT + l * 1024 * 256,
            nullptr, pXG, nullptr, nullptr, NSEG, 1024, 256, 0, 0);
        asd_kernel<<<NSEG, 128>>>(asrc + l * GHEADS * DIM, adst + l * GHEADS * DIM);
        csr_agg<<<NSEG, 128>>>();
        combupd_kernel<<<NN, 256>>>(gat_b + l * 256);
    }

    // 5) scoring MLP + Lorentz exp map
    gemm_bf16<<<dim3(4, NN / 128), 256, SMEM>>>(
        pHh, pHl, 256, pWTh + WT_SP1, pWTl + WT_SP1,
        spb1, nullptr, pSPHh, pSPHl, NN, 512, 256, 1, 0);
    gemm_bf16<<<dim3(2, NN / 128), 256, SMEM>>>(
        pSPHh, pSPHl, 512, pWTh + WT_SP2, pWTl + WT_SP2,
        spb2, pTH, nullptr, nullptr, NN, 256, 512, 0, 0);
    final_kernel<<<NN, 256>>>(log_c, out);
}

// round 13
// speedup vs baseline: 1.1103x; 1.0274x over previous
#include <cuda_runtime.h>
#include <cuda_bf16.h>
#include <math.h>
#include <stdint.h>

// ---------------------------------------------------------------------------
// Problem constants
// ---------------------------------------------------------------------------
#define NN      2048
#define SEQ     64
#define DIM     256
#define NH      8
#define DH      32
#define GHEADS  4
#define NEDGE   32768
#define NTOK    (NN*SEQ)
#define SPH     512
#define NREL    3
#define NSEG    (NREL*NN)     // 6144

// ---------------------------------------------------------------------------
// Scratch (device globals)
// ---------------------------------------------------------------------------
__device__ float g_H  [NN*DIM];
__device__ float g_TH [NN*DIM];
__device__ float g_PE [SEQ*DIM];
__device__ float g_XG [NSEG*GHEADS*DIM];
__device__ float g_AS [NSEG*GHEADS];
__device__ float g_AD [NSEG*GHEADS];
__device__ float g_NUMR[NSEG*DIM];

// CSR of edges sorted by (rel, dst)
__device__ int g_off[NSEG + 1];
__device__ int g_srt[NEDGE];

// bf16 activations
__device__ __nv_bfloat16 g_QKVh[NTOK*3*DIM];                 // QKV, bf16 storage
__device__ __nv_bfloat16 g_Xh [NTOK*DIM],  g_Xl [NTOK*DIM];
__device__ __nv_bfloat16 g_T1h[NTOK*DIM],  g_T1l[NTOK*DIM];
__device__ __nv_bfloat16 g_Hh [NN*DIM],    g_Hl [NN*DIM];
__device__ __nv_bfloat16 g_THAh[NREL*NN*DIM], g_THAl[NREL*NN*DIM];
__device__ __nv_bfloat16 g_SPHh[NN*SPH],   g_SPHl[NN*SPH];

// transposed + split weights, K-major [N, K]
#define WT_QKV   0
#define WT_WO    (WT_QKV + 2*768*256)
#define WT_W1    (WT_WO  + 2*256*256)
#define WT_W2    (WT_W1  + 2*256*256)
#define WT_MSG   (WT_W2  + 2*256*256)
#define WT_GAT   (WT_MSG + 3*256*256)
#define WT_SP1   (WT_GAT + 4*1024*256)
#define WT_SP2   (WT_SP1 + 512*256)
#define WT_TOTAL (WT_SP2 + 256*512)
__device__ __nv_bfloat16 g_WTh[WT_TOTAL], g_WTl[WT_TOTAL];

// ---------------------------------------------------------------------------
// Helpers
// ---------------------------------------------------------------------------
__device__ __forceinline__ float lrelu(float x) { return x > 0.f ? x : 0.2f * x; }

__device__ __forceinline__ uint32_t smem_u32(const void* p) {
    uint32_t a;
    asm("{ .reg .u64 t; cvta.to.shared.u64 t, %1; cvt.u32.u64 %0, t; }" : "=r"(a) : "l"(p));
    return a;
}

__device__ __forceinline__ void split1(float v, __nv_bfloat16& h, __nv_bfloat16& l) {
    h = __float2bfloat16_rn(v);
    l = __float2bfloat16_rn(v - __bfloat162float(h));
}

__device__ __forceinline__ void split2(float a, float b, uint32_t& hi, uint32_t& lo) {
    __nv_bfloat16 ha, la, hb, lb;
    split1(a, ha, la);
    split1(b, hb, lb);
    hi = (uint32_t)__bfloat16_as_ushort(ha) | ((uint32_t)__bfloat16_as_ushort(hb) << 16);
    lo = (uint32_t)__bfloat16_as_ushort(la) | ((uint32_t)__bfloat16_as_ushort(lb) << 16);
}

__device__ __forceinline__ uint32_t pack2(float a, float b) {
    __nv_bfloat16 ha = __float2bfloat16_rn(a), hb = __float2bfloat16_rn(b);
    return (uint32_t)__bfloat16_as_ushort(ha) | ((uint32_t)__bfloat16_as_ushort(hb) << 16);
}

__device__ __forceinline__ float bflo(uint32_t x) {
    return __bfloat162float(__ushort_as_bfloat16((unsigned short)(x & 0xffffu)));
}
__device__ __forceinline__ float bfhi(uint32_t x) {
    return __bfloat162float(__ushort_as_bfloat16((unsigned short)(x >> 16)));
}

__device__ __forceinline__ void ldsm_x4(uint32_t* r, uint32_t a) {
    asm volatile("ldmatrix.sync.aligned.m8n8.x4.shared.b16 {%0,%1,%2,%3}, [%4];"
                 : "=r"(r[0]), "=r"(r[1]), "=r"(r[2]), "=r"(r[3]) : "r"(a));
}

__device__ __forceinline__ void mma16816(float* c, const uint32_t* a, const uint32_t* b) {
    asm volatile(
        "mma.sync.aligned.m16n8k16.row.col.f32.bf16.bf16.f32 "
        "{%0,%1,%2,%3}, {%4,%5,%6,%7}, {%8,%9}, {%0,%1,%2,%3};"
        : "+f"(c[0]), "+f"(c[1]), "+f"(c[2]), "+f"(c[3])
        : "r"(a[0]), "r"(a[1]), "r"(a[2]), "r"(a[3]), "r"(b[0]), "r"(b[1]));
}

__device__ __forceinline__ void cp_async16(uint32_t dst, const void* src) {
    asm volatile("cp.async.cg.shared.global [%0], [%1], 16;" :: "r"(dst), "l"(src) : "memory");
}
__device__ __forceinline__ void cp_commit() {
    asm volatile("cp.async.commit_group;" ::: "memory");
}
template<int W> __device__ __forceinline__ void cp_wait() {
    asm volatile("cp.async.wait_group %0;" :: "n"(W) : "memory");
}

// ---------------------------------------------------------------------------
// Pipelined bf16-split GEMM (256 threads, 128x128 tile, 3-stage)
// Outputs: fp32 Cf, and/or split (Chi,Clo); if Clo==nullptr, Chi gets hi-only.
// ---------------------------------------------------------------------------
#define ARR_BYTES  8192
#define STAGE_BYTES (4*ARR_BYTES)
#define NSTAGE 3

__device__ __forceinline__ void gemm_issue(
    uint32_t sb, int stage, int tid,
    const __nv_bfloat16* Ahi, const __nv_bfloat16* Alo, int lda,
    const __nv_bfloat16* Bhi, const __nv_bfloat16* Blo, int K,
    int row0, int col0, int k0)
{
    #pragma unroll
    for (int i = 0; i < 8; i++) {
        int idx = tid + i * 256;
        int arr = idx >> 9;
        int j   = idx & 511;
        int r   = j >> 2;
        int c   = j & 3;
        uint32_t dst = sb + stage * STAGE_BYTES + arr * ARR_BYTES
                     + (uint32_t)(r * 4 + (c ^ ((r >> 1) & 3))) * 16;
        const __nv_bfloat16* src;
        if (arr == 0)      src = Ahi + (size_t)(row0 + r) * lda + k0 + c * 8;
        else if (arr == 1) src = Alo + (size_t)(row0 + r) * lda + k0 + c * 8;
        else if (arr == 2) src = Bhi + (size_t)(col0 + r) * K + k0 + c * 8;
        else               src = Blo + (size_t)(col0 + r) * K + k0 + c * 8;
        cp_async16(dst, src);
    }
    cp_commit();
}

__global__ void __launch_bounds__(256)
gemm_bf16(const __nv_bfloat16* __restrict__ Ahi, const __nv_bfloat16* __restrict__ Alo, int lda,
          const __nv_bfloat16* __restrict__ Bhi, const __nv_bfloat16* __restrict__ Blo,
          const float* __restrict__ bias,
          float* __restrict__ Cf,
          __nv_bfloat16* __restrict__ Chi, __nv_bfloat16* __restrict__ Clo,
          int M, int N, int K, int act, int rmaj) {
    extern __shared__ char sm[];
    const uint32_t sb = smem_u32(sm);
    const int tid  = threadIdx.x;
    const int lane = tid & 31;
    const int warp = tid >> 5;
    const int wm = warp & 3;
    const int wn = warp >> 2;
    const int row0 = blockIdx.y * 128;
    const int col0 = blockIdx.x * 128;

    float acc[2][8][4];
    #pragma unroll
    for (int i = 0; i < 2; i++)
        #pragma unroll
        for (int j = 0; j < 8; j++)
            #pragma unroll
            for (int k = 0; k < 4; k++) acc[i][j][k] = 0.f;

    const int nch = K >> 5;
    gemm_issue(sb, 0, tid, Ahi, Alo, lda, Bhi, Blo, K, row0, col0, 0);
    if (nch > 1)
        gemm_issue(sb, 1, tid, Ahi, Alo, lda, Bhi, Blo, K, row0, col0, 32);

    for (int ch = 0; ch < nch; ch++) {
        if (ch + 1 < nch) cp_wait<1>(); else cp_wait<0>();
        __syncthreads();

        const uint32_t base = sb + (ch % NSTAGE) * STAGE_BYTES;
        #pragma unroll
        for (int s = 0; s < 2; s++) {
            uint32_t ah[2][4], al[2][4];
            #pragma unroll
            for (int mt = 0; mt < 2; mt++) {
                int row = wm * 32 + mt * 16 + (lane & 15);
                int c = 2 * s + (lane >> 4);
                uint32_t off = (uint32_t)(row * 4 + (c ^ ((row >> 1) & 3))) * 16;
                ldsm_x4(ah[mt], base + off);
                ldsm_x4(al[mt], base + ARR_BYTES + off);
            }
            #pragma unroll
            for (int ntp = 0; ntp < 4; ntp++) {
                int nr = wn * 64 + (ntp * 2 + ((lane >> 4) & 1)) * 8 + (lane & 7);
                int c = 2 * s + ((lane >> 3) & 1);
                uint32_t off = (uint32_t)(nr * 4 + (c ^ ((nr >> 1) & 3))) * 16;
                uint32_t bh[4], bl[4];
                ldsm_x4(bh, base + 2 * ARR_BYTES + off);
                ldsm_x4(bl, base + 3 * ARR_BYTES + off);
                #pragma unroll
                for (int half = 0; half < 2; half++) {
                    int nt = ntp * 2 + half;
                    #pragma unroll
                    for (int mt = 0; mt < 2; mt++) {
                        mma16816(acc[mt][nt], ah[mt], bh + 2 * half);
                        mma16816(acc[mt][nt], ah[mt], bl + 2 * half);
                        mma16816(acc[mt][nt], al[mt], bh + 2 * half);
                    }
                }
            }
        }
        __syncthreads();
        if (ch + 2 < nch)
            gemm_issue(sb, (ch + 2) % NSTAGE, tid, Ahi, Alo, lda, Bhi, Blo, K,
                       row0, col0, (ch + 2) << 5);
    }

    const int g4 = lane >> 2, tig = lane & 3;
    #pragma unroll
    for (int nt = 0; nt < 8; nt++) {
        int col = col0 + wn * 64 + nt * 8 + tig * 2;
        float b0 = 0.f, b1 = 0.f;
        if (bias) { b0 = bias[col]; b1 = bias[col + 1]; }
        #pragma unroll
        for (int mt = 0; mt < 2; mt++) {
            int row = row0 + wm * 32 + mt * 16 + g4;
            float v0 = acc[mt][nt][0] + b0;
            float v1 = acc[mt][nt][1] + b1;
            float v2 = acc[mt][nt][2] + b0;
            float v3 = acc[mt][nt][3] + b1;
            if (act) {
                v0 = fmaxf(v0, 0.f); v1 = fmaxf(v1, 0.f);
                v2 = fmaxf(v2, 0.f); v3 = fmaxf(v3, 0.f);
            }
            size_t o0, o1;
            if (rmaj) {
                o0 = (size_t)(col >> 8) * rmaj + (size_t)row * 256 + (col & 255);
                o1 = o0 + 8 * 256;
            } else {
                o0 = (size_t)row * N + col;
                o1 = o0 + (size_t)8 * N;
            }
            if (Cf) {
                *(float2*)(Cf + o0) = make_float2(v0, v1);
                *(float2*)(Cf + o1) = make_float2(v2, v3);
            }
            if (Chi) {
                if (Clo) {
                    uint32_t h01, l01, h23, l23;
                    split2(v0, v1, h01, l01);
                    split2(v2, v3, h23, l23);
                    *(uint32_t*)(Chi + o0) = h01;
                    *(uint32_t*)(Clo + o0) = l01;
                    *(uint32_t*)(Chi + o1) = h23;
                    *(uint32_t*)(Clo + o1) = l23;
                } else {
                    *(uint32_t*)(Chi + o0) = pack2(v0, v1);
                    *(uint32_t*)(Chi + o1) = pack2(v2, v3);
                }
            }
        }
    }
}

// ---------------------------------------------------------------------------
// Fused GEMM + residual + LayerNorm
// ---------------------------------------------------------------------------
#define LSTG 49152

__device__ __forceinline__ void gemm_ln_issue(
    uint32_t sb, int stage, int tid, int row0, int k0,
    const __nv_bfloat16* Ahi, const __nv_bfloat16* Alo,
    const __nv_bfloat16* Bhi, const __nv_bfloat16* Blo)
{
    #pragma unroll
    for (int i = 0; i < 6; i++) {
        int idx = tid + i * 512;
        uint32_t stg = sb + stage * LSTG;
        const __nv_bfloat16* src;
        uint32_t dst;
        if (idx < 1024) {
            int j = idx & 511;
            int r = j >> 2, c = j & 3;
            dst = stg + ((idx >> 9) ? 8192u : 0u)
                + (uint32_t)(r * 4 + (c ^ ((r >> 1) & 3))) * 16;
            src = ((idx >> 9) ? Alo : Ahi) + (size_t)(row0 + r) * 256 + k0 + c * 8;
        } else {
            int j = (idx - 1024) & 1023;
            int r = j >> 2, c = j & 3;
            dst = stg + ((idx >= 2048) ? 32768u : 16384u)
                + (uint32_t)(r * 4 + (c ^ ((r >> 1) & 3))) * 16;
            src = ((idx >= 2048) ? Blo : Bhi) + (size_t)r * 256 + k0 + c * 8;
        }
        cp_async16(dst, src);
    }
    cp_commit();
}

__global__ void __launch_bounds__(512)
gemm_ln(const __nv_bfloat16* __restrict__ Ahi, const __nv_bfloat16* __restrict__ Alo,
        const __nv_bfloat16* __restrict__ Bhi, const __nv_bfloat16* __restrict__ Blo,
        const float* __restrict__ bias,
        const float* __restrict__ lng, const float* __restrict__ lnb,
        __nv_bfloat16* Xh, __nv_bfloat16* Xl) {
    extern __shared__ char sm[];
    const uint32_t sb = smem_u32(sm);
    float* s_sum  = (float*)(sm + 3 * LSTG);
    float* s_g    = (float*)(sm + 3 * LSTG + 4096);
    float* s_b    = s_g + 256;
    float* s_bias = s_b + 256;
    const int tid  = threadIdx.x;
    const int lane = tid & 31;
    const int warp = tid >> 5;
    const int wm = warp & 3;
    const int wn = warp >> 2;
    const int row0 = blockIdx.x * 128;

    if (tid < 256) { s_g[tid] = lng[tid]; s_b[tid] = lnb[tid]; s_bias[tid] = bias[tid]; }

    float acc[2][8][4];
    #pragma unroll
    for (int i = 0; i < 2; i++)
        #pragma unroll
        for (int j = 0; j < 8; j++)
            #pragma unroll
            for (int k = 0; k < 4; k++) acc[i][j][k] = 0.f;

    gemm_ln_issue(sb, 0, tid, row0, 0, Ahi, Alo, Bhi, Blo);
    gemm_ln_issue(sb, 1, tid, row0, 32, Ahi, Alo, Bhi, Blo);

    for (int ch = 0; ch < 8; ch++) {
        if (ch < 7) cp_wait<1>(); else cp_wait<0>();
        __syncthreads();
        const uint32_t base = sb + (ch % 3) * LSTG;
        #pragma unroll
        for (int s = 0; s < 2; s++) {
            uint32_t ah[2][4], al[2][4];
            #pragma unroll
            for (int mt = 0; mt < 2; mt++) {
                int row = wm * 32 + mt * 16 + (lane & 15);
                int c = 2 * s + (lane >> 4);
                uint32_t off = (uint32_t)(row * 4 + (c ^ ((row >> 1) & 3))) * 16;
                ldsm_x4(ah[mt], base + off);
                ldsm_x4(al[mt], base + 8192 + off);
            }
            #pragma unroll
            for (int ntp = 0; ntp < 4; ntp++) {
                int nr = wn * 64 + (ntp * 2 + ((lane >> 4) & 1)) * 8 + (lane & 7);
                int c = 2 * s + ((lane >> 3) & 1);
                uint32_t off = (uint32_t)(nr * 4 + (c ^ ((nr >> 1) & 3))) * 16;
                uint32_t bh[4], bl[4];
                ldsm_x4(bh, base + 16384 + off);
                ldsm_x4(bl, base + 32768 + off);
                #pragma unroll
                for (int half = 0; half < 2; half++) {
                    int nt = ntp * 2 + half;
                    #pragma unroll
                    for (int mt = 0; mt < 2; mt++) {
                        mma16816(acc[mt][nt], ah[mt], bh + 2 * half);
                        mma16816(acc[mt][nt], ah[mt], bl + 2 * half);
                        mma16816(acc[mt][nt], al[mt], bh + 2 * half);
                    }
                }
            }
        }
        __syncthreads();
        if (ch + 2 < 8)
            gemm_ln_issue(sb, (ch + 2) % 3, tid, row0, (ch + 2) * 32, Ahi, Alo, Bhi, Blo);
    }

    const int g4 = lane >> 2, tig = lane & 3;
    float ps[2][2][2];
    #pragma unroll
    for (int mt = 0; mt < 2; mt++)
        #pragma unroll
        for (int h = 0; h < 2; h++) { ps[mt][h][0] = 0.f; ps[mt][h][1] = 0.f; }

    #pragma unroll
    for (int nt = 0; nt < 8; nt++) {
        int col = wn * 64 + nt * 8 + tig * 2;
        float b0 = s_bias[col], b1 = s_bias[col + 1];
        #pragma unroll
        for (int mt = 0; mt < 2; mt++) {
            size_t rA = (size_t)(row0 + wm * 32 + mt * 16 + g4) * 256 + col;
            uint32_t rh0 = *(const uint32_t*)(Xh + rA);
            uint32_t rl0 = *(const uint32_t*)(Xl + rA);
            uint32_t rh1 = *(const uint32_t*)(Xh + rA + 8 * 256);
            uint32_t rl1 = *(const uint32_t*)(Xl + rA + 8 * 256);
            float v0 = acc[mt][nt][0] + b0 + bflo(rh0) + bflo(rl0);
            float v1 = acc[mt][nt][1] + b1 + bfhi(rh0) + bfhi(rl0);
            float v2 = acc[mt][nt][2] + b0 + bflo(rh1) + bflo(rl1);
            float v3 = acc[mt][nt][3] + b1 + bfhi(rh1) + bfhi(rl1);
            acc[mt][nt][0] = v0; acc[mt][nt][1] = v1;
            acc[mt][nt][2] = v2; acc[mt][nt][3] = v3;
            ps[mt][0][0] += v0 + v1; ps[mt][0][1] += v0 * v0 + v1 * v1;
            ps[mt][1][0] += v2 + v3; ps[mt][1][1] += v2 * v2 + v3 * v3;
        }
    }
    #pragma unroll
    for (int mt = 0; mt < 2; mt++)
        #pragma unroll
        for (int h = 0; h < 2; h++) {
            ps[mt][h][0] += __shfl_xor_sync(0xffffffffu, ps[mt][h][0], 1);
            ps[mt][h][0] += __shfl_xor_sync(0xffffffffu, ps[mt][h][0], 2);
            ps[mt][h][1] += __shfl_xor_sync(0xffffffffu, ps[mt][h][1], 1);
            ps[mt][h][1] += __shfl_xor_sync(0xffffffffu, ps[mt][h][1], 2);
        }
    if (tig == 0) {
        #pragma unroll
        for (int mt = 0; mt < 2; mt++)
            #pragma unroll
            for (int h = 0; h < 2; h++) {
                int row = wm * 32 + mt * 16 + g4 + h * 8;
                *(float2*)&s_sum[(row * 4 + wn) * 2] =
                    make_float2(ps[mt][h][0], ps[mt][h][1]);
            }
    }
    __syncthreads();

    float mean[2][2], rstd[2][2];
    #pragma unroll
    for (int mt = 0; mt < 2; mt++)
        #pragma unroll
        for (int h = 0; h < 2; h++) {
            int row = wm * 32 + mt * 16 + g4 + h * 8;
            float s = 0.f, q = 0.f;
            #pragma unroll
            for (int w = 0; w < 4; w++) {
                float2 t = *(float2*)&s_sum[(row * 4 + w) * 2];
                s += t.x; q += t.y;
            }
            float m = s * (1.f / 256.f);
            float var = fmaxf(q * (1.f / 256.f) - m * m, 0.f);
            mean[mt][h] = m;
            rstd[mt][h] = rsqrtf(var + 1e-5f);
        }

    #pragma unroll
    for (int nt = 0; nt < 8; nt++) {
        int col = wn * 64 + nt * 8 + tig * 2;
        float gg0 = s_g[col], gg1 = s_g[col + 1];
        float bb0 = s_b[col], bb1 = s_b[col + 1];
        #pragma unroll
        for (int mt = 0; mt < 2; mt++) {
            size_t rA = (size_t)(row0 + wm * 32 + mt * 16 + g4) * 256 + col;
            float o0 = (acc[mt][nt][0] - mean[mt][0]) * rstd[mt][0] * gg0 + bb0;
            float o1 = (acc[mt][nt][1] - mean[mt][0]) * rstd[mt][0] * gg1 + bb1;
            float o2 = (acc[mt][nt][2] - mean[mt][1]) * rstd[mt][1] * gg0 + bb0;
            float o3 = (acc[mt][nt][3] - mean[mt][1]) * rstd[mt][1] * gg1 + bb1;
            uint32_t h01, l01, h23, l23;
            split2(o0, o1, h01, l01);
            split2(o2, o3, h23, l23);
            *(uint32_t*)(Xh + rA)           = h01;
            *(uint32_t*)(Xl + rA)           = l01;
            *(uint32_t*)(Xh + rA + 8 * 256) = h23;
            *(uint32_t*)(Xl + rA + 8 * 256) = l23;
        }
    }
}

// ---------------------------------------------------------------------------
// Merged weight transpose + split
// ---------------------------------------------------------------------------
__global__ void transpose_all(const float* Wqkv, const float* Wo, const float* W1,
                              const float* W2, const float* msg_W, const float* gat_W,
                              const float* spW1, const float* spW2,
                              __nv_bfloat16* Thi, __nv_bfloat16* Tlo) {
    const int z = blockIdx.z;
    const float* src;
    int dstoff, K, N;
    if (z < 2)       { src = Wqkv + (size_t)z * 256 * 768; dstoff = WT_QKV + z * 768 * 256; K = 256; N = 768; }
    else if (z < 4)  { int l = z - 2;  src = Wo + (size_t)l * 65536;  dstoff = WT_WO + l * 65536;  K = 256; N = 256; }
    else if (z < 6)  { int l = z - 4;  src = W1 + (size_t)l * 65536;  dstoff = WT_W1 + l * 65536;  K = 256; N = 256; }
    else if (z < 8)  { int l = z - 6;  src = W2 + (size_t)l * 65536;  dstoff = WT_W2 + l * 65536;  K = 256; N = 256; }
    else if (z < 11) { int r = z - 8;  src = msg_W + (size_t)r * 65536; dstoff = WT_MSG + r * 65536; K = 256; N = 256; }
    else if (z < 15) { int l = z - 11; src = gat_W + (size_t)l * 256 * 1024; dstoff = WT_GAT + l * 1024 * 256; K = 256; N = 1024; }
    else if (z < 16) { src = spW1; dstoff = WT_SP1; K = 256; N = 512; }
    else             { src = spW2; dstoff = WT_SP2; K = 512; N = 256; }

    int n0 = blockIdx.x * 32, k0 = blockIdx.y * 32;
    if (n0 >= N || k0 >= K) return;

    __shared__ float t[32][33];
    int x = threadIdx.x, y = threadIdx.y;
    #pragma unroll
    for (int i = 0; i < 4; i++)
        t[y + i * 8][x] = src[(size_t)(k0 + y + i * 8) * N + n0 + x];
    __syncthreads();
    #pragma unroll
    for (int i = 0; i < 4; i++) {
        float v = t[x][y + i * 8];
        __nv_bfloat16 h, l;
        split1(v, h, l);
        size_t o = (size_t)dstoff + (size_t)(n0 + y + i * 8) * K + k0 + x;
        Thi[o] = h; Tlo[o] = l;
    }
}

// ---------------------------------------------------------------------------
// Fused CSR build
// ---------------------------------------------------------------------------
__global__ void __launch_bounds__(1024) csr_build(const int* __restrict__ src,
                                                  const int* __restrict__ dst,
                                                  const int* __restrict__ etype) {
    __shared__ int cnt[NSEG];
    __shared__ int ws[1024];
    const int tid = threadIdx.x;
    #pragma unroll
    for (int k = 0; k < 6; k++) cnt[tid + k * 1024] = 0;
    __syncthreads();
    for (int e = tid; e < NEDGE; e += 1024)
        atomicAdd(&cnt[etype[e] * NN + dst[e]], 1);
    __syncthreads();
    const int base = tid * 6;
    int local[6];
    int sum = 0;
    #pragma unroll
    for (int k = 0; k < 6; k++) { local[k] = sum; sum += cnt[base + k]; }
    ws[tid] = sum;
    __syncthreads();
    for (int d = 1; d < 1024; d <<= 1) {
        int v = (tid >= d) ? ws[tid - d] : 0;
        __syncthreads();
        ws[tid] += v;
        __syncthreads();
    }
    int pre = ws[tid] - sum;
    #pragma unroll
    for (int k = 0; k < 6; k++) {
        g_off[base + k] = pre + local[k];
        cnt[base + k] = pre + local[k];
    }
    if (tid == 1023) g_off[NSEG] = ws[1023];
    __syncthreads();
    for (int e = tid; e < NEDGE; e += 1024) {
        int p = atomicAdd(&cnt[etype[e] * NN + dst[e]], 1);
        g_srt[p] = src[e];
    }
}

// ---------------------------------------------------------------------------
// PE table + embedding (vectorized: 4 dims/thread)
// ---------------------------------------------------------------------------
__global__ void pe_kernel() {
    int s = blockIdx.x, d = threadIdx.x;
    int i2 = d >> 1;
    float div = expf((float)(2 * i2) * (-logf(10000.f) / (float)DIM));
    float arg = (float)s * div;
    g_PE[s * DIM + d] = (d & 1) ? cosf(arg) : sinf(arg);
}

__global__ void embed_kernel(const float* __restrict__ tok_emb,
                             const int* __restrict__ tokens) {
    int idx = (blockIdx.x * 256 + threadIdx.x) * 4;   // grid = NTOK*DIM/1024
    int row = idx >> 8;
    int d = idx & 255;
    int s = row & (SEQ - 1);
    int tok = tokens[row];
    float4 te = *(const float4*)(tok_emb + (size_t)tok * DIM + d);
    float4 pe = *(const float4*)(g_PE + s * DIM + d);
    float v0 = te.x * 16.f + pe.x;
    float v1 = te.y * 16.f + pe.y;
    float v2 = te.z * 16.f + pe.z;
    float v3 = te.w * 16.f + pe.w;
    uint32_t h01, l01, h23, l23;
    split2(v0, v1, h01, l01);
    split2(v2, v3, h23, l23);
    size_t o = (size_t)row * DIM + d;
    *(uint2*)(g_Xh + o) = make_uint2(h01, h23);
    *(uint2*)(g_Xl + o) = make_uint2(l01, l23);
}

// ---------------------------------------------------------------------------
// Attention (QKV stored bf16)
// ---------------------------------------------------------------------------
__global__ void attn_kernel() {
    int n = blockIdx.x >> 3;
    int h = blockIdx.x & 7;
    __shared__ float Qs[SEQ][DH + 1];
    __shared__ float Ks[SEQ][DH + 1];
    __shared__ float Vs[SEQ][DH + 1];
    const __nv_bfloat16* base = g_QKVh + (size_t)n * SEQ * 3 * DIM;
    for (int e = threadIdx.x; e < SEQ * DH; e += blockDim.x) {
        int r = e >> 5, d = e & 31;
        Qs[r][d] = __bfloat162float(base[r * 3 * DIM + h * DH + d]);
        Ks[r][d] = __bfloat162float(base[r * 3 * DIM + DIM + h * DH + d]);
        Vs[r][d] = __bfloat162float(base[r * 3 * DIM + 2 * DIM + h * DH + d]);
    }
    __syncthreads();
    int i = threadIdx.x;
    float q[DH];
    #pragma unroll
    for (int d = 0; d < DH; d++) q[d] = Qs[i][d];
    const float scale = 0.17677669529663687f;
    float m = -1e30f, l = 0.f;
    float o[DH];
    #pragma unroll
    for (int d = 0; d < DH; d++) o[d] = 0.f;
    for (int j = 0; j < SEQ; j++) {
        float s0 = 0.f, s1 = 0.f, s2 = 0.f, s3 = 0.f;
        #pragma unroll
        for (int d = 0; d < DH; d += 4) {
            s0 += q[d]     * Ks[j][d];
            s1 += q[d + 1] * Ks[j][d + 1];
            s2 += q[d + 2] * Ks[j][d + 2];
            s3 += q[d + 3] * Ks[j][d + 3];
        }
        float s = ((s0 + s1) + (s2 + s3)) * scale;
        if (s > m) {
            float c = expf(m - s);
            l *= c;
            #pragma unroll
            for (int d = 0; d < DH; d++) o[d] *= c;
            m = s;
        }
        float p = expf(s - m);
        l += p;
        #pragma unroll
        for (int d = 0; d < DH; d++) o[d] += p * Vs[j][d];
    }
    float inv = 1.f / l;
    size_t ob = ((size_t)n * SEQ + i) * DIM + h * DH;
    #pragma unroll
    for (int d = 0; d < DH; d += 2) {
        uint32_t hi, lo;
        split2(o[d] * inv, o[d + 1] * inv, hi, lo);
        *(uint32_t*)(g_T1h + ob + d) = hi;
        *(uint32_t*)(g_T1l + ob + d) = lo;
    }
}

// ---------------------------------------------------------------------------
// mean over seq + type emb
// ---------------------------------------------------------------------------
__global__ void mean_kernel(const int* __restrict__ types,
                            const float* __restrict__ type_emb) {
    int n = blockIdx.x, d = threadIdx.x;
    float acc = 0.f;
    const __nv_bfloat16* bh = g_Xh + (size_t)n * SEQ * DIM + d;
    const __nv_bfloat16* bl = g_Xl + (size_t)n * SEQ * DIM + d;
    for (int s = 0; s < SEQ; s++)
        acc += __bfloat162float(bh[s * DIM]) + __bfloat162float(bl[s * DIM]);
    float v = acc * (1.f / SEQ) + type_emb[(size_t)types[n] * DIM + d];
    size_t o = (size_t)n * DIM + d;
    g_H[o] = v;
    __nv_bfloat16 h, l;
    split1(v, h, l);
    g_Hh[o] = h; g_Hl[o] = l;
}

// ---------------------------------------------------------------------------
// GNN kernels
// ---------------------------------------------------------------------------
__global__ void asd_kernel(const float* __restrict__ asrc,
                           const float* __restrict__ adst) {
    int i = blockIdx.x;
    int w = threadIdx.x >> 5, lane = threadIdx.x & 31;
    float s1 = 0.f, s2 = 0.f;
    const float* xg = g_XG + (size_t)i * GHEADS * DIM + w * DIM;
    #pragma unroll
    for (int d = lane; d < DIM; d += 32) {
        float xv = xg[d];
        s1 += xv * asrc[w * DIM + d];
        s2 += xv * adst[w * DIM + d];
    }
    #pragma unroll
    for (int off = 16; off > 0; off >>= 1) {
        s1 += __shfl_down_sync(0xffffffffu, s1, off);
        s2 += __shfl_down_sync(0xffffffffu, s2, off);
    }
    if (lane == 0) {
        g_AS[i * GHEADS + w] = s1;
        g_AD[i * GHEADS + w] = s2;
    }
}

__global__ void __launch_bounds__(128) csr_agg() {
    __shared__ float s_acc[4][DIM];
    const int i = blockIdx.x;
    const int w = threadIdx.x >> 5;
    const int lane = threadIdx.x & 31;
    const int rbase = (i >> 11) << 11;
    const int beg = g_off[i], end = g_off[i + 1];

    const float ad = g_AD[i * GHEADS + w];
    const float self_e = lrelu(g_AS[i * GHEADS + w] + ad);

    float m = self_e;
    for (int j = beg + lane; j < end; j += 32)
        m = fmaxf(m, lrelu(g_AS[(rbase + g_srt[j]) * GHEADS + w] + ad));
    #pragma unroll
    for (int off = 16; off > 0; off >>= 1)
        m = fmaxf(m, __shfl_xor_sync(0xffffffffu, m, off));

    float den = expf(self_e - m);
    float acc[8];
    const float* xs = g_XG + (size_t)i * (GHEADS * DIM) + w * DIM;
    #pragma unroll
    for (int k = 0; k < 8; k++) acc[k] = den * xs[lane + 32 * k];
    for (int j = beg; j < end; j++) {
        int s = rbase + g_srt[j];
        float wgt = expf(lrelu(g_AS[s * GHEADS + w] + ad) - m);
        den += wgt;
        const float* xv = g_XG + (size_t)s * (GHEADS * DIM) + w * DIM;
        #pragma unroll
        for (int k = 0; k < 8; k++) acc[k] += wgt * xv[lane + 32 * k];
    }
    float inv = 0.25f / den;
    #pragma unroll
    for (int k = 0; k < 8; k++) s_acc[w][lane + 32 * k] = acc[k] * inv;
    __syncthreads();
    float* nm = g_NUMR + (size_t)i * DIM;
    #pragma unroll
    for (int k = 0; k < 2; k++) {
        int d = threadIdx.x + 128 * k;
        nm[d] = s_acc[0][d] + s_acc[1][d] + s_acc[2][d] + s_acc[3][d];
    }
}

__global__ void combupd_kernel(const float* __restrict__ gb) {
    int n = blockIdx.x, d = threadIdx.x;
    float acc = g_NUMR[(size_t)n * DIM + d]
              + g_NUMR[(size_t)(NN + n) * DIM + d]
              + g_NUMR[(size_t)(2 * NN + n) * DIM + d];
    size_t o = (size_t)n * DIM + d;
    float v = fmaxf(g_H[o] + acc + 3.f * gb[d], 0.f);
    g_H[o] = v;
    __nv_bfloat16 h, l;
    split1(v, h, l);
    g_Hh[o] = h; g_Hl[o] = l;
}

__global__ void final_kernel(const float* __restrict__ log_c, float* __restrict__ out) {
    int n = blockIdx.x, d = threadIdx.x;
    __shared__ float sh[256];
    __shared__ float stat;
    float scale = sqrtf(expf(log_c[0]));
    float st = tanhf(g_TH[(size_t)n * DIM + d]) * 2.f * scale;
    sh[d] = st * st; __syncthreads();
    for (int s = 128; s > 0; s >>= 1) { if (d < s) sh[d] += sh[d + s]; __syncthreads(); }
    if (d == 0) stat = sh[0];
    __syncthreads();
    float r = fmaxf(sqrtf(stat), 1e-8f);
    if (d == 0) out[(size_t)n * 257] = coshf(r);
    out[(size_t)n * 257 + 1 + d] = sinhf(r) / r * st;
}

// ---------------------------------------------------------------------------
// Host orchestration
// ---------------------------------------------------------------------------
extern "C" void kernel_launch(void* const* d_in, const int* in_sizes, int n_in,
                              void* d_out, int out_size) {
    const float* tok_emb = (const float*)d_in[0];
    const float* Wqkv    = (const float*)d_in[1];
    const float* bqkv    = (const float*)d_in[2];
    const float* Wo      = (const float*)d_in[3];
    const float* bo      = (const float*)d_in[4];
    const float* ln1g    = (const float*)d_in[5];
    const float* ln1b    = (const float*)d_in[6];
    const float* ln2g    = (const float*)d_in[7];
    const float* ln2b    = (const float*)d_in[8];
    const float* W1      = (const float*)d_in[9];
    const float* b1      = (const float*)d_in[10];
    const float* W2      = (const float*)d_in[11];
    const float* b2      = (const float*)d_in[12];
    const float* type_emb= (const float*)d_in[13];
    const float* msg_W   = (const float*)d_in[14];
    const float* msg_b   = (const float*)d_in[15];
    const float* gat_W   = (const float*)d_in[16];
    const float* gat_b   = (const float*)d_in[17];
    const float* asrc    = (const float*)d_in[18];
    const float* adst    = (const float*)d_in[19];
    const float* spW1    = (const float*)d_in[20];
    const float* spb1    = (const float*)d_in[21];
    const float* spW2    = (const float*)d_in[22];
    const float* spb2    = (const float*)d_in[23];
    const float* log_c   = (const float*)d_in[24];
    const int*   tokens  = (const int*)d_in[25];
    const int*   types   = (const int*)d_in[26];
    const int*   eidx    = (const int*)d_in[27];
    const int*   etype   = (const int*)d_in[28];
    const int* esrc = eidx;
    const int* edst = eidx + NEDGE;
    float* out = (float*)d_out;

    float *pH, *pTH, *pXG;
    __nv_bfloat16 *pQKVh, *pXh, *pXl, *pT1h, *pT1l, *pHh, *pHl, *pTHAh, *pTHAl,
                  *pSPHh, *pSPHl, *pWTh, *pWTl;
    cudaGetSymbolAddress((void**)&pH,    g_H);
    cudaGetSymbolAddress((void**)&pTH,   g_TH);
    cudaGetSymbolAddress((void**)&pXG,   g_XG);
    cudaGetSymbolAddress((void**)&pQKVh, g_QKVh);
    cudaGetSymbolAddress((void**)&pXh,   g_Xh);
    cudaGetSymbolAddress((void**)&pXl,   g_Xl);
    cudaGetSymbolAddress((void**)&pT1h,  g_T1h);
    cudaGetSymbolAddress((void**)&pT1l,  g_T1l);
    cudaGetSymbolAddress((void**)&pHh,   g_Hh);
    cudaGetSymbolAddress((void**)&pHl,   g_Hl);
    cudaGetSymbolAddress((void**)&pTHAh, g_THAh);
    cudaGetSymbolAddress((void**)&pTHAl, g_THAl);
    cudaGetSymbolAddress((void**)&pSPHh, g_SPHh);
    cudaGetSymbolAddress((void**)&pSPHl, g_SPHl);
    cudaGetSymbolAddress((void**)&pWTh,  g_WTh);
    cudaGetSymbolAddress((void**)&pWTl,  g_WTl);

    cudaFuncSetAttribute(gemm_bf16, cudaFuncAttributeMaxDynamicSharedMemorySize,
                         NSTAGE * STAGE_BYTES);
    cudaFuncSetAttribute(gemm_ln, cudaFuncAttributeMaxDynamicSharedMemorySize,
                         3 * LSTG + 4096 + 3 * 1024);
    const int SMEM   = NSTAGE * STAGE_BYTES;
    const int SMEMLN = 3 * LSTG + 4096 + 3 * 1024;

    // 0) merged weight transpose+split, PE, fused CSR build
    transpose_all<<<dim3(32, 16, 17), dim3(32, 8)>>>(
        Wqkv, Wo, W1, W2, msg_W, gat_W, spW1, spW2, pWTh, pWTl);
    pe_kernel<<<SEQ, 256>>>();
    csr_build<<<1, 1024>>>(esrc, edst, etype);

    // 1) embedding + PE (vectorized)
    embed_kernel<<<NTOK * DIM / 1024, 256>>>(tok_emb, tokens);

    // 2) transformer encoder
    for (int l = 0; l < 2; l++) {
        // QKV -> bf16 storage (hi-only)
        gemm_bf16<<<dim3(6, NTOK / 128), 256, SMEM>>>(
            pXh, pXl, 256, pWTh + WT_QKV + l * 768 * 256, pWTl + WT_QKV + l * 768 * 256,
            bqkv + l * 768, nullptr, pQKVh, nullptr, NTOK, 768, 256, 0, 0);
        attn_kernel<<<NN * NH, 64>>>();
        gemm_ln<<<NTOK / 128, 512, SMEMLN>>>(
            pT1h, pT1l, pWTh + WT_WO + l * 65536, pWTl + WT_WO + l * 65536,
            bo + l * 256, ln1g + l * 256, ln1b + l * 256, pXh, pXl);
        gemm_bf16<<<dim3(2, NTOK / 128), 256, SMEM>>>(
            pXh, pXl, 256, pWTh + WT_W1 + l * 65536, pWTl + WT_W1 + l * 65536,
            b1 + l * 256, nullptr, pT1h, pT1l, NTOK, 256, 256, 1, 0);
        gemm_ln<<<NTOK / 128, 512, SMEMLN>>>(
            pT1h, pT1l, pWTh + WT_W2 + l * 65536, pWTl + WT_W2 + l * 65536,
            b2 + l * 256, ln2g + l * 256, ln2b + l * 256, pXh, pXl);
    }

    // 3) mean over seq + type embedding
    mean_kernel<<<NN, 256>>>(types, type_emb);

    // 4) 4 GNN layers
    for (int l = 0; l < 4; l++) {
        gemm_bf16<<<dim3(6, NN / 128), 256, SMEM>>>(
            pHh, pHl, 256, pWTh + WT_MSG, pWTl + WT_MSG,
            msg_b, nullptr, pTHAh, pTHAl, NN, 768, 256, 0, NN * DIM);
        gemm_bf16<<<dim3(8, NSEG / 128), 256, SMEM>>>(
            pTHAh, pTHAl, 256,
            pWTh + WT_GAT + l * 1024 * 256, pWTl + WT_GAT + l * 1024 * 256,
            nullptr, pXG, nullptr, nullptr, NSEG, 1024, 256, 0, 0);
        asd_kernel<<<NSEG, 128>>>(asrc + l * GHEADS * DIM, adst + l * GHEADS * DIM);
        csr_agg<<<NSEG, 128>>>();
        combupd_kernel<<<NN, 256>>>(gat_b + l * 256);
    }

    // 5) scoring MLP + Lorentz exp map
    gemm_bf16<<<dim3(4, NN / 128), 256, SMEM>>>(
        pHh, pHl, 256, pWTh + WT_SP1, pWTl + WT_SP1,
        spb1, nullptr, pSPHh, pSPHl, NN, 512, 256, 1, 0);
    gemm_bf16<<<dim3(2, NN / 128), 256, SMEM>>>(
        pSPHh, pSPHl, 512, pWTh + WT_SP2, pWTl + WT_SP2,
        spb2, pTH, nullptr, nullptr, NN, 256, 512, 0, 0);
    final_kernel<<<NN, 256>>>(log_c, out);
}

// round 15
// speedup vs baseline: 1.2151x; 1.0944x over previous
#include <cuda_runtime.h>
#include <cuda_bf16.h>
#include <math.h>
#include <stdint.h>

// ---------------------------------------------------------------------------
// Problem constants
// ---------------------------------------------------------------------------
#define NN      2048
#define SEQ     64
#define DIM     256
#define NH      8
#define DH      32
#define GHEADS  4
#define NEDGE   32768
#define NTOK    (NN*SEQ)
#define SPH     512
#define NREL    3
#define NSEG    (NREL*NN)     // 6144

// ---------------------------------------------------------------------------
// Scratch (device globals)
// ---------------------------------------------------------------------------
__device__ float g_H  [NN*DIM];
__device__ float g_TH [NN*DIM];
__device__ float g_PE [SEQ*DIM];
__device__ float g_XG [NSEG*GHEADS*DIM];
__device__ float g_AS [NSEG*GHEADS];
__device__ float g_AD [NSEG*GHEADS];
__device__ float g_NUMR[NSEG*DIM];

// CSR of edges sorted by (rel, dst)
__device__ int g_off[NSEG + 1];
__device__ int g_srt[NEDGE];

// bf16 activations (T1 hi-only: both consumers feed residual+LN)
__device__ __nv_bfloat16 g_QKVh[NTOK*3*DIM];
__device__ __nv_bfloat16 g_Xh [NTOK*DIM],  g_Xl [NTOK*DIM];
__device__ __nv_bfloat16 g_T1h[NTOK*DIM];
__device__ __nv_bfloat16 g_Hh [NN*DIM],    g_Hl [NN*DIM];
__device__ __nv_bfloat16 g_THAh[NREL*NN*DIM], g_THAl[NREL*NN*DIM];
__device__ __nv_bfloat16 g_SPHh[NN*SPH],   g_SPHl[NN*SPH];

// transposed + split weights, K-major [N, K]
#define WT_QKV   0
#define WT_WO    (WT_QKV + 2*768*256)
#define WT_W1    (WT_WO  + 2*256*256)
#define WT_W2    (WT_W1  + 2*256*256)
#define WT_MSG   (WT_W2  + 2*256*256)
#define WT_GAT   (WT_MSG + 3*256*256)
#define WT_SP1   (WT_GAT + 4*1024*256)
#define WT_SP2   (WT_SP1 + 512*256)
#define WT_TOTAL (WT_SP2 + 256*512)
__device__ __nv_bfloat16 g_WTh[WT_TOTAL], g_WTl[WT_TOTAL];

// ---------------------------------------------------------------------------
// Helpers
// ---------------------------------------------------------------------------
__device__ __forceinline__ float lrelu(float x) { return x > 0.f ? x : 0.2f * x; }

__device__ __forceinline__ uint32_t smem_u32(const void* p) {
    uint32_t a;
    asm("{ .reg .u64 t; cvta.to.shared.u64 t, %1; cvt.u32.u64 %0, t; }" : "=r"(a) : "l"(p));
    return a;
}

__device__ __forceinline__ void split1(float v, __nv_bfloat16& h, __nv_bfloat16& l) {
    h = __float2bfloat16_rn(v);
    l = __float2bfloat16_rn(v - __bfloat162float(h));
}

__device__ __forceinline__ void split2(float a, float b, uint32_t& hi, uint32_t& lo) {
    __nv_bfloat16 ha, la, hb, lb;
    split1(a, ha, la);
    split1(b, hb, lb);
    hi = (uint32_t)__bfloat16_as_ushort(ha) | ((uint32_t)__bfloat16_as_ushort(hb) << 16);
    lo = (uint32_t)__bfloat16_as_ushort(la) | ((uint32_t)__bfloat16_as_ushort(lb) << 16);
}

__device__ __forceinline__ uint32_t pack2(float a, float b) {
    __nv_bfloat16 ha = __float2bfloat16_rn(a), hb = __float2bfloat16_rn(b);
    return (uint32_t)__bfloat16_as_ushort(ha) | ((uint32_t)__bfloat16_as_ushort(hb) << 16);
}

__device__ __forceinline__ float bflo(uint32_t x) {
    return __bfloat162float(__ushort_as_bfloat16((unsigned short)(x & 0xffffu)));
}
__device__ __forceinline__ float bfhi(uint32_t x) {
    return __bfloat162float(__ushort_as_bfloat16((unsigned short)(x >> 16)));
}

__device__ __forceinline__ void ldsm_x4(uint32_t* r, uint32_t a) {
    asm volatile("ldmatrix.sync.aligned.m8n8.x4.shared.b16 {%0,%1,%2,%3}, [%4];"
                 : "=r"(r[0]), "=r"(r[1]), "=r"(r[2]), "=r"(r[3]) : "r"(a));
}

__device__ __forceinline__ void mma16816(float* c, const uint32_t* a, const uint32_t* b) {
    asm volatile(
        "mma.sync.aligned.m16n8k16.row.col.f32.bf16.bf16.f32 "
        "{%0,%1,%2,%3}, {%4,%5,%6,%7}, {%8,%9}, {%0,%1,%2,%3};"
        : "+f"(c[0]), "+f"(c[1]), "+f"(c[2]), "+f"(c[3])
        : "r"(a[0]), "r"(a[1]), "r"(a[2]), "r"(a[3]), "r"(b[0]), "r"(b[1]));
}

__device__ __forceinline__ void cp_async16(uint32_t dst, const void* src) {
    asm volatile("cp.async.cg.shared.global [%0], [%1], 16;" :: "r"(dst), "l"(src) : "memory");
}
__device__ __forceinline__ void cp_commit() {
    asm volatile("cp.async.commit_group;" ::: "memory");
}
template<int W> __device__ __forceinline__ void cp_wait() {
    asm volatile("cp.async.wait_group %0;" :: "n"(W) : "memory");
}

// ---------------------------------------------------------------------------
// Pipelined bf16-split GEMM (256 threads, 128x128 tile, 3-stage)
// ALO: A has lo part (3-term). Otherwise 2-term (A_hi*B_hi + A_hi*B_lo).
// ---------------------------------------------------------------------------
#define ARR_BYTES  8192
#define STAGE_BYTES (4*ARR_BYTES)
#define NSTAGE 3

template<bool ALO>
__device__ __forceinline__ void gemm_issue(
    uint32_t sb, int stage, int tid,
    const __nv_bfloat16* Ahi, const __nv_bfloat16* Alo, int lda,
    const __nv_bfloat16* Bhi, const __nv_bfloat16* Blo, int K,
    int row0, int col0, int k0)
{
    #pragma unroll
    for (int i = 0; i < 8; i++) {
        int idx = tid + i * 256;
        int arr = idx >> 9;
        if (!ALO && arr == 1) continue;
        int j   = idx & 511;
        int r   = j >> 2;
        int c   = j & 3;
        uint32_t dst = sb + stage * STAGE_BYTES + arr * ARR_BYTES
                     + (uint32_t)(r * 4 + (c ^ ((r >> 1) & 3))) * 16;
        const __nv_bfloat16* src;
        if (arr == 0)      src = Ahi + (size_t)(row0 + r) * lda + k0 + c * 8;
        else if (arr == 1) src = Alo + (size_t)(row0 + r) * lda + k0 + c * 8;
        else if (arr == 2) src = Bhi + (size_t)(col0 + r) * K + k0 + c * 8;
        else               src = Blo + (size_t)(col0 + r) * K + k0 + c * 8;
        cp_async16(dst, src);
    }
    cp_commit();
}

template<bool ALO>
__global__ void __launch_bounds__(256)
gemm_bf16(const __nv_bfloat16* __restrict__ Ahi, const __nv_bfloat16* __restrict__ Alo, int lda,
          const __nv_bfloat16* __restrict__ Bhi, const __nv_bfloat16* __restrict__ Blo,
          const float* __restrict__ bias,
          float* __restrict__ Cf,
          __nv_bfloat16* __restrict__ Chi, __nv_bfloat16* __restrict__ Clo,
          int M, int N, int K, int act, int rmaj) {
    extern __shared__ char sm[];
    const uint32_t sb = smem_u32(sm);
    const int tid  = threadIdx.x;
    const int lane = tid & 31;
    const int warp = tid >> 5;
    const int wm = warp & 3;
    const int wn = warp >> 2;
    const int row0 = blockIdx.y * 128;
    const int col0 = blockIdx.x * 128;

    float acc[2][8][4];
    #pragma unroll
    for (int i = 0; i < 2; i++)
        #pragma unroll
        for (int j = 0; j < 8; j++)
            #pragma unroll
            for (int k = 0; k < 4; k++) acc[i][j][k] = 0.f;

    const int nch = K >> 5;
    gemm_issue<ALO>(sb, 0, tid, Ahi, Alo, lda, Bhi, Blo, K, row0, col0, 0);
    if (nch > 1)
        gemm_issue<ALO>(sb, 1, tid, Ahi, Alo, lda, Bhi, Blo, K, row0, col0, 32);

    for (int ch = 0; ch < nch; ch++) {
        if (ch + 1 < nch) cp_wait<1>(); else cp_wait<0>();
        __syncthreads();

        const uint32_t base = sb + (ch % NSTAGE) * STAGE_BYTES;
        #pragma unroll
        for (int s = 0; s < 2; s++) {
            uint32_t ah[2][4], al[2][4];
            #pragma unroll
            for (int mt = 0; mt < 2; mt++) {
                int row = wm * 32 + mt * 16 + (lane & 15);
                int c = 2 * s + (lane >> 4);
                uint32_t off = (uint32_t)(row * 4 + (c ^ ((row >> 1) & 3))) * 16;
                ldsm_x4(ah[mt], base + off);
                if (ALO) ldsm_x4(al[mt], base + ARR_BYTES + off);
            }
            #pragma unroll
            for (int ntp = 0; ntp < 4; ntp++) {
                int nr = wn * 64 + (ntp * 2 + ((lane >> 4) & 1)) * 8 + (lane & 7);
                int c = 2 * s + ((lane >> 3) & 1);
                uint32_t off = (uint32_t)(nr * 4 + (c ^ ((nr >> 1) & 3))) * 16;
                uint32_t bh[4], bl[4];
                ldsm_x4(bh, base + 2 * ARR_BYTES + off);
                ldsm_x4(bl, base + 3 * ARR_BYTES + off);
                #pragma unroll
                for (int half = 0; half < 2; half++) {
                    int nt = ntp * 2 + half;
                    #pragma unroll
                    for (int mt = 0; mt < 2; mt++) {
                        mma16816(acc[mt][nt], ah[mt], bh + 2 * half);
                        mma16816(acc[mt][nt], ah[mt], bl + 2 * half);
                        if (ALO) mma16816(acc[mt][nt], al[mt], bh + 2 * half);
                    }
                }
            }
        }
        __syncthreads();
        if (ch + 2 < nch)
            gemm_issue<ALO>(sb, (ch + 2) % NSTAGE, tid, Ahi, Alo, lda, Bhi, Blo, K,
                            row0, col0, (ch + 2) << 5);
    }

    const int g4 = lane >> 2, tig = lane & 3;
    #pragma unroll
    for (int nt = 0; nt < 8; nt++) {
        int col = col0 + wn * 64 + nt * 8 + tig * 2;
        float b0 = 0.f, b1 = 0.f;
        if (bias) { b0 = bias[col]; b1 = bias[col + 1]; }
        #pragma unroll
        for (int mt = 0; mt < 2; mt++) {
            int row = row0 + wm * 32 + mt * 16 + g4;
            float v0 = acc[mt][nt][0] + b0;
            float v1 = acc[mt][nt][1] + b1;
            float v2 = acc[mt][nt][2] + b0;
            float v3 = acc[mt][nt][3] + b1;
            if (act) {
                v0 = fmaxf(v0, 0.f); v1 = fmaxf(v1, 0.f);
                v2 = fmaxf(v2, 0.f); v3 = fmaxf(v3, 0.f);
            }
            size_t o0, o1;
            if (rmaj) {
                o0 = (size_t)(col >> 8) * rmaj + (size_t)row * 256 + (col & 255);
                o1 = o0 + 8 * 256;
            } else {
                o0 = (size_t)row * N + col;
                o1 = o0 + (size_t)8 * N;
            }
            if (Cf) {
                *(float2*)(Cf + o0) = make_float2(v0, v1);
                *(float2*)(Cf + o1) = make_float2(v2, v3);
            }
            if (Chi) {
                if (Clo) {
                    uint32_t h01, l01, h23, l23;
                    split2(v0, v1, h01, l01);
                    split2(v2, v3, h23, l23);
                    *(uint32_t*)(Chi + o0) = h01;
                    *(uint32_t*)(Clo + o0) = l01;
                    *(uint32_t*)(Chi + o1) = h23;
                    *(uint32_t*)(Clo + o1) = l23;
                } else {
                    *(uint32_t*)(Chi + o0) = pack2(v0, v1);
                    *(uint32_t*)(Chi + o1) = pack2(v2, v3);
                }
            }
        }
    }
}

// ---------------------------------------------------------------------------
// Fused GEMM + residual + LayerNorm. A = T1 is hi-only (2-term).
// ---------------------------------------------------------------------------
#define LSTG 49152

template<bool ALO>
__device__ __forceinline__ void gemm_ln_issue(
    uint32_t sb, int stage, int tid, int row0, int k0,
    const __nv_bfloat16* Ahi, const __nv_bfloat16* Alo,
    const __nv_bfloat16* Bhi, const __nv_bfloat16* Blo)
{
    #pragma unroll
    for (int i = 0; i < 6; i++) {
        int idx = tid + i * 512;
        uint32_t stg = sb + stage * LSTG;
        const __nv_bfloat16* src;
        uint32_t dst;
        if (idx < 1024) {
            if (!ALO && (idx >> 9)) continue;
            int j = idx & 511;
            int r = j >> 2, c = j & 3;
            dst = stg + ((idx >> 9) ? 8192u : 0u)
                + (uint32_t)(r * 4 + (c ^ ((r >> 1) & 3))) * 16;
            src = ((idx >> 9) ? Alo : Ahi) + (size_t)(row0 + r) * 256 + k0 + c * 8;
        } else {
            int j = (idx - 1024) & 1023;
            int r = j >> 2, c = j & 3;
            dst = stg + ((idx >= 2048) ? 32768u : 16384u)
                + (uint32_t)(r * 4 + (c ^ ((r >> 1) & 3))) * 16;
            src = ((idx >= 2048) ? Blo : Bhi) + (size_t)r * 256 + k0 + c * 8;
        }
        cp_async16(dst, src);
    }
    cp_commit();
}

template<bool ALO>
__global__ void __launch_bounds__(512)
gemm_ln(const __nv_bfloat16* __restrict__ Ahi, const __nv_bfloat16* __restrict__ Alo,
        const __nv_bfloat16* __restrict__ Bhi, const __nv_bfloat16* __restrict__ Blo,
        const float* __restrict__ bias,
        const float* __restrict__ lng, const float* __restrict__ lnb,
        __nv_bfloat16* Xh, __nv_bfloat16* Xl) {
    extern __shared__ char sm[];
    const uint32_t sb = smem_u32(sm);
    float* s_sum  = (float*)(sm + 3 * LSTG);
    float* s_g    = (float*)(sm + 3 * LSTG + 4096);
    float* s_b    = s_g + 256;
    float* s_bias = s_b + 256;
    const int tid  = threadIdx.x;
    const int lane = tid & 31;
    const int warp = tid >> 5;
    const int wm = warp & 3;
    const int wn = warp >> 2;
    const int row0 = blockIdx.x * 128;

    if (tid < 256) { s_g[tid] = lng[tid]; s_b[tid] = lnb[tid]; s_bias[tid] = bias[tid]; }

    float acc[2][8][4];
    #pragma unroll
    for (int i = 0; i < 2; i++)
        #pragma unroll
        for (int j = 0; j < 8; j++)
            #pragma unroll
            for (int k = 0; k < 4; k++) acc[i][j][k] = 0.f;

    gemm_ln_issue<ALO>(sb, 0, tid, row0, 0, Ahi, Alo, Bhi, Blo);
    gemm_ln_issue<ALO>(sb, 1, tid, row0, 32, Ahi, Alo, Bhi, Blo);

    for (int ch = 0; ch < 8; ch++) {
        if (ch < 7) cp_wait<1>(); else cp_wait<0>();
        __syncthreads();
        const uint32_t base = sb + (ch % 3) * LSTG;
        #pragma unroll
        for (int s = 0; s < 2; s++) {
            uint32_t ah[2][4], al[2][4];
            #pragma unroll
            for (int mt = 0; mt < 2; mt++) {
                int row = wm * 32 + mt * 16 + (lane & 15);
                int c = 2 * s + (lane >> 4);
                uint32_t off = (uint32_t)(row * 4 + (c ^ ((row >> 1) & 3))) * 16;
                ldsm_x4(ah[mt], base + off);
                if (ALO) ldsm_x4(al[mt], base + 8192 + off);
            }
            #pragma unroll
            for (int ntp = 0; ntp < 4; ntp++) {
                int nr = wn * 64 + (ntp * 2 + ((lane >> 4) & 1)) * 8 + (lane & 7);
                int c = 2 * s + ((lane >> 3) & 1);
                uint32_t off = (uint32_t)(nr * 4 + (c ^ ((nr >> 1) & 3))) * 16;
                uint32_t bh[4], bl[4];
                ldsm_x4(bh, base + 16384 + off);
                ldsm_x4(bl, base + 32768 + off);
                #pragma unroll
                for (int half = 0; half < 2; half++) {
                    int nt = ntp * 2 + half;
                    #pragma unroll
                    for (int mt = 0; mt < 2; mt++) {
                        mma16816(acc[mt][nt], ah[mt], bh + 2 * half);
                        mma16816(acc[mt][nt], ah[mt], bl + 2 * half);
                        if (ALO) mma16816(acc[mt][nt], al[mt], bh + 2 * half);
                    }
                }
            }
        }
        __syncthreads();
        if (ch + 2 < 8)
            gemm_ln_issue<ALO>(sb, (ch + 2) % 3, tid, row0, (ch + 2) * 32, Ahi, Alo, Bhi, Blo);
    }

    const int g4 = lane >> 2, tig = lane & 3;
    float ps[2][2][2];
    #pragma unroll
    for (int mt = 0; mt < 2; mt++)
        #pragma unroll
        for (int h = 0; h < 2; h++) { ps[mt][h][0] = 0.f; ps[mt][h][1] = 0.f; }

    #pragma unroll
    for (int nt = 0; nt < 8; nt++) {
        int col = wn * 64 + nt * 8 + tig * 2;
        float b0 = s_bias[col], b1 = s_bias[col + 1];
        #pragma unroll
        for (int mt = 0; mt < 2; mt++) {
            size_t rA = (size_t)(row0 + wm * 32 + mt * 16 + g4) * 256 + col;
            uint32_t rh0 = *(const uint32_t*)(Xh + rA);
            uint32_t rl0 = *(const uint32_t*)(Xl + rA);
            uint32_t rh1 = *(const uint32_t*)(Xh + rA + 8 * 256);
            uint32_t rl1 = *(const uint32_t*)(Xl + rA + 8 * 256);
            float v0 = acc[mt][nt][0] + b0 + bflo(rh0) + bflo(rl0);
            float v1 = acc[mt][nt][1] + b1 + bfhi(rh0) + bfhi(rl0);
            float v2 = acc[mt][nt][2] + b0 + bflo(rh1) + bflo(rl1);
            float v3 = acc[mt][nt][3] + b1 + bfhi(rh1) + bfhi(rl1);
            acc[mt][nt][0] = v0; acc[mt][nt][1] = v1;
            acc[mt][nt][2] = v2; acc[mt][nt][3] = v3;
            ps[mt][0][0] += v0 + v1; ps[mt][0][1] += v0 * v0 + v1 * v1;
            ps[mt][1][0] += v2 + v3; ps[mt][1][1] += v2 * v2 + v3 * v3;
        }
    }
    #pragma unroll
    for (int mt = 0; mt < 2; mt++)
        #pragma unroll
        for (int h = 0; h < 2; h++) {
            ps[mt][h][0] += __shfl_xor_sync(0xffffffffu, ps[mt][h][0], 1);
            ps[mt][h][0] += __shfl_xor_sync(0xffffffffu, ps[mt][h][0], 2);
            ps[mt][h][1] += __shfl_xor_sync(0xffffffffu, ps[mt][h][1], 1);
            ps[mt][h][1] += __shfl_xor_sync(0xffffffffu, ps[mt][h][1], 2);
        }
    if (tig == 0) {
        #pragma unroll
        for (int mt = 0; mt < 2; mt++)
            #pragma unroll
            for (int h = 0; h < 2; h++) {
                int row = wm * 32 + mt * 16 + g4 + h * 8;
                *(float2*)&s_sum[(row * 4 + wn) * 2] =
                    make_float2(ps[mt][h][0], ps[mt][h][1]);
            }
    }
    __syncthreads();

    float mean[2][2], rstd[2][2];
    #pragma unroll
    for (int mt = 0; mt < 2; mt++)
        #pragma unroll
        for (int h = 0; h < 2; h++) {
            int row = wm * 32 + mt * 16 + g4 + h * 8;
            float s = 0.f, q = 0.f;
            #pragma unroll
            for (int w = 0; w < 4; w++) {
                float2 t = *(float2*)&s_sum[(row * 4 + w) * 2];
                s += t.x; q += t.y;
            }
            float m = s * (1.f / 256.f);
            float var = fmaxf(q * (1.f / 256.f) - m * m, 0.f);
            mean[mt][h] = m;
            rstd[mt][h] = rsqrtf(var + 1e-5f);
        }

    #pragma unroll
    for (int nt = 0; nt < 8; nt++) {
        int col = wn * 64 + nt * 8 + tig * 2;
        float gg0 = s_g[col], gg1 = s_g[col + 1];
        float bb0 = s_b[col], bb1 = s_b[col + 1];
        #pragma unroll
        for (int mt = 0; mt < 2; mt++) {
            size_t rA = (size_t)(row0 + wm * 32 + mt * 16 + g4) * 256 + col;
            float o0 = (acc[mt][nt][0] - mean[mt][0]) * rstd[mt][0] * gg0 + bb0;
            float o1 = (acc[mt][nt][1] - mean[mt][0]) * rstd[mt][0] * gg1 + bb1;
            float o2 = (acc[mt][nt][2] - mean[mt][1]) * rstd[mt][1] * gg0 + bb0;
            float o3 = (acc[mt][nt][3] - mean[mt][1]) * rstd[mt][1] * gg1 + bb1;
            uint32_t h01, l01, h23, l23;
            split2(o0, o1, h01, l01);
            split2(o2, o3, h23, l23);
            *(uint32_t*)(Xh + rA)           = h01;
            *(uint32_t*)(Xl + rA)           = l01;
            *(uint32_t*)(Xh + rA + 8 * 256) = h23;
            *(uint32_t*)(Xl + rA + 8 * 256) = l23;
        }
    }
}

// ---------------------------------------------------------------------------
// Merged weight transpose + split
// ---------------------------------------------------------------------------
__global__ void transpose_all(const float* Wqkv, const float* Wo, const float* W1,
                              const float* W2, const float* msg_W, const float* gat_W,
                              const float* spW1, const float* spW2,
                              __nv_bfloat16* Thi, __nv_bfloat16* Tlo) {
    const int z = blockIdx.z;
    const float* src;
    int dstoff, K, N;
    if (z < 2)       { src = Wqkv + (size_t)z * 256 * 768; dstoff = WT_QKV + z * 768 * 256; K = 256; N = 768; }
    else if (z < 4)  { int l = z - 2;  src = Wo + (size_t)l * 65536;  dstoff = WT_WO + l * 65536;  K = 256; N = 256; }
    else if (z < 6)  { int l = z - 4;  src = W1 + (size_t)l * 65536;  dstoff = WT_W1 + l * 65536;  K = 256; N = 256; }
    else if (z < 8)  { int l = z - 6;  src = W2 + (size_t)l * 65536;  dstoff = WT_W2 + l * 65536;  K = 256; N = 256; }
    else if (z < 11) { int r = z - 8;  src = msg_W + (size_t)r * 65536; dstoff = WT_MSG + r * 65536; K = 256; N = 256; }
    else if (z < 15) { int l = z - 11; src = gat_W + (size_t)l * 256 * 1024; dstoff = WT_GAT + l * 1024 * 256; K = 256; N = 1024; }
    else if (z < 16) { src = spW1; dstoff = WT_SP1; K = 256; N = 512; }
    else             { src = spW2; dstoff = WT_SP2; K = 512; N = 256; }

    int n0 = blockIdx.x * 32, k0 = blockIdx.y * 32;
    if (n0 >= N || k0 >= K) return;

    __shared__ float t[32][33];
    int x = threadIdx.x, y = threadIdx.y;
    #pragma unroll
    for (int i = 0; i < 4; i++)
        t[y + i * 8][x] = src[(size_t)(k0 + y + i * 8) * N + n0 + x];
    __syncthreads();
    #pragma unroll
    for (int i = 0; i < 4; i++) {
        float v = t[x][y + i * 8];
        __nv_bfloat16 h, l;
        split1(v, h, l);
        size_t o = (size_t)dstoff + (size_t)(n0 + y + i * 8) * K + k0 + x;
        Thi[o] = h; Tlo[o] = l;
    }
}

// ---------------------------------------------------------------------------
// Fused CSR build
// ---------------------------------------------------------------------------
__global__ void __launch_bounds__(1024) csr_build(const int* __restrict__ src,
                                                  const int* __restrict__ dst,
                                                  const int* __restrict__ etype) {
    __shared__ int cnt[NSEG];
    __shared__ int ws[1024];
    const int tid = threadIdx.x;
    #pragma unroll
    for (int k = 0; k < 6; k++) cnt[tid + k * 1024] = 0;
    __syncthreads();
    for (int e = tid; e < NEDGE; e += 1024)
        atomicAdd(&cnt[etype[e] * NN + dst[e]], 1);
    __syncthreads();
    const int base = tid * 6;
    int local[6];
    int sum = 0;
    #pragma unroll
    for (int k = 0; k < 6; k++) { local[k] = sum; sum += cnt[base + k]; }
    ws[tid] = sum;
    __syncthreads();
    for (int d = 1; d < 1024; d <<= 1) {
        int v = (tid >= d) ? ws[tid - d] : 0;
        __syncthreads();
        ws[tid] += v;
        __syncthreads();
    }
    int pre = ws[tid] - sum;
    #pragma unroll
    for (int k = 0; k < 6; k++) {
        g_off[base + k] = pre + local[k];
        cnt[base + k] = pre + local[k];
    }
    if (tid == 1023) g_off[NSEG] = ws[1023];
    __syncthreads();
    for (int e = tid; e < NEDGE; e += 1024) {
        int p = atomicAdd(&cnt[etype[e] * NN + dst[e]], 1);
        g_srt[p] = src[e];
    }
}

// ---------------------------------------------------------------------------
// PE table + embedding
// ---------------------------------------------------------------------------
__global__ void pe_kernel() {
    int s = blockIdx.x, d = threadIdx.x;
    int i2 = d >> 1;
    float div = expf((float)(2 * i2) * (-logf(10000.f) / (float)DIM));
    float arg = (float)s * div;
    g_PE[s * DIM + d] = (d & 1) ? cosf(arg) : sinf(arg);
}

__global__ void embed_kernel(const float* __restrict__ tok_emb,
                             const int* __restrict__ tokens) {
    int idx = (blockIdx.x * 256 + threadIdx.x) * 4;
    int row = idx >> 8;
    int d = idx & 255;
    int s = row & (SEQ - 1);
    int tok = tokens[row];
    float4 te = *(const float4*)(tok_emb + (size_t)tok * DIM + d);
    float4 pe = *(const float4*)(g_PE + s * DIM + d);
    float v0 = te.x * 16.f + pe.x;
    float v1 = te.y * 16.f + pe.y;
    float v2 = te.z * 16.f + pe.z;
    float v3 = te.w * 16.f + pe.w;
    uint32_t h01, l01, h23, l23;
    split2(v0, v1, h01, l01);
    split2(v2, v3, h23, l23);
    size_t o = (size_t)row * DIM + d;
    *(uint2*)(g_Xh + o) = make_uint2(h01, h23);
    *(uint2*)(g_Xl + o) = make_uint2(l01, l23);
}

// ---------------------------------------------------------------------------
// Attention (QKV bf16 in, T1 hi-only out)
// ---------------------------------------------------------------------------
__global__ void attn_kernel() {
    int n = blockIdx.x >> 3;
    int h = blockIdx.x & 7;
    __shared__ float Qs[SEQ][DH + 1];
    __shared__ float Ks[SEQ][DH + 1];
    __shared__ float Vs[SEQ][DH + 1];
    const __nv_bfloat16* base = g_QKVh + (size_t)n * SEQ * 3 * DIM;
    for (int e = threadIdx.x; e < SEQ * DH; e += blockDim.x) {
        int r = e >> 5, d = e & 31;
        Qs[r][d] = __bfloat162float(base[r * 3 * DIM + h * DH + d]);
        Ks[r][d] = __bfloat162float(base[r * 3 * DIM + DIM + h * DH + d]);
        Vs[r][d] = __bfloat162float(base[r * 3 * DIM + 2 * DIM + h * DH + d]);
    }
    __syncthreads();
    int i = threadIdx.x;
    float q[DH];
    #pragma unroll
    for (int d = 0; d < DH; d++) q[d] = Qs[i][d];
    const float scale = 0.17677669529663687f;
    float m = -1e30f, l = 0.f;
    float o[DH];
    #pragma unroll
    for (int d = 0; d < DH; d++) o[d] = 0.f;
    for (int j = 0; j < SEQ; j++) {
        float s0 = 0.f, s1 = 0.f, s2 = 0.f, s3 = 0.f;
        #pragma unroll
        for (int d = 0; d < DH; d += 4) {
            s0 += q[d]     * Ks[j][d];
            s1 += q[d + 1] * Ks[j][d + 1];
            s2 += q[d + 2] * Ks[j][d + 2];
            s3 += q[d + 3] * Ks[j][d + 3];
        }
        float s = ((s0 + s1) + (s2 + s3)) * scale;
        if (s > m) {
            float c = expf(m - s);
            l *= c;
            #pragma unroll
            for (int d = 0; d < DH; d++) o[d] *= c;
            m = s;
        }
        float p = expf(s - m);
        l += p;
        #pragma unroll
        for (int d = 0; d < DH; d++) o[d] += p * Vs[j][d];
    }
    float inv = 1.f / l;
    size_t ob = ((size_t)n * SEQ + i) * DIM + h * DH;
    #pragma unroll
    for (int d = 0; d < DH; d += 2)
        *(uint32_t*)(g_T1h + ob + d) = pack2(o[d] * inv, o[d + 1] * inv);
}

// ---------------------------------------------------------------------------
// mean over seq + type emb
// ---------------------------------------------------------------------------
__global__ void mean_kernel(const int* __restrict__ types,
                            const float* __restrict__ type_emb) {
    int n = blockIdx.x, d = threadIdx.x;
    float acc = 0.f;
    const __nv_bfloat16* bh = g_Xh + (size_t)n * SEQ * DIM + d;
    const __nv_bfloat16* bl = g_Xl + (size_t)n * SEQ * DIM + d;
    for (int s = 0; s < SEQ; s++)
        acc += __bfloat162float(bh[s * DIM]) + __bfloat162float(bl[s * DIM]);
    float v = acc * (1.f / SEQ) + type_emb[(size_t)types[n] * DIM + d];
    size_t o = (size_t)n * DIM + d;
    g_H[o] = v;
    __nv_bfloat16 h, l;
    split1(v, h, l);
    g_Hh[o] = h; g_Hl[o] = l;
}

// ---------------------------------------------------------------------------
// GNN kernels
// ---------------------------------------------------------------------------
__global__ void asd_kernel(const float* __restrict__ asrc,
                           const float* __restrict__ adst) {
    int i = blockIdx.x;
    int w = threadIdx.x >> 5, lane = threadIdx.x & 31;
    float s1 = 0.f, s2 = 0.f;
    const float* xg = g_XG + (size_t)i * GHEADS * DIM + w * DIM;
    #pragma unroll
    for (int d = lane; d < DIM; d += 32) {
        float xv = xg[d];
        s1 += xv * asrc[w * DIM + d];
        s2 += xv * adst[w * DIM + d];
    }
    #pragma unroll
    for (int off = 16; off > 0; off >>= 1) {
        s1 += __shfl_down_sync(0xffffffffu, s1, off);
        s2 += __shfl_down_sync(0xffffffffu, s2, off);
    }
    if (lane == 0) {
        g_AS[i * GHEADS + w] = s1;
        g_AD[i * GHEADS + w] = s2;
    }
}

__global__ void __launch_bounds__(128) csr_agg() {
    __shared__ float s_acc[4][DIM];
    const int i = blockIdx.x;
    const int w = threadIdx.x >> 5;
    const int lane = threadIdx.x & 31;
    const int rbase = (i >> 11) << 11;
    const int beg = g_off[i], end = g_off[i + 1];

    const float ad = g_AD[i * GHEADS + w];
    const float self_e = lrelu(g_AS[i * GHEADS + w] + ad);

    float m = self_e;
    for (int j = beg + lane; j < end; j += 32)
        m = fmaxf(m, lrelu(g_AS[(rbase + g_srt[j]) * GHEADS + w] + ad));
    #pragma unroll
    for (int off = 16; off > 0; off >>= 1)
        m = fmaxf(m, __shfl_xor_sync(0xffffffffu, m, off));

    float den = expf(self_e - m);
    float acc[8];
    const float* xs = g_XG + (size_t)i * (GHEADS * DIM) + w * DIM;
    #pragma unroll
    for (int k = 0; k < 8; k++) acc[k] = den * xs[lane + 32 * k];
    for (int j = beg; j < end; j++) {
        int s = rbase + g_srt[j];
        float wgt = expf(lrelu(g_AS[s * GHEADS + w] + ad) - m);
        den += wgt;
        const float* xv = g_XG + (size_t)s * (GHEADS * DIM) + w * DIM;
        #pragma unroll
        for (int k = 0; k < 8; k++) acc[k] += wgt * xv[lane + 32 * k];
    }
    float inv = 0.25f / den;
    #pragma unroll
    for (int k = 0; k < 8; k++) s_acc[w][lane + 32 * k] = acc[k] * inv;
    __syncthreads();
    float* nm = g_NUMR + (size_t)i * DIM;
    #pragma unroll
    for (int k = 0; k < 2; k++) {
        int d = threadIdx.x + 128 * k;
        nm[d] = s_acc[0][d] + s_acc[1][d] + s_acc[2][d] + s_acc[3][d];
    }
}

__global__ void combupd_kernel(const float* __restrict__ gb) {
    int n = blockIdx.x, d = threadIdx.x;
    float acc = g_NUMR[(size_t)n * DIM + d]
              + g_NUMR[(size_t)(NN + n) * DIM + d]
              + g_NUMR[(size_t)(2 * NN + n) * DIM + d];
    size_t o = (size_t)n * DIM + d;
    float v = fmaxf(g_H[o] + acc + 3.f * gb[d], 0.f);
    g_H[o] = v;
    __nv_bfloat16 h, l;
    split1(v, h, l);
    g_Hh[o] = h; g_Hl[o] = l;
}

__global__ void final_kernel(const float* __restrict__ log_c, float* __restrict__ out) {
    int n = blockIdx.x, d = threadIdx.x;
    __shared__ float sh[256];
    __shared__ float stat;
    float scale = sqrtf(expf(log_c[0]));
    float st = tanhf(g_TH[(size_t)n * DIM + d]) * 2.f * scale;
    sh[d] = st * st; __syncthreads();
    for (int s = 128; s > 0; s >>= 1) { if (d < s) sh[d] += sh[d + s]; __syncthreads(); }
    if (d == 0) stat = sh[0];
    __syncthreads();
    float r = fmaxf(sqrtf(stat), 1e-8f);
    if (d == 0) out[(size_t)n * 257] = coshf(r);
    out[(size_t)n * 257 + 1 + d] = sinhf(r) / r * st;
}

// ---------------------------------------------------------------------------
// Host orchestration
// ---------------------------------------------------------------------------
extern "C" void kernel_launch(void* const* d_in, const int* in_sizes, int n_in,
                              void* d_out, int out_size) {
    const float* tok_emb = (const float*)d_in[0];
    const float* Wqkv    = (const float*)d_in[1];
    const float* bqkv    = (const float*)d_in[2];
    const float* Wo      = (const float*)d_in[3];
    const float* bo      = (const float*)d_in[4];
    const float* ln1g    = (const float*)d_in[5];
    const float* ln1b    = (const float*)d_in[6];
    const float* ln2g    = (const float*)d_in[7];
    const float* ln2b    = (const float*)d_in[8];
    const float* W1      = (const float*)d_in[9];
    const float* b1      = (const float*)d_in[10];
    const float* W2      = (const float*)d_in[11];
    const float* b2      = (const float*)d_in[12];
    const float* type_emb= (const float*)d_in[13];
    const float* msg_W   = (const float*)d_in[14];
    const float* msg_b   = (const float*)d_in[15];
    const float* gat_W   = (const float*)d_in[16];
    const float* gat_b   = (const float*)d_in[17];
    const float* asrc    = (const float*)d_in[18];
    const float* adst    = (const float*)d_in[19];
    const float* spW1    = (const float*)d_in[20];
    const float* spb1    = (const float*)d_in[21];
    const float* spW2    = (const float*)d_in[22];
    const float* spb2    = (const float*)d_in[23];
    const float* log_c   = (const float*)d_in[24];
    const int*   tokens  = (const int*)d_in[25];
    const int*   types   = (const int*)d_in[26];
    const int*   eidx    = (const int*)d_in[27];
    const int*   etype   = (const int*)d_in[28];
    const int* esrc = eidx;
    const int* edst = eidx + NEDGE;
    float* out = (float*)d_out;

    float *pH, *pTH, *pXG;
    __nv_bfloat16 *pQKVh, *pXh, *pXl, *pT1h, *pHh, *pHl, *pTHAh, *pTHAl,
                  *pSPHh, *pSPHl, *pWTh, *pWTl;
    cudaGetSymbolAddress((void**)&pH,    g_H);
    cudaGetSymbolAddress((void**)&pTH,   g_TH);
    cudaGetSymbolAddress((void**)&pXG,   g_XG);
    cudaGetSymbolAddress((void**)&pQKVh, g_QKVh);
    cudaGetSymbolAddress((void**)&pXh,   g_Xh);
    cudaGetSymbolAddress((void**)&pXl,   g_Xl);
    cudaGetSymbolAddress((void**)&pT1h,  g_T1h);
    cudaGetSymbolAddress((void**)&pHh,   g_Hh);
    cudaGetSymbolAddress((void**)&pHl,   g_Hl);
    cudaGetSymbolAddress((void**)&pTHAh, g_THAh);
    cudaGetSymbolAddress((void**)&pTHAl, g_THAl);
    cudaGetSymbolAddress((void**)&pSPHh, g_SPHh);
    cudaGetSymbolAddress((void**)&pSPHl, g_SPHl);
    cudaGetSymbolAddress((void**)&pWTh,  g_WTh);
    cudaGetSymbolAddress((void**)&pWTl,  g_WTl);

    cudaFuncSetAttribute(gemm_bf16<true>,  cudaFuncAttributeMaxDynamicSharedMemorySize,
                         NSTAGE * STAGE_BYTES);
    cudaFuncSetAttribute(gemm_bf16<false>, cudaFuncAttributeMaxDynamicSharedMemorySize,
                         NSTAGE * STAGE_BYTES);
    cudaFuncSetAttribute(gemm_ln<false>, cudaFuncAttributeMaxDynamicSharedMemorySize,
                         3 * LSTG + 4096 + 3 * 1024);
    const int SMEM   = NSTAGE * STAGE_BYTES;
    const int SMEMLN = 3 * LSTG + 4096 + 3 * 1024;

    // 0) merged weight transpose+split, PE, fused CSR build
    transpose_all<<<dim3(32, 16, 17), dim3(32, 8)>>>(
        Wqkv, Wo, W1, W2, msg_W, gat_W, spW1, spW2, pWTh, pWTl);
    pe_kernel<<<SEQ, 256>>>();
    csr_build<<<1, 1024>>>(esrc, edst, etype);

    // 1) embedding + PE
    embed_kernel<<<NTOK * DIM / 1024, 256>>>(tok_emb, tokens);

    // 2) transformer encoder (T1 hi-only; Wo/W2 LN-GEMMs 2-term)
    for (int l = 0; l < 2; l++) {
        gemm_bf16<true><<<dim3(6, NTOK / 128), 256, SMEM>>>(
            pXh, pXl, 256, pWTh + WT_QKV + l * 768 * 256, pWTl + WT_QKV + l * 768 * 256,
            bqkv + l * 768, nullptr, pQKVh, nullptr, NTOK, 768, 256, 0, 0);
        attn_kernel<<<NN * NH, 64>>>();
        gemm_ln<false><<<NTOK / 128, 512, SMEMLN>>>(
            pT1h, nullptr, pWTh + WT_WO + l * 65536, pWTl + WT_WO + l * 65536,
            bo + l * 256, ln1g + l * 256, ln1b + l * 256, pXh, pXl);
        gemm_bf16<true><<<dim3(2, NTOK / 128), 256, SMEM>>>(
            pXh, pXl, 256, pWTh + WT_W1 + l * 65536, pWTl + WT_W1 + l * 65536,
            b1 + l * 256, nullptr, pT1h, nullptr, NTOK, 256, 256, 1, 0);
        gemm_ln<false><<<NTOK / 128, 512, SMEMLN>>>(
            pT1h, nullptr, pWTh + WT_W2 + l * 65536, pWTl + WT_W2 + l * 65536,
            b2 + l * 256, ln2g + l * 256, ln2b + l * 256, pXh, pXl);
    }

    // 3) mean over seq + type embedding
    mean_kernel<<<NN, 256>>>(types, type_emb);

    // 4) 4 GNN layers (THA fully split — feeds recurrent GNN path)
    for (int l = 0; l < 4; l++) {
        gemm_bf16<true><<<dim3(6, NN / 128), 256, SMEM>>>(
            pHh, pHl, 256, pWTh + WT_MSG, pWTl + WT_MSG,
            msg_b, nullptr, pTHAh, pTHAl, NN, 768, 256, 0, NN * DIM);
        gemm_bf16<true><<<dim3(8, NSEG / 128), 256, SMEM>>>(
            pTHAh, pTHAl, 256,
            pWTh + WT_GAT + l * 1024 * 256, pWTl + WT_GAT + l * 1024 * 256,
            nullptr, pXG, nullptr, nullptr, NSEG, 1024, 256, 0, 0);
        asd_kernel<<<NSEG, 128>>>(asrc + l * GHEADS * DIM, adst + l * GHEADS * DIM);
        csr_agg<<<NSEG, 128>>>();
        combupd_kernel<<<NN, 256>>>(gat_b + l * 256);
    }

    // 5) scoring MLP + Lorentz exp map (SPH fully split — un-normalized output path)
    gemm_bf16<true><<<dim3(4, NN / 128), 256, SMEM>>>(
        pHh, pHl, 256, pWTh + WT_SP1, pWTl + WT_SP1,
        spb1, nullptr, pSPHh, pSPHl, NN, 512, 256, 1, 0);
    gemm_bf16<true><<<dim3(2, NN / 128), 256, SMEM>>>(
        pSPHh, pSPHl, 512, pWTh + WT_SP2, pWTl + WT_SP2,
        spb2, pTH, nullptr, nullptr, NN, 256, 512, 0, 0);
    final_kernel<<<NN, 256>>>(log_c, out);
}

// round 16
// speedup vs baseline: 1.3164x; 1.0834x over previous
#include <cuda_runtime.h>
#include <cuda_bf16.h>
#include <math.h>
#include <stdint.h>

// ---------------------------------------------------------------------------
// Problem constants
// ---------------------------------------------------------------------------
#define NN      2048
#define SEQ     64
#define DIM     256
#define NH      8
#define DH      32
#define GHEADS  4
#define NEDGE   32768
#define NTOK    (NN*SEQ)
#define SPH     512
#define NREL    3
#define NSEG    (NREL*NN)     // 6144

// ---------------------------------------------------------------------------
// Scratch (device globals)
// ---------------------------------------------------------------------------
__device__ float g_H  [NN*DIM];
__device__ float g_TH [NN*DIM];
__device__ float g_PE [SEQ*DIM];
__device__ float g_XG [NSEG*GHEADS*DIM];
__device__ float g_AS [NSEG*GHEADS];
__device__ float g_AD [NSEG*GHEADS];
__device__ float g_NUMR[NSEG*DIM];

// CSR of edges sorted by (rel, dst)
__device__ int g_off[NSEG + 1];
__device__ int g_srt[NEDGE];

// bf16 activations (T1 hi-only: both consumers feed residual+LN)
__device__ __nv_bfloat16 g_QKVh[NTOK*3*DIM];
__device__ __nv_bfloat16 g_Xh [NTOK*DIM],  g_Xl [NTOK*DIM];
__device__ __nv_bfloat16 g_T1h[NTOK*DIM];
__device__ __nv_bfloat16 g_Hh [NN*DIM],    g_Hl [NN*DIM];
__device__ __nv_bfloat16 g_THAh[NREL*NN*DIM], g_THAl[NREL*NN*DIM];
__device__ __nv_bfloat16 g_SPHh[NN*SPH],   g_SPHl[NN*SPH];

// transposed + split weights, K-major [N, K]
#define WT_QKV   0
#define WT_WO    (WT_QKV + 2*768*256)
#define WT_W1    (WT_WO  + 2*256*256)
#define WT_W2    (WT_W1  + 2*256*256)
#define WT_MSG   (WT_W2  + 2*256*256)
#define WT_GAT   (WT_MSG + 3*256*256)
#define WT_SP1   (WT_GAT + 4*1024*256)
#define WT_SP2   (WT_SP1 + 512*256)
#define WT_TOTAL (WT_SP2 + 256*512)
__device__ __nv_bfloat16 g_WTh[WT_TOTAL], g_WTl[WT_TOTAL];

// ---------------------------------------------------------------------------
// Helpers
// ---------------------------------------------------------------------------
__device__ __forceinline__ float lrelu(float x) { return x > 0.f ? x : 0.2f * x; }

__device__ __forceinline__ uint32_t smem_u32(const void* p) {
    uint32_t a;
    asm("{ .reg .u64 t; cvta.to.shared.u64 t, %1; cvt.u32.u64 %0, t; }" : "=r"(a) : "l"(p));
    return a;
}

__device__ __forceinline__ void split1(float v, __nv_bfloat16& h, __nv_bfloat16& l) {
    h = __float2bfloat16_rn(v);
    l = __float2bfloat16_rn(v - __bfloat162float(h));
}

__device__ __forceinline__ void split2(float a, float b, uint32_t& hi, uint32_t& lo) {
    __nv_bfloat16 ha, la, hb, lb;
    split1(a, ha, la);
    split1(b, hb, lb);
    hi = (uint32_t)__bfloat16_as_ushort(ha) | ((uint32_t)__bfloat16_as_ushort(hb) << 16);
    lo = (uint32_t)__bfloat16_as_ushort(la) | ((uint32_t)__bfloat16_as_ushort(lb) << 16);
}

__device__ __forceinline__ uint32_t pack2(float a, float b) {
    __nv_bfloat16 ha = __float2bfloat16_rn(a), hb = __float2bfloat16_rn(b);
    return (uint32_t)__bfloat16_as_ushort(ha) | ((uint32_t)__bfloat16_as_ushort(hb) << 16);
}

__device__ __forceinline__ float bflo(uint32_t x) {
    return __bfloat162float(__ushort_as_bfloat16((unsigned short)(x & 0xffffu)));
}
__device__ __forceinline__ float bfhi(uint32_t x) {
    return __bfloat162float(__ushort_as_bfloat16((unsigned short)(x >> 16)));
}

__device__ __forceinline__ void ldsm_x4(uint32_t* r, uint32_t a) {
    asm volatile("ldmatrix.sync.aligned.m8n8.x4.shared.b16 {%0,%1,%2,%3}, [%4];"
                 : "=r"(r[0]), "=r"(r[1]), "=r"(r[2]), "=r"(r[3]) : "r"(a));
}

__device__ __forceinline__ void mma16816(float* c, const uint32_t* a, const uint32_t* b) {
    asm volatile(
        "mma.sync.aligned.m16n8k16.row.col.f32.bf16.bf16.f32 "
        "{%0,%1,%2,%3}, {%4,%5,%6,%7}, {%8,%9}, {%0,%1,%2,%3};"
        : "+f"(c[0]), "+f"(c[1]), "+f"(c[2]), "+f"(c[3])
        : "r"(a[0]), "r"(a[1]), "r"(a[2]), "r"(a[3]), "r"(b[0]), "r"(b[1]));
}

__device__ __forceinline__ void cp_async16(uint32_t dst, const void* src) {
    asm volatile("cp.async.cg.shared.global [%0], [%1], 16;" :: "r"(dst), "l"(src) : "memory");
}
__device__ __forceinline__ void cp_commit() {
    asm volatile("cp.async.commit_group;" ::: "memory");
}
template<int W> __device__ __forceinline__ void cp_wait() {
    asm volatile("cp.async.wait_group %0;" :: "n"(W) : "memory");
}

// ---------------------------------------------------------------------------
// Pipelined bf16-split GEMM (256 threads, 128x128 tile, 3-stage)
// ALO: A has lo part (3-term). Otherwise 2-term (A_hi*B_hi + A_hi*B_lo).
// ---------------------------------------------------------------------------
#define ARR_BYTES  8192
#define STAGE_BYTES (4*ARR_BYTES)
#define NSTAGE 3

template<bool ALO>
__device__ __forceinline__ void gemm_issue(
    uint32_t sb, int stage, int tid,
    const __nv_bfloat16* Ahi, const __nv_bfloat16* Alo, int lda,
    const __nv_bfloat16* Bhi, const __nv_bfloat16* Blo, int K,
    int row0, int col0, int k0)
{
    #pragma unroll
    for (int i = 0; i < 8; i++) {
        int idx = tid + i * 256;
        int arr = idx >> 9;
        if (!ALO && arr == 1) continue;
        int j   = idx & 511;
        int r   = j >> 2;
        int c   = j & 3;
        uint32_t dst = sb + stage * STAGE_BYTES + arr * ARR_BYTES
                     + (uint32_t)(r * 4 + (c ^ ((r >> 1) & 3))) * 16;
        const __nv_bfloat16* src;
        if (arr == 0)      src = Ahi + (size_t)(row0 + r) * lda + k0 + c * 8;
        else if (arr == 1) src = Alo + (size_t)(row0 + r) * lda + k0 + c * 8;
        else if (arr == 2) src = Bhi + (size_t)(col0 + r) * K + k0 + c * 8;
        else               src = Blo + (size_t)(col0 + r) * K + k0 + c * 8;
        cp_async16(dst, src);
    }
    cp_commit();
}

template<bool ALO>
__global__ void __launch_bounds__(256)
gemm_bf16(const __nv_bfloat16* __restrict__ Ahi, const __nv_bfloat16* __restrict__ Alo, int lda,
          const __nv_bfloat16* __restrict__ Bhi, const __nv_bfloat16* __restrict__ Blo,
          const float* __restrict__ bias,
          float* __restrict__ Cf,
          __nv_bfloat16* __restrict__ Chi, __nv_bfloat16* __restrict__ Clo,
          int M, int N, int K, int act, int rmaj) {
    extern __shared__ char sm[];
    const uint32_t sb = smem_u32(sm);
    const int tid  = threadIdx.x;
    const int lane = tid & 31;
    const int warp = tid >> 5;
    const int wm = warp & 3;
    const int wn = warp >> 2;
    const int row0 = blockIdx.y * 128;
    const int col0 = blockIdx.x * 128;

    float acc[2][8][4];
    #pragma unroll
    for (int i = 0; i < 2; i++)
        #pragma unroll
        for (int j = 0; j < 8; j++)
            #pragma unroll
            for (int k = 0; k < 4; k++) acc[i][j][k] = 0.f;

    const int nch = K >> 5;
    gemm_issue<ALO>(sb, 0, tid, Ahi, Alo, lda, Bhi, Blo, K, row0, col0, 0);
    if (nch > 1)
        gemm_issue<ALO>(sb, 1, tid, Ahi, Alo, lda, Bhi, Blo, K, row0, col0, 32);

    for (int ch = 0; ch < nch; ch++) {
        if (ch + 1 < nch) cp_wait<1>(); else cp_wait<0>();
        __syncthreads();

        const uint32_t base = sb + (ch % NSTAGE) * STAGE_BYTES;
        #pragma unroll
        for (int s = 0; s < 2; s++) {
            uint32_t ah[2][4], al[2][4];
            #pragma unroll
            for (int mt = 0; mt < 2; mt++) {
                int row = wm * 32 + mt * 16 + (lane & 15);
                int c = 2 * s + (lane >> 4);
                uint32_t off = (uint32_t)(row * 4 + (c ^ ((row >> 1) & 3))) * 16;
                ldsm_x4(ah[mt], base + off);
                if (ALO) ldsm_x4(al[mt], base + ARR_BYTES + off);
            }
            #pragma unroll
            for (int ntp = 0; ntp < 4; ntp++) {
                int nr = wn * 64 + (ntp * 2 + ((lane >> 4) & 1)) * 8 + (lane & 7);
                int c = 2 * s + ((lane >> 3) & 1);
                uint32_t off = (uint32_t)(nr * 4 + (c ^ ((nr >> 1) & 3))) * 16;
                uint32_t bh[4], bl[4];
                ldsm_x4(bh, base + 2 * ARR_BYTES + off);
                ldsm_x4(bl, base + 3 * ARR_BYTES + off);
                #pragma unroll
                for (int half = 0; half < 2; half++) {
                    int nt = ntp * 2 + half;
                    #pragma unroll
                    for (int mt = 0; mt < 2; mt++) {
                        mma16816(acc[mt][nt], ah[mt], bh + 2 * half);
                        mma16816(acc[mt][nt], ah[mt], bl + 2 * half);
                        if (ALO) mma16816(acc[mt][nt], al[mt], bh + 2 * half);
                    }
                }
            }
        }
        __syncthreads();
        if (ch + 2 < nch)
            gemm_issue<ALO>(sb, (ch + 2) % NSTAGE, tid, Ahi, Alo, lda, Bhi, Blo, K,
                            row0, col0, (ch + 2) << 5);
    }

    const int g4 = lane >> 2, tig = lane & 3;
    #pragma unroll
    for (int nt = 0; nt < 8; nt++) {
        int col = col0 + wn * 64 + nt * 8 + tig * 2;
        float b0 = 0.f, b1 = 0.f;
        if (bias) { b0 = bias[col]; b1 = bias[col + 1]; }
        #pragma unroll
        for (int mt = 0; mt < 2; mt++) {
            int row = row0 + wm * 32 + mt * 16 + g4;
            float v0 = acc[mt][nt][0] + b0;
            float v1 = acc[mt][nt][1] + b1;
            float v2 = acc[mt][nt][2] + b0;
            float v3 = acc[mt][nt][3] + b1;
            if (act) {
                v0 = fmaxf(v0, 0.f); v1 = fmaxf(v1, 0.f);
                v2 = fmaxf(v2, 0.f); v3 = fmaxf(v3, 0.f);
            }
            size_t o0, o1;
            if (rmaj) {
                o0 = (size_t)(col >> 8) * rmaj + (size_t)row * 256 + (col & 255);
                o1 = o0 + 8 * 256;
            } else {
                o0 = (size_t)row * N + col;
                o1 = o0 + (size_t)8 * N;
            }
            if (Cf) {
                *(float2*)(Cf + o0) = make_float2(v0, v1);
                *(float2*)(Cf + o1) = make_float2(v2, v3);
            }
            if (Chi) {
                if (Clo) {
                    uint32_t h01, l01, h23, l23;
                    split2(v0, v1, h01, l01);
                    split2(v2, v3, h23, l23);
                    *(uint32_t*)(Chi + o0) = h01;
                    *(uint32_t*)(Clo + o0) = l01;
                    *(uint32_t*)(Chi + o1) = h23;
                    *(uint32_t*)(Clo + o1) = l23;
                } else {
                    *(uint32_t*)(Chi + o0) = pack2(v0, v1);
                    *(uint32_t*)(Chi + o1) = pack2(v2, v3);
                }
            }
        }
    }
}

// ---------------------------------------------------------------------------
// Fused GEMM + residual + LayerNorm. A = T1 is hi-only (2-term).
// ---------------------------------------------------------------------------
#define LSTG 49152

template<bool ALO>
__device__ __forceinline__ void gemm_ln_issue(
    uint32_t sb, int stage, int tid, int row0, int k0,
    const __nv_bfloat16* Ahi, const __nv_bfloat16* Alo,
    const __nv_bfloat16* Bhi, const __nv_bfloat16* Blo)
{
    #pragma unroll
    for (int i = 0; i < 6; i++) {
        int idx = tid + i * 512;
        uint32_t stg = sb + stage * LSTG;
        const __nv_bfloat16* src;
        uint32_t dst;
        if (idx < 1024) {
            if (!ALO && (idx >> 9)) continue;
            int j = idx & 511;
            int r = j >> 2, c = j & 3;
            dst = stg + ((idx >> 9) ? 8192u : 0u)
                + (uint32_t)(r * 4 + (c ^ ((r >> 1) & 3))) * 16;
            src = ((idx >> 9) ? Alo : Ahi) + (size_t)(row0 + r) * 256 + k0 + c * 8;
        } else {
            int j = (idx - 1024) & 1023;
            int r = j >> 2, c = j & 3;
            dst = stg + ((idx >= 2048) ? 32768u : 16384u)
                + (uint32_t)(r * 4 + (c ^ ((r >> 1) & 3))) * 16;
            src = ((idx >= 2048) ? Blo : Bhi) + (size_t)r * 256 + k0 + c * 8;
        }
        cp_async16(dst, src);
    }
    cp_commit();
}

template<bool ALO>
__global__ void __launch_bounds__(512)
gemm_ln(const __nv_bfloat16* __restrict__ Ahi, const __nv_bfloat16* __restrict__ Alo,
        const __nv_bfloat16* __restrict__ Bhi, const __nv_bfloat16* __restrict__ Blo,
        const float* __restrict__ bias,
        const float* __restrict__ lng, const float* __restrict__ lnb,
        __nv_bfloat16* Xh, __nv_bfloat16* Xl) {
    extern __shared__ char sm[];
    const uint32_t sb = smem_u32(sm);
    float* s_sum  = (float*)(sm + 3 * LSTG);
    float* s_g    = (float*)(sm + 3 * LSTG + 4096);
    float* s_b    = s_g + 256;
    float* s_bias = s_b + 256;
    const int tid  = threadIdx.x;
    const int lane = tid & 31;
    const int warp = tid >> 5;
    const int wm = warp & 3;
    const int wn = warp >> 2;
    const int row0 = blockIdx.x * 128;

    if (tid < 256) { s_g[tid] = lng[tid]; s_b[tid] = lnb[tid]; s_bias[tid] = bias[tid]; }

    float acc[2][8][4];
    #pragma unroll
    for (int i = 0; i < 2; i++)
        #pragma unroll
        for (int j = 0; j < 8; j++)
            #pragma unroll
            for (int k = 0; k < 4; k++) acc[i][j][k] = 0.f;

    gemm_ln_issue<ALO>(sb, 0, tid, row0, 0, Ahi, Alo, Bhi, Blo);
    gemm_ln_issue<ALO>(sb, 1, tid, row0, 32, Ahi, Alo, Bhi, Blo);

    for (int ch = 0; ch < 8; ch++) {
        if (ch < 7) cp_wait<1>(); else cp_wait<0>();
        __syncthreads();
        const uint32_t base = sb + (ch % 3) * LSTG;
        #pragma unroll
        for (int s = 0; s < 2; s++) {
            uint32_t ah[2][4], al[2][4];
            #pragma unroll
            for (int mt = 0; mt < 2; mt++) {
                int row = wm * 32 + mt * 16 + (lane & 15);
                int c = 2 * s + (lane >> 4);
                uint32_t off = (uint32_t)(row * 4 + (c ^ ((row >> 1) & 3))) * 16;
                ldsm_x4(ah[mt], base + off);
                if (ALO) ldsm_x4(al[mt], base + 8192 + off);
            }
            #pragma unroll
            for (int ntp = 0; ntp < 4; ntp++) {
                int nr = wn * 64 + (ntp * 2 + ((lane >> 4) & 1)) * 8 + (lane & 7);
                int c = 2 * s + ((lane >> 3) & 1);
                uint32_t off = (uint32_t)(nr * 4 + (c ^ ((nr >> 1) & 3))) * 16;
                uint32_t bh[4], bl[4];
                ldsm_x4(bh, base + 16384 + off);
                ldsm_x4(bl, base + 32768 + off);
                #pragma unroll
                for (int half = 0; half < 2; half++) {
                    int nt = ntp * 2 + half;
                    #pragma unroll
                    for (int mt = 0; mt < 2; mt++) {
                        mma16816(acc[mt][nt], ah[mt], bh + 2 * half);
                        mma16816(acc[mt][nt], ah[mt], bl + 2 * half);
                        if (ALO) mma16816(acc[mt][nt], al[mt], bh + 2 * half);
                    }
                }
            }
        }
        __syncthreads();
        if (ch + 2 < 8)
            gemm_ln_issue<ALO>(sb, (ch + 2) % 3, tid, row0, (ch + 2) * 32, Ahi, Alo, Bhi, Blo);
    }

    const int g4 = lane >> 2, tig = lane & 3;
    float ps[2][2][2];
    #pragma unroll
    for (int mt = 0; mt < 2; mt++)
        #pragma unroll
        for (int h = 0; h < 2; h++) { ps[mt][h][0] = 0.f; ps[mt][h][1] = 0.f; }

    #pragma unroll
    for (int nt = 0; nt < 8; nt++) {
        int col = wn * 64 + nt * 8 + tig * 2;
        float b0 = s_bias[col], b1 = s_bias[col + 1];
        #pragma unroll
        for (int mt = 0; mt < 2; mt++) {
            size_t rA = (size_t)(row0 + wm * 32 + mt * 16 + g4) * 256 + col;
            uint32_t rh0 = *(const uint32_t*)(Xh + rA);
            uint32_t rl0 = *(const uint32_t*)(Xl + rA);
            uint32_t rh1 = *(const uint32_t*)(Xh + rA + 8 * 256);
            uint32_t rl1 = *(const uint32_t*)(Xl + rA + 8 * 256);
            float v0 = acc[mt][nt][0] + b0 + bflo(rh0) + bflo(rl0);
            float v1 = acc[mt][nt][1] + b1 + bfhi(rh0) + bfhi(rl0);
            float v2 = acc[mt][nt][2] + b0 + bflo(rh1) + bflo(rl1);
            float v3 = acc[mt][nt][3] + b1 + bfhi(rh1) + bfhi(rl1);
            acc[mt][nt][0] = v0; acc[mt][nt][1] = v1;
            acc[mt][nt][2] = v2; acc[mt][nt][3] = v3;
            ps[mt][0][0] += v0 + v1; ps[mt][0][1] += v0 * v0 + v1 * v1;
            ps[mt][1][0] += v2 + v3; ps[mt][1][1] += v2 * v2 + v3 * v3;
        }
    }
    #pragma unroll
    for (int mt = 0; mt < 2; mt++)
        #pragma unroll
        for (int h = 0; h < 2; h++) {
            ps[mt][h][0] += __shfl_xor_sync(0xffffffffu, ps[mt][h][0], 1);
            ps[mt][h][0] += __shfl_xor_sync(0xffffffffu, ps[mt][h][0], 2);
            ps[mt][h][1] += __shfl_xor_sync(0xffffffffu, ps[mt][h][1], 1);
            ps[mt][h][1] += __shfl_xor_sync(0xffffffffu, ps[mt][h][1], 2);
        }
    if (tig == 0) {
        #pragma unroll
        for (int mt = 0; mt < 2; mt++)
            #pragma unroll
            for (int h = 0; h < 2; h++) {
                int row = wm * 32 + mt * 16 + g4 + h * 8;
                *(float2*)&s_sum[(row * 4 + wn) * 2] =
                    make_float2(ps[mt][h][0], ps[mt][h][1]);
            }
    }
    __syncthreads();

    float mean[2][2], rstd[2][2];
    #pragma unroll
    for (int mt = 0; mt < 2; mt++)
        #pragma unroll
        for (int h = 0; h < 2; h++) {
            int row = wm * 32 + mt * 16 + g4 + h * 8;
            float s = 0.f, q = 0.f;
            #pragma unroll
            for (int w = 0; w < 4; w++) {
                float2 t = *(float2*)&s_sum[(row * 4 + w) * 2];
                s += t.x; q += t.y;
            }
            float m = s * (1.f / 256.f);
            float var = fmaxf(q * (1.f / 256.f) - m * m, 0.f);
            mean[mt][h] = m;
            rstd[mt][h] = rsqrtf(var + 1e-5f);
        }

    #pragma unroll
    for (int nt = 0; nt < 8; nt++) {
        int col = wn * 64 + nt * 8 + tig * 2;
        float gg0 = s_g[col], gg1 = s_g[col + 1];
        float bb0 = s_b[col], bb1 = s_b[col + 1];
        #pragma unroll
        for (int mt = 0; mt < 2; mt++) {
            size_t rA = (size_t)(row0 + wm * 32 + mt * 16 + g4) * 256 + col;
            float o0 = (acc[mt][nt][0] - mean[mt][0]) * rstd[mt][0] * gg0 + bb0;
            float o1 = (acc[mt][nt][1] - mean[mt][0]) * rstd[mt][0] * gg1 + bb1;
            float o2 = (acc[mt][nt][2] - mean[mt][1]) * rstd[mt][1] * gg0 + bb0;
            float o3 = (acc[mt][nt][3] - mean[mt][1]) * rstd[mt][1] * gg1 + bb1;
            uint32_t h01, l01, h23, l23;
            split2(o0, o1, h01, l01);
            split2(o2, o3, h23, l23);
            *(uint32_t*)(Xh + rA)           = h01;
            *(uint32_t*)(Xl + rA)           = l01;
            *(uint32_t*)(Xh + rA + 8 * 256) = h23;
            *(uint32_t*)(Xl + rA + 8 * 256) = l23;
        }
    }
}

// ---------------------------------------------------------------------------
// Merged weight transpose + split
// ---------------------------------------------------------------------------
__global__ void transpose_all(const float* Wqkv, const float* Wo, const float* W1,
                              const float* W2, const float* msg_W, const float* gat_W,
                              const float* spW1, const float* spW2,
                              __nv_bfloat16* Thi, __nv_bfloat16* Tlo) {
    const int z = blockIdx.z;
    const float* src;
    int dstoff, K, N;
    if (z < 2)       { src = Wqkv + (size_t)z * 256 * 768; dstoff = WT_QKV + z * 768 * 256; K = 256; N = 768; }
    else if (z < 4)  { int l = z - 2;  src = Wo + (size_t)l * 65536;  dstoff = WT_WO + l * 65536;  K = 256; N = 256; }
    else if (z < 6)  { int l = z - 4;  src = W1 + (size_t)l * 65536;  dstoff = WT_W1 + l * 65536;  K = 256; N = 256; }
    else if (z < 8)  { int l = z - 6;  src = W2 + (size_t)l * 65536;  dstoff = WT_W2 + l * 65536;  K = 256; N = 256; }
    else if (z < 11) { int r = z - 8;  src = msg_W + (size_t)r * 65536; dstoff = WT_MSG + r * 65536; K = 256; N = 256; }
    else if (z < 15) { int l = z - 11; src = gat_W + (size_t)l * 256 * 1024; dstoff = WT_GAT + l * 1024 * 256; K = 256; N = 1024; }
    else if (z < 16) { src = spW1; dstoff = WT_SP1; K = 256; N = 512; }
    else             { src = spW2; dstoff = WT_SP2; K = 512; N = 256; }

    int n0 = blockIdx.x * 32, k0 = blockIdx.y * 32;
    if (n0 >= N || k0 >= K) return;

    __shared__ float t[32][33];
    int x = threadIdx.x, y = threadIdx.y;
    #pragma unroll
    for (int i = 0; i < 4; i++)
        t[y + i * 8][x] = src[(size_t)(k0 + y + i * 8) * N + n0 + x];
    __syncthreads();
    #pragma unroll
    for (int i = 0; i < 4; i++) {
        float v = t[x][y + i * 8];
        __nv_bfloat16 h, l;
        split1(v, h, l);
        size_t o = (size_t)dstoff + (size_t)(n0 + y + i * 8) * K + k0 + x;
        Thi[o] = h; Tlo[o] = l;
    }
}

// ---------------------------------------------------------------------------
// Fused CSR build
// ---------------------------------------------------------------------------
__global__ void __launch_bounds__(1024) csr_build(const int* __restrict__ src,
                                                  const int* __restrict__ dst,
                                                  const int* __restrict__ etype) {
    __shared__ int cnt[NSEG];
    __shared__ int ws[1024];
    const int tid = threadIdx.x;
    #pragma unroll
    for (int k = 0; k < 6; k++) cnt[tid + k * 1024] = 0;
    __syncthreads();
    for (int e = tid; e < NEDGE; e += 1024)
        atomicAdd(&cnt[etype[e] * NN + dst[e]], 1);
    __syncthreads();
    const int base = tid * 6;
    int local[6];
    int sum = 0;
    #pragma unroll
    for (int k = 0; k < 6; k++) { local[k] = sum; sum += cnt[base + k]; }
    ws[tid] = sum;
    __syncthreads();
    for (int d = 1; d < 1024; d <<= 1) {
        int v = (tid >= d) ? ws[tid - d] : 0;
        __syncthreads();
        ws[tid] += v;
        __syncthreads();
    }
    int pre = ws[tid] - sum;
    #pragma unroll
    for (int k = 0; k < 6; k++) {
        g_off[base + k] = pre + local[k];
        cnt[base + k] = pre + local[k];
    }
    if (tid == 1023) g_off[NSEG] = ws[1023];
    __syncthreads();
    for (int e = tid; e < NEDGE; e += 1024) {
        int p = atomicAdd(&cnt[etype[e] * NN + dst[e]], 1);
        g_srt[p] = src[e];
    }
}

// ---------------------------------------------------------------------------
// PE table + embedding
// ---------------------------------------------------------------------------
__global__ void pe_kernel() {
    int s = blockIdx.x, d = threadIdx.x;
    int i2 = d >> 1;
    float div = expf((float)(2 * i2) * (-logf(10000.f) / (float)DIM));
    float arg = (float)s * div;
    g_PE[s * DIM + d] = (d & 1) ? cosf(arg) : sinf(arg);
}

__global__ void embed_kernel(const float* __restrict__ tok_emb,
                             const int* __restrict__ tokens) {
    int idx = (blockIdx.x * 256 + threadIdx.x) * 4;
    int row = idx >> 8;
    int d = idx & 255;
    int s = row & (SEQ - 1);
    int tok = tokens[row];
    float4 te = *(const float4*)(tok_emb + (size_t)tok * DIM + d);
    float4 pe = *(const float4*)(g_PE + s * DIM + d);
    float v0 = te.x * 16.f + pe.x;
    float v1 = te.y * 16.f + pe.y;
    float v2 = te.z * 16.f + pe.z;
    float v3 = te.w * 16.f + pe.w;
    uint32_t h01, l01, h23, l23;
    split2(v0, v1, h01, l01);
    split2(v2, v3, h23, l23);
    size_t o = (size_t)row * DIM + d;
    *(uint2*)(g_Xh + o) = make_uint2(h01, h23);
    *(uint2*)(g_Xl + o) = make_uint2(l01, l23);
}

// ---------------------------------------------------------------------------
// Attention (QKV bf16 in, T1 hi-only out)
// ---------------------------------------------------------------------------
__global__ void attn_kernel() {
    int n = blockIdx.x >> 3;
    int h = blockIdx.x & 7;
    __shared__ float Qs[SEQ][DH + 1];
    __shared__ float Ks[SEQ][DH + 1];
    __shared__ float Vs[SEQ][DH + 1];
    const __nv_bfloat16* base = g_QKVh + (size_t)n * SEQ * 3 * DIM;
    for (int e = threadIdx.x; e < SEQ * DH; e += blockDim.x) {
        int r = e >> 5, d = e & 31;
        Qs[r][d] = __bfloat162float(base[r * 3 * DIM + h * DH + d]);
        Ks[r][d] = __bfloat162float(base[r * 3 * DIM + DIM + h * DH + d]);
        Vs[r][d] = __bfloat162float(base[r * 3 * DIM + 2 * DIM + h * DH + d]);
    }
    __syncthreads();
    int i = threadIdx.x;
    float q[DH];
    #pragma unroll
    for (int d = 0; d < DH; d++) q[d] = Qs[i][d];
    const float scale = 0.17677669529663687f;
    float m = -1e30f, l = 0.f;
    float o[DH];
    #pragma unroll
    for (int d = 0; d < DH; d++) o[d] = 0.f;
    for (int j = 0; j < SEQ; j++) {
        float s0 = 0.f, s1 = 0.f, s2 = 0.f, s3 = 0.f;
        #pragma unroll
        for (int d = 0; d < DH; d += 4) {
            s0 += q[d]     * Ks[j][d];
            s1 += q[d + 1] * Ks[j][d + 1];
            s2 += q[d + 2] * Ks[j][d + 2];
            s3 += q[d + 3] * Ks[j][d + 3];
        }
        float s = ((s0 + s1) + (s2 + s3)) * scale;
        if (s > m) {
            float c = expf(m - s);
            l *= c;
            #pragma unroll
            for (int d = 0; d < DH; d++) o[d] *= c;
            m = s;
        }
        float p = expf(s - m);
        l += p;
        #pragma unroll
        for (int d = 0; d < DH; d++) o[d] += p * Vs[j][d];
    }
    float inv = 1.f / l;
    size_t ob = ((size_t)n * SEQ + i) * DIM + h * DH;
    #pragma unroll
    for (int d = 0; d < DH; d += 2)
        *(uint32_t*)(g_T1h + ob + d) = pack2(o[d] * inv, o[d + 1] * inv);
}

// ---------------------------------------------------------------------------
// mean over seq + type emb
// ---------------------------------------------------------------------------
__global__ void mean_kernel(const int* __restrict__ types,
                            const float* __restrict__ type_emb) {
    int n = blockIdx.x, d = threadIdx.x;
    float acc = 0.f;
    const __nv_bfloat16* bh = g_Xh + (size_t)n * SEQ * DIM + d;
    const __nv_bfloat16* bl = g_Xl + (size_t)n * SEQ * DIM + d;
    for (int s = 0; s < SEQ; s++)
        acc += __bfloat162float(bh[s * DIM]) + __bfloat162float(bl[s * DIM]);
    float v = acc * (1.f / SEQ) + type_emb[(size_t)types[n] * DIM + d];
    size_t o = (size_t)n * DIM + d;
    g_H[o] = v;
    __nv_bfloat16 h, l;
    split1(v, h, l);
    g_Hh[o] = h; g_Hl[o] = l;
}

// ---------------------------------------------------------------------------
// GNN kernels
// ---------------------------------------------------------------------------
__global__ void asd_kernel(const float* __restrict__ asrc,
                           const float* __restrict__ adst) {
    int i = blockIdx.x;
    int w = threadIdx.x >> 5, lane = threadIdx.x & 31;
    float s1 = 0.f, s2 = 0.f;
    const float* xg = g_XG + (size_t)i * GHEADS * DIM + w * DIM;
    #pragma unroll
    for (int d = lane; d < DIM; d += 32) {
        float xv = xg[d];
        s1 += xv * asrc[w * DIM + d];
        s2 += xv * adst[w * DIM + d];
    }
    #pragma unroll
    for (int off = 16; off > 0; off >>= 1) {
        s1 += __shfl_down_sync(0xffffffffu, s1, off);
        s2 += __shfl_down_sync(0xffffffffu, s2, off);
    }
    if (lane == 0) {
        g_AS[i * GHEADS + w] = s1;
        g_AD[i * GHEADS + w] = s2;
    }
}

__global__ void __launch_bounds__(128) csr_agg() {
    __shared__ float s_acc[4][DIM];
    const int i = blockIdx.x;
    const int w = threadIdx.x >> 5;
    const int lane = threadIdx.x & 31;
    const int rbase = (i >> 11) << 11;
    const int beg = g_off[i], end = g_off[i + 1];

    const float ad = g_AD[i * GHEADS + w];
    const float self_e = lrelu(g_AS[i * GHEADS + w] + ad);

    float m = self_e;
    for (int j = beg + lane; j < end; j += 32)
        m = fmaxf(m, lrelu(g_AS[(rbase + g_srt[j]) * GHEADS + w] + ad));
    #pragma unroll
    for (int off = 16; off > 0; off >>= 1)
        m = fmaxf(m, __shfl_xor_sync(0xffffffffu, m, off));

    float den = expf(self_e - m);
    float acc[8];
    const float* xs = g_XG + (size_t)i * (GHEADS * DIM) + w * DIM;
    #pragma unroll
    for (int k = 0; k < 8; k++) acc[k] = den * xs[lane + 32 * k];
    for (int j = beg; j < end; j++) {
        int s = rbase + g_srt[j];
        float wgt = expf(lrelu(g_AS[s * GHEADS + w] + ad) - m);
        den += wgt;
        const float* xv = g_XG + (size_t)s * (GHEADS * DIM) + w * DIM;
        #pragma unroll
        for (int k = 0; k < 8; k++) acc[k] += wgt * xv[lane + 32 * k];
    }
    float inv = 0.25f / den;
    #pragma unroll
    for (int k = 0; k < 8; k++) s_acc[w][lane + 32 * k] = acc[k] * inv;
    __syncthreads();
    float* nm = g_NUMR + (size_t)i * DIM;
    #pragma unroll
    for (int k = 0; k < 2; k++) {
        int d = threadIdx.x + 128 * k;
        nm[d] = s_acc[0][d] + s_acc[1][d] + s_acc[2][d] + s_acc[3][d];
    }
}

__global__ void combupd_kernel(const float* __restrict__ gb) {
    int n = blockIdx.x, d = threadIdx.x;
    float acc = g_NUMR[(size_t)n * DIM + d]
              + g_NUMR[(size_t)(NN + n) * DIM + d]
              + g_NUMR[(size_t)(2 * NN + n) * DIM + d];
    size_t o = (size_t)n * DIM + d;
    float v = fmaxf(g_H[o] + acc + 3.f * gb[d], 0.f);
    g_H[o] = v;
    __nv_bfloat16 h, l;
    split1(v, h, l);
    g_Hh[o] = h; g_Hl[o] = l;
}

__global__ void final_kernel(const float* __restrict__ log_c, float* __restrict__ out) {
    int n = blockIdx.x, d = threadIdx.x;
    __shared__ float sh[256];
    __shared__ float stat;
    float scale = sqrtf(expf(log_c[0]));
    float st = tanhf(g_TH[(size_t)n * DIM + d]) * 2.f * scale;
    sh[d] = st * st; __syncthreads();
    for (int s = 128; s > 0; s >>= 1) { if (d < s) sh[d] += sh[d + s]; __syncthreads(); }
    if (d == 0) stat = sh[0];
    __syncthreads();
    float r = fmaxf(sqrtf(stat), 1e-8f);
    if (d == 0) out[(size_t)n * 257] = coshf(r);
    out[(size_t)n * 257 + 1 + d] = sinhf(r) / r * st;
}

// ---------------------------------------------------------------------------
// Host orchestration
// ---------------------------------------------------------------------------
extern "C" void kernel_launch(void* const* d_in, const int* in_sizes, int n_in,
                              void* d_out, int out_size) {
    const float* tok_emb = (const float*)d_in[0];
    const float* Wqkv    = (const float*)d_in[1];
    const float* bqkv    = (const float*)d_in[2];
    const float* Wo      = (const float*)d_in[3];
    const float* bo      = (const float*)d_in[4];
    const float* ln1g    = (const float*)d_in[5];
    const float* ln1b    = (const float*)d_in[6];
    const float* ln2g    = (const float*)d_in[7];
    const float* ln2b    = (const float*)d_in[8];
    const float* W1      = (const float*)d_in[9];
    const float* b1      = (const float*)d_in[10];
    const float* W2      = (const float*)d_in[11];
    const float* b2      = (const float*)d_in[12];
    const float* type_emb= (const float*)d_in[13];
    const float* msg_W   = (const float*)d_in[14];
    const float* msg_b   = (const float*)d_in[15];
    const float* gat_W   = (const float*)d_in[16];
    const float* gat_b   = (const float*)d_in[17];
    const float* asrc    = (const float*)d_in[18];
    const float* adst    = (const float*)d_in[19];
    const float* spW1    = (const float*)d_in[20];
    const float* spb1    = (const float*)d_in[21];
    const float* spW2    = (const float*)d_in[22];
    const float* spb2    = (const float*)d_in[23];
    const float* log_c   = (const float*)d_in[24];
    const int*   tokens  = (const int*)d_in[25];
    const int*   types   = (const int*)d_in[26];
    const int*   eidx    = (const int*)d_in[27];
    const int*   etype   = (const int*)d_in[28];
    const int* esrc = eidx;
    const int* edst = eidx + NEDGE;
    float* out = (float*)d_out;

    float *pH, *pTH, *pXG;
    __nv_bfloat16 *pQKVh, *pXh, *pXl, *pT1h, *pHh, *pHl, *pTHAh, *pTHAl,
                  *pSPHh, *pSPHl, *pWTh, *pWTl;
    cudaGetSymbolAddress((void**)&pH,    g_H);
    cudaGetSymbolAddress((void**)&pTH,   g_TH);
    cudaGetSymbolAddress((void**)&pXG,   g_XG);
    cudaGetSymbolAddress((void**)&pQKVh, g_QKVh);
    cudaGetSymbolAddress((void**)&pXh,   g_Xh);
    cudaGetSymbolAddress((void**)&pXl,   g_Xl);
    cudaGetSymbolAddress((void**)&pT1h,  g_T1h);
    cudaGetSymbolAddress((void**)&pHh,   g_Hh);
    cudaGetSymbolAddress((void**)&pHl,   g_Hl);
    cudaGetSymbolAddress((void**)&pTHAh, g_THAh);
    cudaGetSymbolAddress((void**)&pTHAl, g_THAl);
    cudaGetSymbolAddress((void**)&pSPHh, g_SPHh);
    cudaGetSymbolAddress((void**)&pSPHl, g_SPHl);
    cudaGetSymbolAddress((void**)&pWTh,  g_WTh);
    cudaGetSymbolAddress((void**)&pWTl,  g_WTl);

    cudaFuncSetAttribute(gemm_bf16<true>,  cudaFuncAttributeMaxDynamicSharedMemorySize,
                         NSTAGE * STAGE_BYTES);
    cudaFuncSetAttribute(gemm_bf16<false>, cudaFuncAttributeMaxDynamicSharedMemorySize,
                         NSTAGE * STAGE_BYTES);
    cudaFuncSetAttribute(gemm_ln<false>, cudaFuncAttributeMaxDynamicSharedMemorySize,
                         3 * LSTG + 4096 + 3 * 1024);
    const int SMEM   = NSTAGE * STAGE_BYTES;
    const int SMEMLN = 3 * LSTG + 4096 + 3 * 1024;

    // 0) merged weight transpose+split, PE, fused CSR build
    transpose_all<<<dim3(32, 16, 17), dim3(32, 8)>>>(
        Wqkv, Wo, W1, W2, msg_W, gat_W, spW1, spW2, pWTh, pWTl);
    pe_kernel<<<SEQ, 256>>>();
    csr_build<<<1, 1024>>>(esrc, edst, etype);

    // 1) embedding + PE
    embed_kernel<<<NTOK * DIM / 1024, 256>>>(tok_emb, tokens);

    // 2) transformer encoder (QKV & W1 2-term: LN-damped consumers)
    for (int l = 0; l < 2; l++) {
        gemm_bf16<false><<<dim3(6, NTOK / 128), 256, SMEM>>>(
            pXh, nullptr, 256, pWTh + WT_QKV + l * 768 * 256, pWTl + WT_QKV + l * 768 * 256,
            bqkv + l * 768, nullptr, pQKVh, nullptr, NTOK, 768, 256, 0, 0);
        attn_kernel<<<NN * NH, 64>>>();
        gemm_ln<false><<<NTOK / 128, 512, SMEMLN>>>(
            pT1h, nullptr, pWTh + WT_WO + l * 65536, pWTl + WT_WO + l * 65536,
            bo + l * 256, ln1g + l * 256, ln1b + l * 256, pXh, pXl);
        gemm_bf16<false><<<dim3(2, NTOK / 128), 256, SMEM>>>(
            pXh, nullptr, 256, pWTh + WT_W1 + l * 65536, pWTl + WT_W1 + l * 65536,
            b1 + l * 256, nullptr, pT1h, nullptr, NTOK, 256, 256, 1, 0);
        gemm_ln<false><<<NTOK / 128, 512, SMEMLN>>>(
            pT1h, nullptr, pWTh + WT_W2 + l * 65536, pWTl + WT_W2 + l * 65536,
            b2 + l * 256, ln2g + l * 256, ln2b + l * 256, pXh, pXl);
    }

    // 3) mean over seq + type embedding
    mean_kernel<<<NN, 256>>>(types, type_emb);

    // 4) 4 GNN layers (recurrent path: keep full 3-term splits)
    for (int l = 0; l < 4; l++) {
        gemm_bf16<true><<<dim3(6, NN / 128), 256, SMEM>>>(
            pHh, pHl, 256, pWTh + WT_MSG, pWTl + WT_MSG,
            msg_b, nullptr, pTHAh, pTHAl, NN, 768, 256, 0, NN * DIM);
        gemm_bf16<true><<<dim3(8, NSEG / 128), 256, SMEM>>>(
            pTHAh, pTHAl, 256,
            pWTh + WT_GAT + l * 1024 * 256, pWTl + WT_GAT + l * 1024 * 256,
            nullptr, pXG, nullptr, nullptr, NSEG, 1024, 256, 0, 0);
        asd_kernel<<<NSEG, 128>>>(asrc + l * GHEADS * DIM, adst + l * GHEADS * DIM);
        csr_agg<<<NSEG, 128>>>();
        combupd_kernel<<<NN, 256>>>(gat_b + l * 256);
    }

    // 5) scoring MLP + Lorentz exp map (un-normalized output path: 3-term)
    gemm_bf16<true><<<dim3(4, NN / 128), 256, SMEM>>>(
        pHh, pHl, 256, pWTh + WT_SP1, pWTl + WT_SP1,
        spb1, nullptr, pSPHh, pSPHl, NN, 512, 256, 1, 0);
    gemm_bf16<true><<<dim3(2, NN / 128), 256, SMEM>>>(
        pSPHh, pSPHl, 512, pWTh + WT_SP2, pWTl + WT_SP2,
        spb2, pTH, nullptr, nullptr, NN, 256, 512, 0, 0);
    final_kernel<<<NN, 256>>>(log_c, out);
}

// round 17
// speedup vs baseline: 1.8733x; 1.4230x over previous
#include <cuda_runtime.h>
#include <cuda_bf16.h>
#include <math.h>
#include <stdint.h>

// ---------------------------------------------------------------------------
// Problem constants
// ---------------------------------------------------------------------------
#define NN      2048
#define SEQ     64
#define DIM     256
#define NH      8
#define DH      32
#define GHEADS  4
#define NEDGE   32768
#define NTOK    (NN*SEQ)
#define SPH     512
#define NREL    3
#define NSEG    (NREL*NN)     // 6144

// ---------------------------------------------------------------------------
// Scratch (device globals)
// ---------------------------------------------------------------------------
__device__ float g_H  [NN*DIM];
__device__ float g_TH [NN*DIM];
__device__ float g_PE [SEQ*DIM];
__device__ float g_XG [NSEG*GHEADS*DIM];
__device__ float g_AS [NSEG*GHEADS];
__device__ float g_AD [NSEG*GHEADS];
__device__ float g_NUMR[NSEG*DIM];

// CSR of edges sorted by (rel, dst)
__device__ int g_off[NSEG + 1];
__device__ int g_srt[NEDGE];

// bf16 activations
__device__ __nv_bfloat16 g_QKVh[NTOK*3*DIM];
__device__ __nv_bfloat16 g_Xh [NTOK*DIM],  g_Xl [NTOK*DIM];
__device__ __nv_bfloat16 g_T1h[NTOK*DIM];
__device__ __nv_bfloat16 g_Hh [NN*DIM],    g_Hl [NN*DIM];
__device__ __nv_bfloat16 g_THAh[NREL*NN*DIM], g_THAl[NREL*NN*DIM];
__device__ __nv_bfloat16 g_SPHh[NN*SPH],   g_SPHl[NN*SPH];

// transposed + split weights, K-major [N, K]
#define WT_QKV   0
#define WT_WO    (WT_QKV + 2*768*256)
#define WT_W1    (WT_WO  + 2*256*256)
#define WT_W2    (WT_W1  + 2*256*256)
#define WT_MSG   (WT_W2  + 2*256*256)
#define WT_GAT   (WT_MSG + 3*256*256)
#define WT_SP1   (WT_GAT + 4*1024*256)
#define WT_SP2   (WT_SP1 + 512*256)
#define WT_TOTAL (WT_SP2 + 256*512)
__device__ __nv_bfloat16 g_WTh[WT_TOTAL], g_WTl[WT_TOTAL];

// ---------------------------------------------------------------------------
// Helpers
// ---------------------------------------------------------------------------
__device__ __forceinline__ float lrelu(float x) { return x > 0.f ? x : 0.2f * x; }

__device__ __forceinline__ uint32_t smem_u32(const void* p) {
    uint32_t a;
    asm("{ .reg .u64 t; cvta.to.shared.u64 t, %1; cvt.u32.u64 %0, t; }" : "=r"(a) : "l"(p));
    return a;
}

__device__ __forceinline__ void split1(float v, __nv_bfloat16& h, __nv_bfloat16& l) {
    h = __float2bfloat16_rn(v);
    l = __float2bfloat16_rn(v - __bfloat162float(h));
}

__device__ __forceinline__ void split2(float a, float b, uint32_t& hi, uint32_t& lo) {
    __nv_bfloat16 ha, la, hb, lb;
    split1(a, ha, la);
    split1(b, hb, lb);
    hi = (uint32_t)__bfloat16_as_ushort(ha) | ((uint32_t)__bfloat16_as_ushort(hb) << 16);
    lo = (uint32_t)__bfloat16_as_ushort(la) | ((uint32_t)__bfloat16_as_ushort(lb) << 16);
}

__device__ __forceinline__ uint32_t pack2(float a, float b) {
    __nv_bfloat16 ha = __float2bfloat16_rn(a), hb = __float2bfloat16_rn(b);
    return (uint32_t)__bfloat16_as_ushort(ha) | ((uint32_t)__bfloat16_as_ushort(hb) << 16);
}

__device__ __forceinline__ float bflo(uint32_t x) {
    return __bfloat162float(__ushort_as_bfloat16((unsigned short)(x & 0xffffu)));
}
__device__ __forceinline__ float bfhi(uint32_t x) {
    return __bfloat162float(__ushort_as_bfloat16((unsigned short)(x >> 16)));
}

__device__ __forceinline__ void ldsm_x4(uint32_t* r, uint32_t a) {
    asm volatile("ldmatrix.sync.aligned.m8n8.x4.shared.b16 {%0,%1,%2,%3}, [%4];"
                 : "=r"(r[0]), "=r"(r[1]), "=r"(r[2]), "=r"(r[3]) : "r"(a));
}

__device__ __forceinline__ void mma16816(float* c, const uint32_t* a, const uint32_t* b) {
    asm volatile(
        "mma.sync.aligned.m16n8k16.row.col.f32.bf16.bf16.f32 "
        "{%0,%1,%2,%3}, {%4,%5,%6,%7}, {%8,%9}, {%0,%1,%2,%3};"
        : "+f"(c[0]), "+f"(c[1]), "+f"(c[2]), "+f"(c[3])
        : "r"(a[0]), "r"(a[1]), "r"(a[2]), "r"(a[3]), "r"(b[0]), "r"(b[1]));
}

__device__ __forceinline__ void cp_async16(uint32_t dst, const void* src) {
    asm volatile("cp.async.cg.shared.global [%0], [%1], 16;" :: "r"(dst), "l"(src) : "memory");
}
__device__ __forceinline__ void cp_commit() {
    asm volatile("cp.async.commit_group;" ::: "memory");
}
template<int W> __device__ __forceinline__ void cp_wait() {
    asm volatile("cp.async.wait_group %0;" :: "n"(W) : "memory");
}

// ---------------------------------------------------------------------------
// Pipelined bf16-split GEMM (256 threads, 128x128 tile, 3-stage)
// ALO: A has lo part (3-term). Otherwise 2-term (A_hi*B_hi + A_hi*B_lo).
// ---------------------------------------------------------------------------
#define ARR_BYTES  8192
#define STAGE_BYTES (4*ARR_BYTES)
#define NSTAGE 3

template<bool ALO>
__device__ __forceinline__ void gemm_issue(
    uint32_t sb, int stage, int tid,
    const __nv_bfloat16* Ahi, const __nv_bfloat16* Alo, int lda,
    const __nv_bfloat16* Bhi, const __nv_bfloat16* Blo, int K,
    int row0, int col0, int k0)
{
    #pragma unroll
    for (int i = 0; i < 8; i++) {
        int idx = tid + i * 256;
        int arr = idx >> 9;
        if (!ALO && arr == 1) continue;
        int j   = idx & 511;
        int r   = j >> 2;
        int c   = j & 3;
        uint32_t dst = sb + stage * STAGE_BYTES + arr * ARR_BYTES
                     + (uint32_t)(r * 4 + (c ^ ((r >> 1) & 3))) * 16;
        const __nv_bfloat16* src;
        if (arr == 0)      src = Ahi + (size_t)(row0 + r) * lda + k0 + c * 8;
        else if (arr == 1) src = Alo + (size_t)(row0 + r) * lda + k0 + c * 8;
        else if (arr == 2) src = Bhi + (size_t)(col0 + r) * K + k0 + c * 8;
        else               src = Blo + (size_t)(col0 + r) * K + k0 + c * 8;
        cp_async16(dst, src);
    }
    cp_commit();
}

template<bool ALO>
__global__ void __launch_bounds__(256)
gemm_bf16(const __nv_bfloat16* __restrict__ Ahi, const __nv_bfloat16* __restrict__ Alo, int lda,
          const __nv_bfloat16* __restrict__ Bhi, const __nv_bfloat16* __restrict__ Blo,
          const float* __restrict__ bias,
          float* __restrict__ Cf,
          __nv_bfloat16* __restrict__ Chi, __nv_bfloat16* __restrict__ Clo,
          int M, int N, int K, int act, int rmaj) {
    extern __shared__ char sm[];
    const uint32_t sb = smem_u32(sm);
    const int tid  = threadIdx.x;
    const int lane = tid & 31;
    const int warp = tid >> 5;
    const int wm = warp & 3;
    const int wn = warp >> 2;
    const int row0 = blockIdx.y * 128;
    const int col0 = blockIdx.x * 128;

    float acc[2][8][4];
    #pragma unroll
    for (int i = 0; i < 2; i++)
        #pragma unroll
        for (int j = 0; j < 8; j++)
            #pragma unroll
            for (int k = 0; k < 4; k++) acc[i][j][k] = 0.f;

    const int nch = K >> 5;
    gemm_issue<ALO>(sb, 0, tid, Ahi, Alo, lda, Bhi, Blo, K, row0, col0, 0);
    if (nch > 1)
        gemm_issue<ALO>(sb, 1, tid, Ahi, Alo, lda, Bhi, Blo, K, row0, col0, 32);

    for (int ch = 0; ch < nch; ch++) {
        if (ch + 1 < nch) cp_wait<1>(); else cp_wait<0>();
        __syncthreads();

        const uint32_t base = sb + (ch % NSTAGE) * STAGE_BYTES;
        #pragma unroll
        for (int s = 0; s < 2; s++) {
            uint32_t ah[2][4], al[2][4];
            #pragma unroll
            for (int mt = 0; mt < 2; mt++) {
                int row = wm * 32 + mt * 16 + (lane & 15);
                int c = 2 * s + (lane >> 4);
                uint32_t off = (uint32_t)(row * 4 + (c ^ ((row >> 1) & 3))) * 16;
                ldsm_x4(ah[mt], base + off);
                if (ALO) ldsm_x4(al[mt], base + ARR_BYTES + off);
            }
            #pragma unroll
            for (int ntp = 0; ntp < 4; ntp++) {
                int nr = wn * 64 + (ntp * 2 + ((lane >> 4) & 1)) * 8 + (lane & 7);
                int c = 2 * s + ((lane >> 3) & 1);
                uint32_t off = (uint32_t)(nr * 4 + (c ^ ((nr >> 1) & 3))) * 16;
                uint32_t bh[4], bl[4];
                ldsm_x4(bh, base + 2 * ARR_BYTES + off);
                ldsm_x4(bl, base + 3 * ARR_BYTES + off);
                #pragma unroll
                for (int half = 0; half < 2; half++) {
                    int nt = ntp * 2 + half;
                    #pragma unroll
                    for (int mt = 0; mt < 2; mt++) {
                        mma16816(acc[mt][nt], ah[mt], bh + 2 * half);
                        mma16816(acc[mt][nt], ah[mt], bl + 2 * half);
                        if (ALO) mma16816(acc[mt][nt], al[mt], bh + 2 * half);
                    }
                }
            }
        }
        __syncthreads();
        if (ch + 2 < nch)
            gemm_issue<ALO>(sb, (ch + 2) % NSTAGE, tid, Ahi, Alo, lda, Bhi, Blo, K,
                            row0, col0, (ch + 2) << 5);
    }

    const int g4 = lane >> 2, tig = lane & 3;
    #pragma unroll
    for (int nt = 0; nt < 8; nt++) {
        int col = col0 + wn * 64 + nt * 8 + tig * 2;
        float b0 = 0.f, b1 = 0.f;
        if (bias) { b0 = bias[col]; b1 = bias[col + 1]; }
        #pragma unroll
        for (int mt = 0; mt < 2; mt++) {
            int row = row0 + wm * 32 + mt * 16 + g4;
            float v0 = acc[mt][nt][0] + b0;
            float v1 = acc[mt][nt][1] + b1;
            float v2 = acc[mt][nt][2] + b0;
            float v3 = acc[mt][nt][3] + b1;
            if (act) {
                v0 = fmaxf(v0, 0.f); v1 = fmaxf(v1, 0.f);
                v2 = fmaxf(v2, 0.f); v3 = fmaxf(v3, 0.f);
            }
            size_t o0, o1;
            if (rmaj) {
                o0 = (size_t)(col >> 8) * rmaj + (size_t)row * 256 + (col & 255);
                o1 = o0 + 8 * 256;
            } else {
                o0 = (size_t)row * N + col;
                o1 = o0 + (size_t)8 * N;
            }
            if (Cf) {
                *(float2*)(Cf + o0) = make_float2(v0, v1);
                *(float2*)(Cf + o1) = make_float2(v2, v3);
            }
            if (Chi) {
                if (Clo) {
                    uint32_t h01, l01, h23, l23;
                    split2(v0, v1, h01, l01);
                    split2(v2, v3, h23, l23);
                    *(uint32_t*)(Chi + o0) = h01;
                    *(uint32_t*)(Clo + o0) = l01;
                    *(uint32_t*)(Chi + o1) = h23;
                    *(uint32_t*)(Clo + o1) = l23;
                } else {
                    *(uint32_t*)(Chi + o0) = pack2(v0, v1);
                    *(uint32_t*)(Chi + o1) = pack2(v2, v3);
                }
            }
        }
    }
}

// ---------------------------------------------------------------------------
// Fused GEMM + residual + LayerNorm. A = T1 is hi-only (2-term).
// ---------------------------------------------------------------------------
#define LSTG 49152

template<bool ALO>
__device__ __forceinline__ void gemm_ln_issue(
    uint32_t sb, int stage, int tid, int row0, int k0,
    const __nv_bfloat16* Ahi, const __nv_bfloat16* Alo,
    const __nv_bfloat16* Bhi, const __nv_bfloat16* Blo)
{
    #pragma unroll
    for (int i = 0; i < 6; i++) {
        int idx = tid + i * 512;
        uint32_t stg = sb + stage * LSTG;
        const __nv_bfloat16* src;
        uint32_t dst;
        if (idx < 1024) {
            if (!ALO && (idx >> 9)) continue;
            int j = idx & 511;
            int r = j >> 2, c = j & 3;
            dst = stg + ((idx >> 9) ? 8192u : 0u)
                + (uint32_t)(r * 4 + (c ^ ((r >> 1) & 3))) * 16;
            src = ((idx >> 9) ? Alo : Ahi) + (size_t)(row0 + r) * 256 + k0 + c * 8;
        } else {
            int j = (idx - 1024) & 1023;
            int r = j >> 2, c = j & 3;
            dst = stg + ((idx >= 2048) ? 32768u : 16384u)
                + (uint32_t)(r * 4 + (c ^ ((r >> 1) & 3))) * 16;
            src = ((idx >= 2048) ? Blo : Bhi) + (size_t)r * 256 + k0 + c * 8;
        }
        cp_async16(dst, src);
    }
    cp_commit();
}

template<bool ALO>
__global__ void __launch_bounds__(512)
gemm_ln(const __nv_bfloat16* __restrict__ Ahi, const __nv_bfloat16* __restrict__ Alo,
        const __nv_bfloat16* __restrict__ Bhi, const __nv_bfloat16* __restrict__ Blo,
        const float* __restrict__ bias,
        const float* __restrict__ lng, const float* __restrict__ lnb,
        __nv_bfloat16* Xh, __nv_bfloat16* Xl) {
    extern __shared__ char sm[];
    const uint32_t sb = smem_u32(sm);
    float* s_sum  = (float*)(sm + 3 * LSTG);
    float* s_g    = (float*)(sm + 3 * LSTG + 4096);
    float* s_b    = s_g + 256;
    float* s_bias = s_b + 256;
    const int tid  = threadIdx.x;
    const int lane = tid & 31;
    const int warp = tid >> 5;
    const int wm = warp & 3;
    const int wn = warp >> 2;
    const int row0 = blockIdx.x * 128;

    if (tid < 256) { s_g[tid] = lng[tid]; s_b[tid] = lnb[tid]; s_bias[tid] = bias[tid]; }

    float acc[2][8][4];
    #pragma unroll
    for (int i = 0; i < 2; i++)
        #pragma unroll
        for (int j = 0; j < 8; j++)
            #pragma unroll
            for (int k = 0; k < 4; k++) acc[i][j][k] = 0.f;

    gemm_ln_issue<ALO>(sb, 0, tid, row0, 0, Ahi, Alo, Bhi, Blo);
    gemm_ln_issue<ALO>(sb, 1, tid, row0, 32, Ahi, Alo, Bhi, Blo);

    for (int ch = 0; ch < 8; ch++) {
        if (ch < 7) cp_wait<1>(); else cp_wait<0>();
        __syncthreads();
        const uint32_t base = sb + (ch % 3) * LSTG;
        #pragma unroll
        for (int s = 0; s < 2; s++) {
            uint32_t ah[2][4], al[2][4];
            #pragma unroll
            for (int mt = 0; mt < 2; mt++) {
                int row = wm * 32 + mt * 16 + (lane & 15);
                int c = 2 * s + (lane >> 4);
                uint32_t off = (uint32_t)(row * 4 + (c ^ ((row >> 1) & 3))) * 16;
                ldsm_x4(ah[mt], base + off);
                if (ALO) ldsm_x4(al[mt], base + 8192 + off);
            }
            #pragma unroll
            for (int ntp = 0; ntp < 4; ntp++) {
                int nr = wn * 64 + (ntp * 2 + ((lane >> 4) & 1)) * 8 + (lane & 7);
                int c = 2 * s + ((lane >> 3) & 1);
                uint32_t off = (uint32_t)(nr * 4 + (c ^ ((nr >> 1) & 3))) * 16;
                uint32_t bh[4], bl[4];
                ldsm_x4(bh, base + 16384 + off);
                ldsm_x4(bl, base + 32768 + off);
                #pragma unroll
                for (int half = 0; half < 2; half++) {
                    int nt = ntp * 2 + half;
                    #pragma unroll
                    for (int mt = 0; mt < 2; mt++) {
                        mma16816(acc[mt][nt], ah[mt], bh + 2 * half);
                        mma16816(acc[mt][nt], ah[mt], bl + 2 * half);
                        if (ALO) mma16816(acc[mt][nt], al[mt], bh + 2 * half);
                    }
                }
            }
        }
        __syncthreads();
        if (ch + 2 < 8)
            gemm_ln_issue<ALO>(sb, (ch + 2) % 3, tid, row0, (ch + 2) * 32, Ahi, Alo, Bhi, Blo);
    }

    const int g4 = lane >> 2, tig = lane & 3;
    float ps[2][2][2];
    #pragma unroll
    for (int mt = 0; mt < 2; mt++)
        #pragma unroll
        for (int h = 0; h < 2; h++) { ps[mt][h][0] = 0.f; ps[mt][h][1] = 0.f; }

    #pragma unroll
    for (int nt = 0; nt < 8; nt++) {
        int col = wn * 64 + nt * 8 + tig * 2;
        float b0 = s_bias[col], b1 = s_bias[col + 1];
        #pragma unroll
        for (int mt = 0; mt < 2; mt++) {
            size_t rA = (size_t)(row0 + wm * 32 + mt * 16 + g4) * 256 + col;
            uint32_t rh0 = *(const uint32_t*)(Xh + rA);
            uint32_t rl0 = *(const uint32_t*)(Xl + rA);
            uint32_t rh1 = *(const uint32_t*)(Xh + rA + 8 * 256);
            uint32_t rl1 = *(const uint32_t*)(Xl + rA + 8 * 256);
            float v0 = acc[mt][nt][0] + b0 + bflo(rh0) + bflo(rl0);
            float v1 = acc[mt][nt][1] + b1 + bfhi(rh0) + bfhi(rl0);
            float v2 = acc[mt][nt][2] + b0 + bflo(rh1) + bflo(rl1);
            float v3 = acc[mt][nt][3] + b1 + bfhi(rh1) + bfhi(rl1);
            acc[mt][nt][0] = v0; acc[mt][nt][1] = v1;
            acc[mt][nt][2] = v2; acc[mt][nt][3] = v3;
            ps[mt][0][0] += v0 + v1; ps[mt][0][1] += v0 * v0 + v1 * v1;
            ps[mt][1][0] += v2 + v3; ps[mt][1][1] += v2 * v2 + v3 * v3;
        }
    }
    #pragma unroll
    for (int mt = 0; mt < 2; mt++)
        #pragma unroll
        for (int h = 0; h < 2; h++) {
            ps[mt][h][0] += __shfl_xor_sync(0xffffffffu, ps[mt][h][0], 1);
            ps[mt][h][0] += __shfl_xor_sync(0xffffffffu, ps[mt][h][0], 2);
            ps[mt][h][1] += __shfl_xor_sync(0xffffffffu, ps[mt][h][1], 1);
            ps[mt][h][1] += __shfl_xor_sync(0xffffffffu, ps[mt][h][1], 2);
        }
    if (tig == 0) {
        #pragma unroll
        for (int mt = 0; mt < 2; mt++)
            #pragma unroll
            for (int h = 0; h < 2; h++) {
                int row = wm * 32 + mt * 16 + g4 + h * 8;
                *(float2*)&s_sum[(row * 4 + wn) * 2] =
                    make_float2(ps[mt][h][0], ps[mt][h][1]);
            }
    }
    __syncthreads();

    float mean[2][2], rstd[2][2];
    #pragma unroll
    for (int mt = 0; mt < 2; mt++)
        #pragma unroll
        for (int h = 0; h < 2; h++) {
            int row = wm * 32 + mt * 16 + g4 + h * 8;
            float s = 0.f, q = 0.f;
            #pragma unroll
            for (int w = 0; w < 4; w++) {
                float2 t = *(float2*)&s_sum[(row * 4 + w) * 2];
                s += t.x; q += t.y;
            }
            float m = s * (1.f / 256.f);
            float var = fmaxf(q * (1.f / 256.f) - m * m, 0.f);
            mean[mt][h] = m;
            rstd[mt][h] = rsqrtf(var + 1e-5f);
        }

    #pragma unroll
    for (int nt = 0; nt < 8; nt++) {
        int col = wn * 64 + nt * 8 + tig * 2;
        float gg0 = s_g[col], gg1 = s_g[col + 1];
        float bb0 = s_b[col], bb1 = s_b[col + 1];
        #pragma unroll
        for (int mt = 0; mt < 2; mt++) {
            size_t rA = (size_t)(row0 + wm * 32 + mt * 16 + g4) * 256 + col;
            float o0 = (acc[mt][nt][0] - mean[mt][0]) * rstd[mt][0] * gg0 + bb0;
            float o1 = (acc[mt][nt][1] - mean[mt][0]) * rstd[mt][0] * gg1 + bb1;
            float o2 = (acc[mt][nt][2] - mean[mt][1]) * rstd[mt][1] * gg0 + bb0;
            float o3 = (acc[mt][nt][3] - mean[mt][1]) * rstd[mt][1] * gg1 + bb1;
            uint32_t h01, l01, h23, l23;
            split2(o0, o1, h01, l01);
            split2(o2, o3, h23, l23);
            *(uint32_t*)(Xh + rA)           = h01;
            *(uint32_t*)(Xl + rA)           = l01;
            *(uint32_t*)(Xh + rA + 8 * 256) = h23;
            *(uint32_t*)(Xl + rA + 8 * 256) = l23;
        }
    }
}

// ---------------------------------------------------------------------------
// Merged weight transpose + split
// ---------------------------------------------------------------------------
__global__ void transpose_all(const float* Wqkv, const float* Wo, const float* W1,
                              const float* W2, const float* msg_W, const float* gat_W,
                              const float* spW1, const float* spW2,
                              __nv_bfloat16* Thi, __nv_bfloat16* Tlo) {
    const int z = blockIdx.z;
    const float* src;
    int dstoff, K, N;
    if (z < 2)       { src = Wqkv + (size_t)z * 256 * 768; dstoff = WT_QKV + z * 768 * 256; K = 256; N = 768; }
    else if (z < 4)  { int l = z - 2;  src = Wo + (size_t)l * 65536;  dstoff = WT_WO + l * 65536;  K = 256; N = 256; }
    else if (z < 6)  { int l = z - 4;  src = W1 + (size_t)l * 65536;  dstoff = WT_W1 + l * 65536;  K = 256; N = 256; }
    else if (z < 8)  { int l = z - 6;  src = W2 + (size_t)l * 65536;  dstoff = WT_W2 + l * 65536;  K = 256; N = 256; }
    else if (z < 11) { int r = z - 8;  src = msg_W + (size_t)r * 65536; dstoff = WT_MSG + r * 65536; K = 256; N = 256; }
    else if (z < 15) { int l = z - 11; src = gat_W + (size_t)l * 256 * 1024; dstoff = WT_GAT + l * 1024 * 256; K = 256; N = 1024; }
    else if (z < 16) { src = spW1; dstoff = WT_SP1; K = 256; N = 512; }
    else             { src = spW2; dstoff = WT_SP2; K = 512; N = 256; }

    int n0 = blockIdx.x * 32, k0 = blockIdx.y * 32;
    if (n0 >= N || k0 >= K) return;

    __shared__ float t[32][33];
    int x = threadIdx.x, y = threadIdx.y;
    #pragma unroll
    for (int i = 0; i < 4; i++)
        t[y + i * 8][x] = src[(size_t)(k0 + y + i * 8) * N + n0 + x];
    __syncthreads();
    #pragma unroll
    for (int i = 0; i < 4; i++) {
        float v = t[x][y + i * 8];
        __nv_bfloat16 h, l;
        split1(v, h, l);
        size_t o = (size_t)dstoff + (size_t)(n0 + y + i * 8) * K + k0 + x;
        Thi[o] = h; Tlo[o] = l;
    }
}

// ---------------------------------------------------------------------------
// Fused CSR build
// ---------------------------------------------------------------------------
__global__ void __launch_bounds__(1024) csr_build(const int* __restrict__ src,
                                                  const int* __restrict__ dst,
                                                  const int* __restrict__ etype) {
    __shared__ int cnt[NSEG];
    __shared__ int ws[1024];
    const int tid = threadIdx.x;
    #pragma unroll
    for (int k = 0; k < 6; k++) cnt[tid + k * 1024] = 0;
    __syncthreads();
    for (int e = tid; e < NEDGE; e += 1024)
        atomicAdd(&cnt[etype[e] * NN + dst[e]], 1);
    __syncthreads();
    const int base = tid * 6;
    int local[6];
    int sum = 0;
    #pragma unroll
    for (int k = 0; k < 6; k++) { local[k] = sum; sum += cnt[base + k]; }
    ws[tid] = sum;
    __syncthreads();
    for (int d = 1; d < 1024; d <<= 1) {
        int v = (tid >= d) ? ws[tid - d] : 0;
        __syncthreads();
        ws[tid] += v;
        __syncthreads();
    }
    int pre = ws[tid] - sum;
    #pragma unroll
    for (int k = 0; k < 6; k++) {
        g_off[base + k] = pre + local[k];
        cnt[base + k] = pre + local[k];
    }
    if (tid == 1023) g_off[NSEG] = ws[1023];
    __syncthreads();
    for (int e = tid; e < NEDGE; e += 1024) {
        int p = atomicAdd(&cnt[etype[e] * NN + dst[e]], 1);
        g_srt[p] = src[e];
    }
}

// ---------------------------------------------------------------------------
// PE table + embedding
// ---------------------------------------------------------------------------
__global__ void pe_kernel() {
    int s = blockIdx.x, d = threadIdx.x;
    int i2 = d >> 1;
    float div = expf((float)(2 * i2) * (-logf(10000.f) / (float)DIM));
    float arg = (float)s * div;
    g_PE[s * DIM + d] = (d & 1) ? cosf(arg) : sinf(arg);
}

__global__ void embed_kernel(const float* __restrict__ tok_emb,
                             const int* __restrict__ tokens) {
    int idx = (blockIdx.x * 256 + threadIdx.x) * 4;
    int row = idx >> 8;
    int d = idx & 255;
    int s = row & (SEQ - 1);
    int tok = tokens[row];
    float4 te = *(const float4*)(tok_emb + (size_t)tok * DIM + d);
    float4 pe = *(const float4*)(g_PE + s * DIM + d);
    float v0 = te.x * 16.f + pe.x;
    float v1 = te.y * 16.f + pe.y;
    float v2 = te.z * 16.f + pe.z;
    float v3 = te.w * 16.f + pe.w;
    uint32_t h01, l01, h23, l23;
    split2(v0, v1, h01, l01);
    split2(v2, v3, h23, l23);
    size_t o = (size_t)row * DIM + d;
    *(uint2*)(g_Xh + o) = make_uint2(h01, h23);
    *(uint2*)(g_Xl + o) = make_uint2(l01, l23);
}

// ---------------------------------------------------------------------------
// Tensor-core attention: 4 warps/block, each warp = one (node,head) 32-row half.
// S = Q@K^T (mma), full-row softmax in regs, P reused as A-fragments for P@V.
// ---------------------------------------------------------------------------
#define AT_Q    0
#define AT_K    5120
#define AT_VT   10240
#define AT_SLOT 15360        // Q 5120 + K 5120 + VT 4608 (+pad)

__global__ void __launch_bounds__(128) attn_mma() {
    __shared__ char sm[2 * AT_SLOT];
    const uint32_t sb = smem_u32(sm);
    const int tid = threadIdx.x;

    // cooperative load of both (node,head) slots
    #pragma unroll
    for (int slot = 0; slot < 2; slot++) {
        int nh = blockIdx.x * 2 + slot;
        int nn = nh >> 3, hh = nh & 7;
        const __nv_bfloat16* base = g_QKVh + (size_t)nn * SEQ * 768 + hh * DH;
        char* q  = sm + slot * AT_SLOT + AT_Q;
        char* k  = sm + slot * AT_SLOT + AT_K;
        char* vt = sm + slot * AT_SLOT + AT_VT;
        for (int t = tid; t < 1024; t += 128) {
            int r = t >> 4, d2 = (t & 15) * 2;
            *(uint32_t*)(q + r * 80 + d2 * 2) = *(const uint32_t*)(base + r * 768 + d2);
            *(uint32_t*)(k + r * 80 + d2 * 2) = *(const uint32_t*)(base + r * 768 + 256 + d2);
        }
        for (int t = tid; t < 2048; t += 128) {
            int j = t >> 5, d = t & 31;
            *(__nv_bfloat16*)(vt + d * 144 + j * 2) = base[j * 768 + 512 + d];
        }
    }
    __syncthreads();

    const int warp = tid >> 5, lane = tid & 31;
    const int slot = warp >> 1, half = warp & 1;
    const int nh = blockIdx.x * 2 + slot;
    const int nn = nh >> 3, hh = nh & 7;
    const uint32_t qb = sb + slot * AT_SLOT + AT_Q;
    const uint32_t kb = sb + slot * AT_SLOT + AT_K;
    const uint32_t vb = sb + slot * AT_SLOT + AT_VT;
    const int g4 = lane >> 2, tig = lane & 3;

    // Q fragments (A operand)
    uint32_t aq[2][2][4];
    #pragma unroll
    for (int mt = 0; mt < 2; mt++)
        #pragma unroll
        for (int kk = 0; kk < 2; kk++) {
            int row = half * 32 + mt * 16 + (lane & 15);
            int c = 2 * kk + (lane >> 4);
            ldsm_x4(aq[mt][kk], qb + (uint32_t)(row * 80 + c * 16));
        }

    // S = Q @ K^T
    float sf[2][8][4];
    #pragma unroll
    for (int mt = 0; mt < 2; mt++)
        #pragma unroll
        for (int nt = 0; nt < 8; nt++)
            #pragma unroll
            for (int x = 0; x < 4; x++) sf[mt][nt][x] = 0.f;
    #pragma unroll
    for (int kk = 0; kk < 2; kk++)
        #pragma unroll
        for (int ntp = 0; ntp < 4; ntp++) {
            int nr = (ntp * 2 + ((lane >> 4) & 1)) * 8 + (lane & 7);
            int c = 2 * kk + ((lane >> 3) & 1);
            uint32_t bK[4];
            ldsm_x4(bK, kb + (uint32_t)(nr * 80 + c * 16));
            #pragma unroll
            for (int hn = 0; hn < 2; hn++)
                #pragma unroll
                for (int mt = 0; mt < 2; mt++)
                    mma16816(sf[mt][ntp * 2 + hn], aq[mt][kk], bK + 2 * hn);
        }

    // full softmax over 64 columns (rows: per thread mt x {g4, g4+8})
    const float scale = 0.17677669529663687f;
    float mrow[2][2], lrow[2][2];
    #pragma unroll
    for (int mt = 0; mt < 2; mt++)
        #pragma unroll
        for (int rr = 0; rr < 2; rr++) {
            float mx = -1e30f;
            #pragma unroll
            for (int nt = 0; nt < 8; nt++) {
                sf[mt][nt][2 * rr]     *= scale;
                sf[mt][nt][2 * rr + 1] *= scale;
                mx = fmaxf(mx, fmaxf(sf[mt][nt][2 * rr], sf[mt][nt][2 * rr + 1]));
            }
            mx = fmaxf(mx, __shfl_xor_sync(0xffffffffu, mx, 1));
            mx = fmaxf(mx, __shfl_xor_sync(0xffffffffu, mx, 2));
            float ls = 0.f;
            #pragma unroll
            for (int nt = 0; nt < 8; nt++) {
                float p0 = expf(sf[mt][nt][2 * rr] - mx);
                float p1 = expf(sf[mt][nt][2 * rr + 1] - mx);
                sf[mt][nt][2 * rr] = p0;
                sf[mt][nt][2 * rr + 1] = p1;
                ls += p0 + p1;
            }
            ls += __shfl_xor_sync(0xffffffffu, ls, 1);
            ls += __shfl_xor_sync(0xffffffffu, ls, 2);
            mrow[mt][rr] = mx;
            lrow[mt][rr] = ls;
        }

    // pack P as A fragments for P@V
    uint32_t pf[2][4][4];
    #pragma unroll
    for (int mt = 0; mt < 2; mt++)
        #pragma unroll
        for (int kk = 0; kk < 4; kk++) {
            pf[mt][kk][0] = pack2(sf[mt][2 * kk][0],     sf[mt][2 * kk][1]);
            pf[mt][kk][1] = pack2(sf[mt][2 * kk][2],     sf[mt][2 * kk][3]);
            pf[mt][kk][2] = pack2(sf[mt][2 * kk + 1][0], sf[mt][2 * kk + 1][1]);
            pf[mt][kk][3] = pack2(sf[mt][2 * kk + 1][2], sf[mt][2 * kk + 1][3]);
        }

    // O = P @ V
    float of[2][4][4];
    #pragma unroll
    for (int mt = 0; mt < 2; mt++)
        #pragma unroll
        for (int nt = 0; nt < 4; nt++)
            #pragma unroll
            for (int x = 0; x < 4; x++) of[mt][nt][x] = 0.f;
    #pragma unroll
    for (int kk = 0; kk < 4; kk++)
        #pragma unroll
        for (int ntp = 0; ntp < 2; ntp++) {
            int nr = (ntp * 2 + ((lane >> 4) & 1)) * 8 + (lane & 7);
            int c = 2 * kk + ((lane >> 3) & 1);
            uint32_t bV[4];
            ldsm_x4(bV, vb + (uint32_t)(nr * 144 + c * 16));
            #pragma unroll
            for (int hn = 0; hn < 2; hn++)
                #pragma unroll
                for (int mt = 0; mt < 2; mt++)
                    mma16816(of[mt][ntp * 2 + hn], pf[mt][kk], bV + 2 * hn);
        }

    // write normalized output to T1 (hi-only)
    #pragma unroll
    for (int mt = 0; mt < 2; mt++) {
        float inv0 = 1.f / lrow[mt][0];
        float inv1 = 1.f / lrow[mt][1];
        int row = nn * 64 + half * 32 + mt * 16 + g4;
        #pragma unroll
        for (int nt = 0; nt < 4; nt++) {
            int col = hh * 32 + nt * 8 + tig * 2;
            *(uint32_t*)(g_T1h + (size_t)row * 256 + col) =
                pack2(of[mt][nt][0] * inv0, of[mt][nt][1] * inv0);
            *(uint32_t*)(g_T1h + (size_t)(row + 8) * 256 + col) =
                pack2(of[mt][nt][2] * inv1, of[mt][nt][3] * inv1);
        }
    }
}

// ---------------------------------------------------------------------------
// mean over seq + type emb
// ---------------------------------------------------------------------------
__global__ void mean_kernel(const int* __restrict__ types,
                            const float* __restrict__ type_emb) {
    int n = blockIdx.x, d = threadIdx.x;
    float acc = 0.f;
    const __nv_bfloat16* bh = g_Xh + (size_t)n * SEQ * DIM + d;
    const __nv_bfloat16* bl = g_Xl + (size_t)n * SEQ * DIM + d;
    for (int s = 0; s < SEQ; s++)
        acc += __bfloat162float(bh[s * DIM]) + __bfloat162float(bl[s * DIM]);
    float v = acc * (1.f / SEQ) + type_emb[(size_t)types[n] * DIM + d];
    size_t o = (size_t)n * DIM + d;
    g_H[o] = v;
    __nv_bfloat16 h, l;
    split1(v, h, l);
    g_Hh[o] = h; g_Hl[o] = l;
}

// ---------------------------------------------------------------------------
// GNN kernels
// ---------------------------------------------------------------------------
__global__ void asd_kernel(const float* __restrict__ asrc,
                           const float* __restrict__ adst) {
    int i = blockIdx.x;
    int w = threadIdx.x >> 5, lane = threadIdx.x & 31;
    float s1 = 0.f, s2 = 0.f;
    const float* xg = g_XG + (size_t)i * GHEADS * DIM + w * DIM;
    #pragma unroll
    for (int d = lane; d < DIM; d += 32) {
        float xv = xg[d];
        s1 += xv * asrc[w * DIM + d];
        s2 += xv * adst[w * DIM + d];
    }
    #pragma unroll
    for (int off = 16; off > 0; off >>= 1) {
        s1 += __shfl_down_sync(0xffffffffu, s1, off);
        s2 += __shfl_down_sync(0xffffffffu, s2, off);
    }
    if (lane == 0) {
        g_AS[i * GHEADS + w] = s1;
        g_AD[i * GHEADS + w] = s2;
    }
}

__global__ void __launch_bounds__(128) csr_agg() {
    __shared__ float s_acc[4][DIM];
    const int i = blockIdx.x;
    const int w = threadIdx.x >> 5;
    const int lane = threadIdx.x & 31;
    const int rbase = (i >> 11) << 11;
    const int beg = g_off[i], end = g_off[i + 1];

    const float ad = g_AD[i * GHEADS + w];
    const float self_e = lrelu(g_AS[i * GHEADS + w] + ad);

    float m = self_e;
    for (int j = beg + lane; j < end; j += 32)
        m = fmaxf(m, lrelu(g_AS[(rbase + g_srt[j]) * GHEADS + w] + ad));
    #pragma unroll
    for (int off = 16; off > 0; off >>= 1)
        m = fmaxf(m, __shfl_xor_sync(0xffffffffu, m, off));

    float den = expf(self_e - m);
    float acc[8];
    const float* xs = g_XG + (size_t)i * (GHEADS * DIM) + w * DIM;
    #pragma unroll
    for (int k = 0; k < 8; k++) acc[k] = den * xs[lane + 32 * k];
    for (int j = beg; j < end; j++) {
        int s = rbase + g_srt[j];
        float wgt = expf(lrelu(g_AS[s * GHEADS + w] + ad) - m);
        den += wgt;
        const float* xv = g_XG + (size_t)s * (GHEADS * DIM) + w * DIM;
        #pragma unroll
        for (int k = 0; k < 8; k++) acc[k] += wgt * xv[lane + 32 * k];
    }
    float inv = 0.25f / den;
    #pragma unroll
    for (int k = 0; k < 8; k++) s_acc[w][lane + 32 * k] = acc[k] * inv;
    __syncthreads();
    float* nm = g_NUMR + (size_t)i * DIM;
    #pragma unroll
    for (int k = 0; k < 2; k++) {
        int d = threadIdx.x + 128 * k;
        nm[d] = s_acc[0][d] + s_acc[1][d] + s_acc[2][d] + s_acc[3][d];
    }
}

__global__ void combupd_kernel(const float* __restrict__ gb) {
    int n = blockIdx.x, d = threadIdx.x;
    float acc = g_NUMR[(size_t)n * DIM + d]
              + g_NUMR[(size_t)(NN + n) * DIM + d]
              + g_NUMR[(size_t)(2 * NN + n) * DIM + d];
    size_t o = (size_t)n * DIM + d;
    float v = fmaxf(g_H[o] + acc + 3.f * gb[d], 0.f);
    g_H[o] = v;
    __nv_bfloat16 h, l;
    split1(v, h, l);
    g_Hh[o] = h; g_Hl[o] = l;
}

__global__ void final_kernel(const float* __restrict__ log_c, float* __restrict__ out) {
    int n = blockIdx.x, d = threadIdx.x;
    __shared__ float sh[256];
    __shared__ float stat;
    float scale = sqrtf(expf(log_c[0]));
    float st = tanhf(g_TH[(size_t)n * DIM + d]) * 2.f * scale;
    sh[d] = st * st; __syncthreads();
    for (int s = 128; s > 0; s >>= 1) { if (d < s) sh[d] += sh[d + s]; __syncthreads(); }
    if (d == 0) stat = sh[0];
    __syncthreads();
    float r = fmaxf(sqrtf(stat), 1e-8f);
    if (d == 0) out[(size_t)n * 257] = coshf(r);
    out[(size_t)n * 257 + 1 + d] = sinhf(r) / r * st;
}

// ---------------------------------------------------------------------------
// Host orchestration
// ---------------------------------------------------------------------------
extern "C" void kernel_launch(void* const* d_in, const int* in_sizes, int n_in,
                              void* d_out, int out_size) {
    const float* tok_emb = (const float*)d_in[0];
    const float* Wqkv    = (const float*)d_in[1];
    const float* bqkv    = (const float*)d_in[2];
    const float* Wo      = (const float*)d_in[3];
    const float* bo      = (const float*)d_in[4];
    const float* ln1g    = (const float*)d_in[5];
    const float* ln1b    = (const float*)d_in[6];
    const float* ln2g    = (const float*)d_in[7];
    const float* ln2b    = (const float*)d_in[8];
    const float* W1      = (const float*)d_in[9];
    const float* b1      = (const float*)d_in[10];
    const float* W2      = (const float*)d_in[11];
    const float* b2      = (const float*)d_in[12];
    const float* type_emb= (const float*)d_in[13];
    const float* msg_W   = (const float*)d_in[14];
    const float* msg_b   = (const float*)d_in[15];
    const float* gat_W   = (const float*)d_in[16];
    const float* gat_b   = (const float*)d_in[17];
    const float* asrc    = (const float*)d_in[18];
    const float* adst    = (const float*)d_in[19];
    const float* spW1    = (const float*)d_in[20];
    const float* spb1    = (const float*)d_in[21];
    const float* spW2    = (const float*)d_in[22];
    const float* spb2    = (const float*)d_in[23];
    const float* log_c   = (const float*)d_in[24];
    const int*   tokens  = (const int*)d_in[25];
    const int*   types   = (const int*)d_in[26];
    const int*   eidx    = (const int*)d_in[27];
    const int*   etype   = (const int*)d_in[28];
    const int* esrc = eidx;
    const int* edst = eidx + NEDGE;
    float* out = (float*)d_out;

    float *pH, *pTH, *pXG;
    __nv_bfloat16 *pQKVh, *pXh, *pXl, *pT1h, *pHh, *pHl, *pTHAh, *pTHAl,
                  *pSPHh, *pSPHl, *pWTh, *pWTl;
    cudaGetSymbolAddress((void**)&pH,    g_H);
    cudaGetSymbolAddress((void**)&pTH,   g_TH);
    cudaGetSymbolAddress((void**)&pXG,   g_XG);
    cudaGetSymbolAddress((void**)&pQKVh, g_QKVh);
    cudaGetSymbolAddress((void**)&pXh,   g_Xh);
    cudaGetSymbolAddress((void**)&pXl,   g_Xl);
    cudaGetSymbolAddress((void**)&pT1h,  g_T1h);
    cudaGetSymbolAddress((void**)&pHh,   g_Hh);
    cudaGetSymbolAddress((void**)&pHl,   g_Hl);
    cudaGetSymbolAddress((void**)&pTHAh, g_THAh);
    cudaGetSymbolAddress((void**)&pTHAl, g_THAl);
    cudaGetSymbolAddress((void**)&pSPHh, g_SPHh);
    cudaGetSymbolAddress((void**)&pSPHl, g_SPHl);
    cudaGetSymbolAddress((void**)&pWTh,  g_WTh);
    cudaGetSymbolAddress((void**)&pWTl,  g_WTl);

    cudaFuncSetAttribute(gemm_bf16<true>,  cudaFuncAttributeMaxDynamicSharedMemorySize,
                         NSTAGE * STAGE_BYTES);
    cudaFuncSetAttribute(gemm_bf16<false>, cudaFuncAttributeMaxDynamicSharedMemorySize,
                         NSTAGE * STAGE_BYTES);
    cudaFuncSetAttribute(gemm_ln<false>, cudaFuncAttributeMaxDynamicSharedMemorySize,
                         3 * LSTG + 4096 + 3 * 1024);
    const int SMEM   = NSTAGE * STAGE_BYTES;
    const int SMEMLN = 3 * LSTG + 4096 + 3 * 1024;

    // 0) merged weight transpose+split, PE, fused CSR build
    transpose_all<<<dim3(32, 16, 17), dim3(32, 8)>>>(
        Wqkv, Wo, W1, W2, msg_W, gat_W, spW1, spW2, pWTh, pWTl);
    pe_kernel<<<SEQ, 256>>>();
    csr_build<<<1, 1024>>>(esrc, edst, etype);

    // 1) embedding + PE
    embed_kernel<<<NTOK * DIM / 1024, 256>>>(tok_emb, tokens);

    // 2) transformer encoder (tensor-core attention)
    for (int l = 0; l < 2; l++) {
        gemm_bf16<false><<<dim3(6, NTOK / 128), 256, SMEM>>>(
            pXh, nullptr, 256, pWTh + WT_QKV + l * 768 * 256, pWTl + WT_QKV + l * 768 * 256,
            bqkv + l * 768, nullptr, pQKVh, nullptr, NTOK, 768, 256, 0, 0);
        attn_mma<<<NN * NH / 2, 128>>>();
        gemm_ln<false><<<NTOK / 128, 512, SMEMLN>>>(
            pT1h, nullptr, pWTh + WT_WO + l * 65536, pWTl + WT_WO + l * 65536,
            bo + l * 256, ln1g + l * 256, ln1b + l * 256, pXh, pXl);
        gemm_bf16<false><<<dim3(2, NTOK / 128), 256, SMEM>>>(
            pXh, nullptr, 256, pWTh + WT_W1 + l * 65536, pWTl + WT_W1 + l * 65536,
            b1 + l * 256, nullptr, pT1h, nullptr, NTOK, 256, 256, 1, 0);
        gemm_ln<false><<<NTOK / 128, 512, SMEMLN>>>(
            pT1h, nullptr, pWTh + WT_W2 + l * 65536, pWTl + WT_W2 + l * 65536,
            b2 + l * 256, ln2g + l * 256, ln2b + l * 256, pXh, pXl);
    }

    // 3) mean over seq + type embedding
    mean_kernel<<<NN, 256>>>(types, type_emb);

    // 4) 4 GNN layers (recurrent path: full 3-term splits)
    for (int l = 0; l < 4; l++) {
        gemm_bf16<true><<<dim3(6, NN / 128), 256, SMEM>>>(
            pHh, pHl, 256, pWTh + WT_MSG, pWTl + WT_MSG,
            msg_b, nullptr, pTHAh, pTHAl, NN, 768, 256, 0, NN * DIM);
        gemm_bf16<true><<<dim3(8, NSEG / 128), 256, SMEM>>>(
            pTHAh, pTHAl, 256,
            pWTh + WT_GAT + l * 1024 * 256, pWTl + WT_GAT + l * 1024 * 256,
            nullptr, pXG, nullptr, nullptr, NSEG, 1024, 256, 0, 0);
        asd_kernel<<<NSEG, 128>>>(asrc + l * GHEADS * DIM, adst + l * GHEADS * DIM);
        csr_agg<<<NSEG, 128>>>();
        combupd_kernel<<<NN, 256>>>(gat_b + l * 256);
    }

    // 5) scoring MLP + Lorentz exp map (un-normalized output path: 3-term)
    gemm_bf16<true><<<dim3(4, NN / 128), 256, SMEM>>>(
        pHh, pHl, 256, pWTh + WT_SP1, pWTl + WT_SP1,
        spb1, nullptr, pSPHh, pSPHl, NN, 512, 256, 1, 0);
    gemm_bf16<true><<<dim3(2, NN / 128), 256, SMEM>>>(
        pSPHh, pSPHl, 512, pWTh + WT_SP2, pWTl + WT_SP2,
        spb2, pTH, nullptr, nullptr, NN, 256, 512, 0, 0);
    final_kernel<<<NN, 256>>>(log_c, out);
}